// round 10
// baseline (speedup 1.0000x reference)
#include <cuda_runtime.h>
#include <cuda_bf16.h>
#include <cuda_fp16.h>
#include <math.h>
#include <stdint.h>

// ---------------- problem constants ----------------
#define NUTT   2000
#define NROW   6000
#define NCOL   200
#define NLAY   8
#define SFULL  (NROW * NCOL)
#define WSTRIDE (NCOL * 2 * NCOL)

#define ADJ_SCALE   16384.0f
#define ADJ_ISCALE  (1.0f / 16384.0f)

// ---------------- split-bf16 MMA kernel geometry ----------------
#define BMM   128
#define NST   3
#define SA_H  0u
#define SA_L  8192u
#define SB_H  16384u
#define SB_L  30720u
#define STAGE 45056u
#define DSMEM (3*45056 + 1024)

// ---------------- fp16 single-pass kernel geometry ----------------
#define F_NST   4
#define F_SA    0u
#define F_SB    8192u
#define F_STAGE 22528u
#define F_DSMEM (4*22528 + 1024)

// ---------------- scratch ----------------
__device__ __align__(256) float g_x   [SFULL];
__device__ __align__(256) float g_h0  [SFULL];
__device__ __align__(256) float g_h   [SFULL];
__device__ __align__(256) float g_hi  [SFULL];
__device__ __align__(256) float g_h0w2[NLAY * SFULL];
__device__ __align__(256) float g_part[3 * SFULL];

__device__ __align__(256) __half        g_adj16[NROW * NROW];
__device__ __align__(256) __half        g_hT16 [NCOL * NROW];
__device__ __align__(256) __nv_bfloat16 g_hih  [SFULL];
__device__ __align__(256) __nv_bfloat16 g_hil  [SFULL];
__device__ __align__(256) __nv_bfloat16 g_h0h  [SFULL];
__device__ __align__(256) __nv_bfloat16 g_h0l  [SFULL];
__device__ __align__(256) __nv_bfloat16 g_WTh8 [NLAY * WSTRIDE];
__device__ __align__(256) __nv_bfloat16 g_WTl8 [NLAY * WSTRIDE];
__device__ __align__(256) __nv_bfloat16 g_W0Th [NCOL * NCOL];
__device__ __align__(256) __nv_bfloat16 g_W0Tl [NCOL * NCOL];
__device__ __align__(256) __nv_bfloat16 g_xh   [SFULL];
__device__ __align__(256) __nv_bfloat16 g_xl   [SFULL];

__device__ __align__(256) __nv_bfloat16 g_ah_ [2000 * 304];
__device__ __align__(256) __nv_bfloat16 g_al_ [2000 * 304];
__device__ __align__(256) __nv_bfloat16 g_vh_ [2000 * 352];
__device__ __align__(256) __nv_bfloat16 g_vl_ [2000 * 352];
__device__ __align__(256) __nv_bfloat16 g_lh_ [2000 * 1024];
__device__ __align__(256) __nv_bfloat16 g_ll_ [2000 * 1024];
__device__ __align__(256) __nv_bfloat16 g_WaTh[NCOL * 304];
__device__ __align__(256) __nv_bfloat16 g_WaTl[NCOL * 304];
__device__ __align__(256) __nv_bfloat16 g_WvTh[NCOL * 352];
__device__ __align__(256) __nv_bfloat16 g_WvTl[NCOL * 352];
__device__ __align__(256) __nv_bfloat16 g_WlTh[NCOL * 1024];
__device__ __align__(256) __nv_bfloat16 g_WlTl[NCOL * 1024];

// ---------------- helpers ----------------
__device__ __forceinline__ uint32_t smem_u32(const void* p) {
    uint32_t a;
    asm("{ .reg .u64 t; cvta.to.shared.u64 t, %1; cvt.u32.u64 %0, t; }" : "=r"(a) : "l"(p));
    return a;
}
// 64B-row swizzle: phase = (row>>1)&3 — conflict-free ldmatrix + cp.async
__device__ __forceinline__ uint32_t swz(uint32_t off) {
    return off ^ ((off >> 3) & 0x30u);
}
__device__ __forceinline__ void ldsm4(uint32_t* r, uint32_t a) {
    asm volatile("ldmatrix.sync.aligned.m8n8.x4.shared.b16 {%0,%1,%2,%3}, [%4];"
                 : "=r"(r[0]), "=r"(r[1]), "=r"(r[2]), "=r"(r[3]) : "r"(a));
}
__device__ __forceinline__ void ldsm2(uint32_t* r, uint32_t a) {
    asm volatile("ldmatrix.sync.aligned.m8n8.x2.shared.b16 {%0,%1}, [%2];"
                 : "=r"(r[0]), "=r"(r[1]) : "r"(a));
}
__device__ __forceinline__ void mma_bf(float* d, const uint32_t* a, const uint32_t* b) {
    asm volatile("mma.sync.aligned.m16n8k16.row.col.f32.bf16.bf16.f32 "
                 "{%0,%1,%2,%3}, {%4,%5,%6,%7}, {%8,%9}, {%0,%1,%2,%3};"
                 : "+f"(d[0]), "+f"(d[1]), "+f"(d[2]), "+f"(d[3])
                 : "r"(a[0]), "r"(a[1]), "r"(a[2]), "r"(a[3]), "r"(b[0]), "r"(b[1]));
}
__device__ __forceinline__ void mma_hf(float* d, const uint32_t* a, const uint32_t* b) {
    asm volatile("mma.sync.aligned.m16n8k16.row.col.f32.f16.f16.f32 "
                 "{%0,%1,%2,%3}, {%4,%5,%6,%7}, {%8,%9}, {%0,%1,%2,%3};"
                 : "+f"(d[0]), "+f"(d[1]), "+f"(d[2]), "+f"(d[3])
                 : "r"(a[0]), "r"(a[1]), "r"(a[2]), "r"(a[3]), "r"(b[0]), "r"(b[1]));
}
__device__ __forceinline__ void cp16(uint32_t dst, const void* src, int sz) {
    asm volatile("cp.async.cg.shared.global [%0], [%1], 16, %2;"
                 :: "r"(dst), "l"(src), "r"(sz) : "memory");
}
__device__ __forceinline__ void cp_commit() {
    asm volatile("cp.async.commit_group;" ::: "memory");
}
__device__ __forceinline__ void split_bf(float v, __nv_bfloat16& h, __nv_bfloat16& l) {
    h = __float2bfloat16(v);
    l = __float2bfloat16(v - __bfloat162float(h));
}

// =====================================================================
// fp16 single-pass GEMM (adj path)
// =====================================================================
__device__ __forceinline__ void load_stage_f16(
    uint32_t sb, const __half* __restrict__ A, int lda,
    const __half* __restrict__ B, int ldb,
    int row0, int M, int kb, int ke, int tid)
{
    for (int g = tid; g < 1408; g += 256) {
        const __half* srow;
        uint32_t toff;
        int r, c;
        bool rv;
        if (g < 512) {
            r = g >> 2; c = g & 3;
            srow = A; toff = F_SA;
            rv = (row0 + r) < M;
            if (rv) srow += (size_t)(row0 + r) * lda;
        } else {
            int idx = g - 512;
            r = idx >> 2; c = idx & 3;
            srow = B; toff = F_SB;
            rv = r < NCOL;
            if (rv) srow += (size_t)r * ldb;
        }
        int k0 = kb + c * 8;
        int sz = 0;
        const void* sp = srow;
        if (rv) {
            int kv = (ke - k0) * 2;
            sz = kv >= 16 ? 16 : (kv > 0 ? kv : 0);
            if (sz > 0) sp = srow + k0;
        }
        cp16(sb + toff + swz((uint32_t)(r * 64 + c * 16)), sp, sz);
    }
}

__global__ __launch_bounds__(256)
void mma_f16(const __half* __restrict__ A, int lda,
             const __half* __restrict__ B, int ldb,
             int M, int Ktot, int ksize, float* __restrict__ Cbase)
{
    extern __shared__ char dsm_raw[];
    const int tid  = threadIdx.x;
    const int wid  = tid >> 5;
    const int lane = tid & 31;
    const int wm   = wid >> 2;
    const int wn   = wid & 3;
    const int row0 = blockIdx.x * BMM;
    const int ks   = blockIdx.y * ksize;
    const int ke   = (ks + ksize < Ktot) ? (ks + ksize) : Ktot;
    float* Cout = Cbase + (size_t)blockIdx.y * SFULL;

    const uint32_t base = (smem_u32(dsm_raw) + 1023u) & ~1023u;

    float acc[4][7][4];
#pragma unroll
    for (int mt = 0; mt < 4; mt++)
#pragma unroll
        for (int nt = 0; nt < 7; nt++)
#pragma unroll
            for (int q = 0; q < 4; q++) acc[mt][nt][q] = 0.0f;

    const int nck = (ke - ks + 31) >> 5;

    int issued = 0;
    for (; issued < nck && issued < F_NST - 1; issued++) {
        load_stage_f16(base + issued * F_STAGE, A, lda, B, ldb,
                       row0, M, ks + issued * 32, ke, tid);
        cp_commit();
    }

    for (int i = 0; i < nck; i++) {
        int allow = nck - i - 1;
        if (allow > F_NST - 2) allow = F_NST - 2;
        if (allow >= 2)      asm volatile("cp.async.wait_group 2;" ::: "memory");
        else if (allow == 1) asm volatile("cp.async.wait_group 1;" ::: "memory");
        else                 asm volatile("cp.async.wait_group 0;" ::: "memory");
        __syncthreads();
        if (issued < nck) {
            load_stage_f16(base + (uint32_t)(issued % F_NST) * F_STAGE, A, lda, B, ldb,
                           row0, M, ks + issued * 32, ke, tid);
            cp_commit();
            issued++;
        }

        const uint32_t aB = base + (uint32_t)(i % F_NST) * F_STAGE + F_SA;
        const uint32_t bB = base + (uint32_t)(i % F_NST) * F_STAGE + F_SB;

#pragma unroll
        for (int ksub = 0; ksub < 2; ksub++) {
            uint32_t ah[4][4];
#pragma unroll
            for (int mt = 0; mt < 4; mt++) {
                int r  = wm * 64 + mt * 16 + (lane & 15);
                int ch = 2 * ksub + (lane >> 4);
                ldsm4(ah[mt], aB + swz((uint32_t)(r * 64 + ch * 16)));
            }
#pragma unroll
            for (int nt = 0; nt < 7; nt++) {
                int rb = wn * 56 + nt * 8 + (lane & 7);
                int cb = 2 * ksub + ((lane >> 3) & 1);
                uint32_t bb[2];
                ldsm2(bb, bB + swz((uint32_t)(rb * 64 + cb * 16)));
#pragma unroll
                for (int mt = 0; mt < 4; mt++) mma_hf(acc[mt][nt], ah[mt], bb);
            }
        }
    }

#pragma unroll
    for (int mt = 0; mt < 4; mt++)
#pragma unroll
        for (int hf = 0; hf < 2; hf++) {
            const int r = row0 + wm * 64 + mt * 16 + (lane >> 2) + 8 * hf;
            if (r >= M) continue;
#pragma unroll
            for (int nt = 0; nt < 7; nt++) {
                const int c = wn * 56 + nt * 8 + (lane & 3) * 2;
                if (c >= NCOL) continue;
                float2 o;
                o.x = acc[mt][nt][2 * hf];
                o.y = acc[mt][nt][2 * hf + 1];
                *(float2*)&Cout[(size_t)r * NCOL + c] = o;
            }
        }
}

// =====================================================================
// split-bf16 3-pass GEMM.
// EP: 0 partial write (seg offset), 1 relu+bias, 3 +bias, 4 +bias+speaker,
//     6 batched h0@W2 (blockIdx.y = layer)
// =====================================================================
__device__ __forceinline__ void load_stage(
    uint32_t sb, const __nv_bfloat16* __restrict__ Ah, const __nv_bfloat16* __restrict__ Al,
    int lda, const __nv_bfloat16* __restrict__ Bh, const __nv_bfloat16* __restrict__ Bl,
    int ldb, int row0, int M, int kb, int ke, int tid)
{
    for (int g = tid; g < 2816; g += 256) {
        const __nv_bfloat16* srow;
        uint32_t toff;
        int r, c;
        bool rv;
        if (g < 1024) {
            int t = g >> 9, idx = g & 511;
            r = idx >> 2; c = idx & 3;
            srow = (t ? Al : Ah);
            toff = t ? SA_L : SA_H;
            rv = (row0 + r) < M;
            if (rv) srow += (size_t)(row0 + r) * lda;
        } else {
            int gb = g - 1024;
            int t = gb >= 896;
            int idx = t ? gb - 896 : gb;
            r = idx >> 2; c = idx & 3;
            srow = (t ? Bl : Bh);
            toff = t ? SB_L : SB_H;
            rv = r < NCOL;
            if (rv) srow += (size_t)r * ldb;
        }
        int k0 = kb + c * 8;
        int sz = 0;
        const void* sp = srow;
        if (rv) {
            int kv = (ke - k0) * 2;
            sz = kv >= 16 ? 16 : (kv > 0 ? kv : 0);
            if (sz > 0) sp = srow + k0;
        }
        cp16(sb + toff + swz((uint32_t)(r * 64 + c * 16)), sp, sz);
    }
}

template <int EP>
__global__ __launch_bounds__(256)
void mma_gemm(const __nv_bfloat16* __restrict__ Ah, const __nv_bfloat16* __restrict__ Al, int lda,
              const __nv_bfloat16* __restrict__ Bh, const __nv_bfloat16* __restrict__ Bl, int ldb,
              int M, int Ktot,
              float* __restrict__ Cbase,
              const float* __restrict__ bias,
              const float* __restrict__ aux0, const float* __restrict__ aux1)
{
    extern __shared__ char dsm_raw[];
    const int tid  = threadIdx.x;
    const int wid  = tid >> 5;
    const int lane = tid & 31;
    const int wm   = wid >> 2;
    const int wn   = wid & 3;
    const int row0 = blockIdx.x * BMM;
    const int seg  = blockIdx.y;

    const __nv_bfloat16* BhU = Bh;
    const __nv_bfloat16* BlU = Bl;
    float* Cout = Cbase;
    if (EP == 6) {
        BhU = Bh + (size_t)seg * WSTRIDE + NCOL;
        BlU = Bl + (size_t)seg * WSTRIDE + NCOL;
        Cout = Cbase + (size_t)seg * SFULL;
    } else if (EP == 0) {
        Cout = Cbase + (size_t)seg * SFULL;
    }

    const uint32_t base = (smem_u32(dsm_raw) + 1023u) & ~1023u;

    float acc[4][7][4];
#pragma unroll
    for (int mt = 0; mt < 4; mt++)
#pragma unroll
        for (int nt = 0; nt < 7; nt++)
#pragma unroll
            for (int q = 0; q < 4; q++) acc[mt][nt][q] = 0.0f;

    const int nck = (Ktot + 31) >> 5;

    int issued = 0;
    for (; issued < nck && issued < NST - 1; issued++) {
        load_stage(base + issued * STAGE, Ah, Al, lda, BhU, BlU, ldb,
                   row0, M, issued * 32, Ktot, tid);
        cp_commit();
    }

    for (int i = 0; i < nck; i++) {
        if (nck - i >= 2) asm volatile("cp.async.wait_group 1;" ::: "memory");
        else              asm volatile("cp.async.wait_group 0;" ::: "memory");
        __syncthreads();
        if (issued < nck) {
            load_stage(base + (uint32_t)(issued % NST) * STAGE, Ah, Al, lda, BhU, BlU, ldb,
                       row0, M, issued * 32, Ktot, tid);
            cp_commit();
            issued++;
        }

        const uint32_t sb  = base + (uint32_t)(i % NST) * STAGE;
        const uint32_t aHu = sb + SA_H, aLu = sb + SA_L;
        const uint32_t bHu = sb + SB_H, bLu = sb + SB_L;

#pragma unroll
        for (int ksub = 0; ksub < 2; ksub++) {
            uint32_t ah[4][4], al[4][4];
#pragma unroll
            for (int mt = 0; mt < 4; mt++) {
                int r  = wm * 64 + mt * 16 + (lane & 15);
                int ch = 2 * ksub + (lane >> 4);
                uint32_t off = swz((uint32_t)(r * 64 + ch * 16));
                ldsm4(ah[mt], aHu + off);
                ldsm4(al[mt], aLu + off);
            }
#pragma unroll
            for (int nt = 0; nt < 7; nt++) {
                int rb = wn * 56 + nt * 8 + (lane & 7);
                int cb = 2 * ksub + ((lane >> 3) & 1);
                uint32_t off = swz((uint32_t)(rb * 64 + cb * 16));
                uint32_t bh[2], bl[2];
                ldsm2(bh, bHu + off);
                ldsm2(bl, bLu + off);
#pragma unroll
                for (int mt = 0; mt < 4; mt++) {
                    mma_bf(acc[mt][nt], ah[mt], bh);
                    mma_bf(acc[mt][nt], ah[mt], bl);
                    mma_bf(acc[mt][nt], al[mt], bh);
                }
            }
        }
    }

#pragma unroll
    for (int mt = 0; mt < 4; mt++) {
#pragma unroll
        for (int hf = 0; hf < 2; hf++) {
            const int r = row0 + wm * 64 + mt * 16 + (lane >> 2) + 8 * hf;
            if (r >= M) continue;
            int spk = 0;
            if (EP == 4) {
                int bI = r / 100, tI = r % 100;
                const float* q = aux0 + ((size_t)tI * 20 + bI) * 2;
                spk = (q[1] > q[0]) ? 1 : 0;
            }
#pragma unroll
            for (int nt = 0; nt < 7; nt++) {
                const int c = wn * 56 + nt * 8 + (lane & 3) * 2;
                if (c >= NCOL) continue;
                float vx = acc[mt][nt][2 * hf];
                float vy = acc[mt][nt][2 * hf + 1];
                if (EP == 1) {
                    vx = fmaxf(vx + bias[c], 0.0f);
                    vy = fmaxf(vy + bias[c + 1], 0.0f);
                } else if (EP == 3) {
                    vx += bias[c];
                    vy += bias[c + 1];
                } else if (EP == 4) {
                    vx += bias[c]     + aux1[spk * NCOL + c];
                    vy += bias[c + 1] + aux1[spk * NCOL + c + 1];
                }
                float2 o; o.x = vx; o.y = vy;
                *(float2*)&Cout[(size_t)r * NCOL + c] = o;
            }
        }
    }
}

// =====================================================================
// elementwise / conversion kernels
// =====================================================================
// adj f32 -> fp16*2^14 : 64B in / 32B out per thread (MLP 4)
__global__ void convert_adj(const float4* __restrict__ src, __half* __restrict__ dst) {
    int i = blockIdx.x * blockDim.x + threadIdx.x;      // over 36M/16
    if (i < NROW * NROW / 16) {
        float4 v0 = src[4 * i];
        float4 v1 = src[4 * i + 1];
        float4 v2 = src[4 * i + 2];
        float4 v3 = src[4 * i + 3];
        __half2 a = __floats2half2_rn(v0.x * ADJ_SCALE, v0.y * ADJ_SCALE);
        __half2 b = __floats2half2_rn(v0.z * ADJ_SCALE, v0.w * ADJ_SCALE);
        __half2 c = __floats2half2_rn(v1.x * ADJ_SCALE, v1.y * ADJ_SCALE);
        __half2 d = __floats2half2_rn(v1.z * ADJ_SCALE, v1.w * ADJ_SCALE);
        __half2 e = __floats2half2_rn(v2.x * ADJ_SCALE, v2.y * ADJ_SCALE);
        __half2 f = __floats2half2_rn(v2.z * ADJ_SCALE, v2.w * ADJ_SCALE);
        __half2 g = __floats2half2_rn(v3.x * ADJ_SCALE, v3.y * ADJ_SCALE);
        __half2 h = __floats2half2_rn(v3.z * ADJ_SCALE, v3.w * ADJ_SCALE);
        uint4 o0, o1;
        o0.x = *(uint32_t*)&a; o0.y = *(uint32_t*)&b;
        o0.z = *(uint32_t*)&c; o0.w = *(uint32_t*)&d;
        o1.x = *(uint32_t*)&e; o1.y = *(uint32_t*)&f;
        o1.z = *(uint32_t*)&g; o1.w = *(uint32_t*)&h;
        ((uint4*)dst)[2 * i]     = o0;
        ((uint4*)dst)[2 * i + 1] = o1;
    }
}

__global__ void convert_split4(const float* __restrict__ src, int n4,
                               __nv_bfloat16* __restrict__ dh,
                               __nv_bfloat16* __restrict__ dl)
{
    int i = blockIdx.x * blockDim.x + threadIdx.x;
    if (i < n4) {
        float4 v = ((const float4*)src)[i];
        __nv_bfloat16 h0, l0, h1, l1, h2, l2, h3, l3;
        split_bf(v.x, h0, l0); split_bf(v.y, h1, l1);
        split_bf(v.z, h2, l2); split_bf(v.w, h3, l3);
        __nv_bfloat162* H = (__nv_bfloat162*)dh;
        __nv_bfloat162* L = (__nv_bfloat162*)dl;
        H[2 * i]     = __nv_bfloat162(h0, h1);
        H[2 * i + 1] = __nv_bfloat162(h2, h3);
        L[2 * i]     = __nv_bfloat162(l0, l1);
        L[2 * i + 1] = __nv_bfloat162(l2, l3);
    }
}

__global__ void padsplit(const float* __restrict__ src, int R, int C, int Cp,
                         __nv_bfloat16* __restrict__ dh, __nv_bfloat16* __restrict__ dl)
{
    int i = blockIdx.x * blockDim.x + threadIdx.x;
    if (i < R * Cp) {
        int r = i / Cp, c = i % Cp;
        float v = (c < C) ? src[(size_t)r * C + c] : 0.0f;
        __nv_bfloat16 h, l;
        split_bf(v, h, l);
        dh[i] = h; dl[i] = l;
    }
}

__global__ void tsplit(const float* __restrict__ src, int R, int C, int Rp,
                       __nv_bfloat16* __restrict__ dh, __nv_bfloat16* __restrict__ dl)
{
    __shared__ float t[32][33];
    int r = blockIdx.x * 32 + threadIdx.y;
    int c = blockIdx.y * 32 + threadIdx.x;
    if (r < R && c < C) t[threadIdx.y][threadIdx.x] = src[(size_t)r * C + c];
    __syncthreads();
    int rr = blockIdx.x * 32 + threadIdx.x;
    int cc = blockIdx.y * 32 + threadIdx.y;
    if (rr < Rp && cc < C) {
        float v = (rr < R) ? t[threadIdx.x][threadIdx.y] : 0.0f;
        __nv_bfloat16 h, l;
        split_bf(v, h, l);
        dh[(size_t)cc * Rp + rr] = h;
        dl[(size_t)cc * Rp + rr] = l;
    }
}

__global__ void tsplit_w(const float* __restrict__ W0, const float* __restrict__ convW) {
    __shared__ float t[32][33];
    int z = blockIdx.z;
    const float* src;
    __nv_bfloat16 *dh, *dl;
    int R;
    if (z == 0) { src = W0; dh = g_W0Th; dl = g_W0Tl; R = NCOL; }
    else {
        src = convW + (size_t)(z - 1) * 2 * NCOL * NCOL;
        dh = g_WTh8 + (size_t)(z - 1) * WSTRIDE;
        dl = g_WTl8 + (size_t)(z - 1) * WSTRIDE;
        R = 2 * NCOL;
    }
    int r = blockIdx.x * 32 + threadIdx.y;
    int c = blockIdx.y * 32 + threadIdx.x;
    if (r < R && c < NCOL) t[threadIdx.y][threadIdx.x] = src[(size_t)r * NCOL + c];
    __syncthreads();
    int rr = blockIdx.x * 32 + threadIdx.x;
    int cc = blockIdx.y * 32 + threadIdx.y;
    if (rr < R && cc < NCOL) {
        __nv_bfloat16 h, l;
        split_bf(t[threadIdx.x][threadIdx.y], h, l);
        dh[(size_t)cc * R + rr] = h;
        dl[(size_t)cc * R + rr] = l;
    }
}

__global__ void t_f16(const float* __restrict__ src) {
    __shared__ float t[32][33];
    int r = blockIdx.x * 32 + threadIdx.y;
    int c = blockIdx.y * 32 + threadIdx.x;
    if (r < NROW && c < NCOL) t[threadIdx.y][threadIdx.x] = src[(size_t)r * NCOL + c];
    __syncthreads();
    int rr = blockIdx.x * 32 + threadIdx.x;
    int cc = blockIdx.y * 32 + threadIdx.y;
    if (rr < NROW && cc < NCOL)
        g_hT16[(size_t)cc * NROW + rr] = __float2half(t[threadIdx.x][threadIdx.y]);
}

// hi = (sum of 3 adj partials)*2^-14 ; write f32 + linear bf16 split
__global__ void reduce_hi() {
    int i = blockIdx.x * blockDim.x + threadIdx.x;
    if (i < SFULL / 4) {
        const float4* p = (const float4*)g_part;
        float4 a = p[i], b = p[i + SFULL / 4], c = p[i + SFULL / 2];
        float4 s;
        s.x = (a.x + b.x + c.x) * ADJ_ISCALE;
        s.y = (a.y + b.y + c.y) * ADJ_ISCALE;
        s.z = (a.z + b.z + c.z) * ADJ_ISCALE;
        s.w = (a.w + b.w + c.w) * ADJ_ISCALE;
        ((float4*)g_hi)[i] = s;
        __nv_bfloat16 h0, l0, h1, l1, h2, l2, h3, l3;
        split_bf(s.x, h0, l0); split_bf(s.y, h1, l1);
        split_bf(s.z, h2, l2); split_bf(s.w, h3, l3);
        __nv_bfloat162 H0(h0, h1), H1(h2, h3), L0(l0, l1), L1(l2, l3);
        uint2 oh, ol;
        oh.x = *(uint32_t*)&H0; oh.y = *(uint32_t*)&H1;
        ol.x = *(uint32_t*)&L0; ol.y = *(uint32_t*)&L1;
        ((uint2*)g_hih)[i] = oh;
        ((uint2*)g_hil)[i] = ol;
    }
}

// h = relu(theta*(part + h0w2[lay]) + (1-theta)*(0.9hi+0.1h0)); also hT16
__global__ void reduce_gcnii(float theta, int lay) {
    __shared__ float t[32][33];
    const int r0 = blockIdx.x * 32;
    const int c0 = blockIdx.y * 32;
    const float* h0w2 = g_h0w2 + (size_t)lay * SFULL;
#pragma unroll
    for (int q = 0; q < 4; q++) {
        int r = r0 + threadIdx.y * 4 + q;
        int c = c0 + threadIdx.x;
        float val = 0.0f;
        if (r < NROW && c < NCOL) {
            int i = r * NCOL + c;
            float sw = g_part[i] + h0w2[i];
            float rr = 0.9f * g_hi[i] + 0.1f * g_h0[i];
            val = fmaxf(theta * sw + (1.0f - theta) * rr, 0.0f);
            g_h[i] = val;
        }
        t[threadIdx.y * 4 + q][threadIdx.x] = val;
    }
    __syncthreads();
#pragma unroll
    for (int q = 0; q < 4; q++) {
        int rr2 = r0 + threadIdx.x;
        int cc  = c0 + threadIdx.y * 4 + q;
        if (rr2 < NROW && cc < NCOL)
            g_hT16[(size_t)cc * NROW + rr2] = __float2half(t[threadIdx.x][threadIdx.y * 4 + q]);
    }
}

__global__ void assemble_kernel(float4* __restrict__ out) {
    int i4 = blockIdx.x * blockDim.x + threadIdx.x;
    if (i4 < NUTT * 300) {
        int row = i4 / 300;
        int c4  = i4 % 300;
        int m   = c4 / 100;
        int j   = c4 % 100;
        const float4* src = (j < 50) ? (const float4*)g_x : (const float4*)g_h;
        out[i4] = src[(size_t)(m * NUTT + row) * 50 + (j % 50)];
    }
}

// =====================================================================
extern "C" void kernel_launch(void* const* d_in, const int* in_sizes, int n_in,
                              void* d_out, int out_size)
{
    const float* a     = (const float*)d_in[0];
    const float* v     = (const float*)d_in[1];
    const float* l     = (const float*)d_in[2];
    const float* qmask = (const float*)d_in[3];
    const float* adj   = (const float*)d_in[4];
    const float* Wa    = (const float*)d_in[5];
    const float* ba    = (const float*)d_in[6];
    const float* Wv    = (const float*)d_in[7];
    const float* bv    = (const float*)d_in[8];
    const float* Wl    = (const float*)d_in[9];
    const float* bl    = (const float*)d_in[10];
    const float* spk   = (const float*)d_in[11];
    const float* W0    = (const float*)d_in[12];
    const float* b0    = (const float*)d_in[13];
    const float* convW = (const float*)d_in[14];
    float* out = (float*)d_out;

    float *gx, *gh0, *gpart;
    __half *adj16, *hT16;
    __nv_bfloat16 *hih, *hil, *h0h, *h0l, *WTh8, *WTl8, *W0Th, *W0Tl, *xh, *xl;
    __nv_bfloat16 *ah_, *al_, *vh_, *vl_, *lh_, *ll_;
    __nv_bfloat16 *WaTh, *WaTl, *WvTh, *WvTl, *WlTh, *WlTl;
    float *gh0w2;
    cudaGetSymbolAddress((void**)&gx,    g_x);
    cudaGetSymbolAddress((void**)&gh0,   g_h0);
    cudaGetSymbolAddress((void**)&gh0w2, g_h0w2);
    cudaGetSymbolAddress((void**)&gpart, g_part);
    cudaGetSymbolAddress((void**)&adj16, g_adj16);
    cudaGetSymbolAddress((void**)&hT16,  g_hT16);
    cudaGetSymbolAddress((void**)&hih,   g_hih);
    cudaGetSymbolAddress((void**)&hil,   g_hil);
    cudaGetSymbolAddress((void**)&h0h,   g_h0h);
    cudaGetSymbolAddress((void**)&h0l,   g_h0l);
    cudaGetSymbolAddress((void**)&WTh8,  g_WTh8);
    cudaGetSymbolAddress((void**)&WTl8,  g_WTl8);
    cudaGetSymbolAddress((void**)&W0Th,  g_W0Th);
    cudaGetSymbolAddress((void**)&W0Tl,  g_W0Tl);
    cudaGetSymbolAddress((void**)&xh,    g_xh);
    cudaGetSymbolAddress((void**)&xl,    g_xl);
    cudaGetSymbolAddress((void**)&ah_,   g_ah_);
    cudaGetSymbolAddress((void**)&al_,   g_al_);
    cudaGetSymbolAddress((void**)&vh_,   g_vh_);
    cudaGetSymbolAddress((void**)&vl_,   g_vl_);
    cudaGetSymbolAddress((void**)&lh_,   g_lh_);
    cudaGetSymbolAddress((void**)&ll_,   g_ll_);
    cudaGetSymbolAddress((void**)&WaTh,  g_WaTh);
    cudaGetSymbolAddress((void**)&WaTl,  g_WaTl);
    cudaGetSymbolAddress((void**)&WvTh,  g_WvTh);
    cudaGetSymbolAddress((void**)&WvTl,  g_WvTl);
    cudaGetSymbolAddress((void**)&WlTh,  g_WlTh);
    cudaGetSymbolAddress((void**)&WlTl,  g_WlTl);

    cudaFuncSetAttribute(mma_f16,     cudaFuncAttributeMaxDynamicSharedMemorySize, F_DSMEM);
    cudaFuncSetAttribute(mma_gemm<0>, cudaFuncAttributeMaxDynamicSharedMemorySize, DSMEM);
    cudaFuncSetAttribute(mma_gemm<1>, cudaFuncAttributeMaxDynamicSharedMemorySize, DSMEM);
    cudaFuncSetAttribute(mma_gemm<3>, cudaFuncAttributeMaxDynamicSharedMemorySize, DSMEM);
    cudaFuncSetAttribute(mma_gemm<4>, cudaFuncAttributeMaxDynamicSharedMemorySize, DSMEM);
    cudaFuncSetAttribute(mma_gemm<6>, cudaFuncAttributeMaxDynamicSharedMemorySize, DSMEM);

    const int gProj = (NUTT + BMM - 1) / BMM;    // 16
    const int gFull = (NROW + BMM - 1) / BMM;    // 47

    // ---- one-time conversions (order matters: primer must be launch #6) ----
    convert_adj<<<(NROW * NROW / 16 + 255) / 256, 256>>>((const float4*)adj, adj16);   // 1
    padsplit<<<(2000 * 304 + 255) / 256, 256>>>(a, 2000, 300,  304,  ah_, al_);        // 2
    padsplit<<<(2000 * 352 + 255) / 256, 256>>>(v, 2000, 342,  352,  vh_, vl_);        // 3
    padsplit<<<(2000 * 1024 + 255) / 256, 256>>>(l, 2000, 1024, 1024, lh_, ll_);       // 4
    tsplit<<<dim3(10, 7), dim3(32, 32)>>>(Wa, 300,  NCOL, 304,  WaTh, WaTl);           // 5

    // 6: DIAGNOSTIC PRIMER — full-grid adj GEMM on current (stale/zero) hT16.
    // Output (g_part) is fully overwritten by layer 0 before any read.
    // Placed here so ncu (-s 5 -c 1) profiles THIS kernel.
    mma_f16<<<dim3(gFull, 3), 256, F_DSMEM>>>(adj16, NROW, hT16, NROW,
        NROW, NROW, 2000, gpart);                                                      // 6

    tsplit<<<dim3(11, 7), dim3(32, 32)>>>(Wv, 342,  NCOL, 352,  WvTh, WvTl);           // 7
    tsplit<<<dim3(32, 7), dim3(32, 32)>>>(Wl, 1024, NCOL, 1024, WlTh, WlTl);           // 8
    tsplit_w<<<dim3(13, 7, 9), dim3(32, 32)>>>(W0, convW);                             // 9

    // ---- modality projections -> g_x ----
    mma_gemm<3><<<dim3(gProj, 1), 256, DSMEM>>>(ah_, al_, 304, WaTh, WaTl, 304,
        NUTT, 304, gx, ba, nullptr, nullptr);
    mma_gemm<3><<<dim3(gProj, 1), 256, DSMEM>>>(vh_, vl_, 352, WvTh, WvTl, 352,
        NUTT, 352, gx + (size_t)NUTT * NCOL, bv, nullptr, nullptr);
    mma_gemm<4><<<dim3(gProj, 1), 256, DSMEM>>>(lh_, ll_, 1024, WlTh, WlTl, 1024,
        NUTT, 1024, gx + (size_t)2 * NUTT * NCOL, bl, qmask, spk);

    // ---- h0 = relu(x @ W0 + b0) ----
    convert_split4<<<(SFULL / 4 + 255) / 256, 256>>>(gx, SFULL / 4, xh, xl);
    mma_gemm<1><<<dim3(gFull, 1), 256, DSMEM>>>(xh, xl, NCOL, W0Th, W0Tl, NCOL,
        NROW, NCOL, gh0, b0, nullptr, nullptr);
    convert_split4<<<(SFULL / 4 + 255) / 256, 256>>>(gh0, SFULL / 4, h0h, h0l);
    t_f16<<<dim3(188, 7), dim3(32, 32)>>>(gh0);

    // ---- batched h0 @ W2[lay] for all 8 layers ----
    mma_gemm<6><<<dim3(gFull, NLAY), 256, DSMEM>>>(h0h, h0l, NCOL, WTh8, WTl8, 2 * NCOL,
        NROW, NCOL, gh0w2, nullptr, nullptr, nullptr);

    // ---- GCNII layers ----
    for (int lay = 0; lay < NLAY; lay++) {
        float theta = logf(0.5f / (float)(lay + 1) + 1.0f);

        mma_f16<<<dim3(gFull, 3), 256, F_DSMEM>>>(adj16, NROW, hT16, NROW,
            NROW, NROW, 2000, gpart);
        reduce_hi<<<(SFULL / 4 + 255) / 256, 256>>>();

        // hi @ W1[lay] -> g_part[0]  (single segment, K=200)
        const __nv_bfloat16* Wh  = WTh8 + (size_t)lay * WSTRIDE;
        const __nv_bfloat16* Wl2 = WTl8 + (size_t)lay * WSTRIDE;
        mma_gemm<0><<<dim3(gFull, 1), 256, DSMEM>>>(hih, hil, NCOL, Wh, Wl2, 2 * NCOL,
            NROW, NCOL, gpart, nullptr, nullptr, nullptr);

        // combine + relu -> g_h ; write h^T fp16 for next layer (full chip)
        reduce_gcnii<<<dim3(188, 7), dim3(32, 8)>>>(theta, lay);
    }

    assemble_kernel<<<(NUTT * 300 + 255) / 256, 256>>>((float4*)out);
}

// round 12
// speedup vs baseline: 1.1174x; 1.1174x over previous
#include <cuda_runtime.h>
#include <cuda_bf16.h>
#include <cuda_fp16.h>
#include <math.h>
#include <stdint.h>

// ---------------- problem constants ----------------
#define NUTT   2000
#define NROW   6000
#define NCOL   200
#define NLAY   8
#define SFULL  (NROW * NCOL)
#define WSTRIDE (NCOL * 2 * NCOL)

#define ADJ_SCALE   16384.0f
#define ADJ_ISCALE  (1.0f / 16384.0f)

// ---------------- split-bf16 MMA kernel geometry ----------------
#define BMM   128
#define NST   3
#define SA_H  0u
#define SA_L  8192u
#define SB_H  16384u
#define SB_L  30720u
#define STAGE 45056u
#define DSMEM (3*45056 + 1024)

// ---------------- fp16 single-pass kernel geometry ----------------
#define F_NST   4
#define F_SA    0u
#define F_SB    8192u
#define F_STAGE 22528u
#define F_DSMEM (4*22528 + 1024)

// ---------------- scratch ----------------
__device__ __align__(256) float g_x   [SFULL];
__device__ __align__(256) float g_h0  [SFULL];
__device__ __align__(256) float g_h   [SFULL];
__device__ __align__(256) float g_hi  [SFULL];
__device__ __align__(256) float g_part[3 * SFULL];

__device__ __align__(256) __half        g_adj16[NROW * NROW];
__device__ __align__(256) __half        g_hT16 [NCOL * NROW];
__device__ __align__(256) __nv_bfloat16 g_hih  [SFULL];
__device__ __align__(256) __nv_bfloat16 g_hil  [SFULL];
__device__ __align__(256) __nv_bfloat16 g_h0h  [SFULL];
__device__ __align__(256) __nv_bfloat16 g_h0l  [SFULL];
__device__ __align__(256) __nv_bfloat16 g_WTh8 [NLAY * WSTRIDE];
__device__ __align__(256) __nv_bfloat16 g_WTl8 [NLAY * WSTRIDE];
__device__ __align__(256) __nv_bfloat16 g_W0Th [NCOL * NCOL];
__device__ __align__(256) __nv_bfloat16 g_W0Tl [NCOL * NCOL];
__device__ __align__(256) __nv_bfloat16 g_xh   [SFULL];
__device__ __align__(256) __nv_bfloat16 g_xl   [SFULL];

__device__ __align__(256) __nv_bfloat16 g_ah_ [2000 * 304];
__device__ __align__(256) __nv_bfloat16 g_al_ [2000 * 304];
__device__ __align__(256) __nv_bfloat16 g_vh_ [2000 * 352];
__device__ __align__(256) __nv_bfloat16 g_vl_ [2000 * 352];
__device__ __align__(256) __nv_bfloat16 g_lh_ [2000 * 1024];
__device__ __align__(256) __nv_bfloat16 g_ll_ [2000 * 1024];
__device__ __align__(256) __nv_bfloat16 g_WaTh[NCOL * 304];
__device__ __align__(256) __nv_bfloat16 g_WaTl[NCOL * 304];
__device__ __align__(256) __nv_bfloat16 g_WvTh[NCOL * 352];
__device__ __align__(256) __nv_bfloat16 g_WvTl[NCOL * 352];
__device__ __align__(256) __nv_bfloat16 g_WlTh[NCOL * 1024];
__device__ __align__(256) __nv_bfloat16 g_WlTl[NCOL * 1024];

// ---------------- helpers ----------------
__device__ __forceinline__ uint32_t smem_u32(const void* p) {
    uint32_t a;
    asm("{ .reg .u64 t; cvta.to.shared.u64 t, %1; cvt.u32.u64 %0, t; }" : "=r"(a) : "l"(p));
    return a;
}
// 64B-row swizzle: phase = (row>>1)&3 — conflict-free ldmatrix + cp.async
__device__ __forceinline__ uint32_t swz(uint32_t off) {
    return off ^ ((off >> 3) & 0x30u);
}
__device__ __forceinline__ void ldsm4(uint32_t* r, uint32_t a) {
    asm volatile("ldmatrix.sync.aligned.m8n8.x4.shared.b16 {%0,%1,%2,%3}, [%4];"
                 : "=r"(r[0]), "=r"(r[1]), "=r"(r[2]), "=r"(r[3]) : "r"(a));
}
__device__ __forceinline__ void ldsm2(uint32_t* r, uint32_t a) {
    asm volatile("ldmatrix.sync.aligned.m8n8.x2.shared.b16 {%0,%1}, [%2];"
                 : "=r"(r[0]), "=r"(r[1]) : "r"(a));
}
__device__ __forceinline__ void mma_bf(float* d, const uint32_t* a, const uint32_t* b) {
    asm volatile("mma.sync.aligned.m16n8k16.row.col.f32.bf16.bf16.f32 "
                 "{%0,%1,%2,%3}, {%4,%5,%6,%7}, {%8,%9}, {%0,%1,%2,%3};"
                 : "+f"(d[0]), "+f"(d[1]), "+f"(d[2]), "+f"(d[3])
                 : "r"(a[0]), "r"(a[1]), "r"(a[2]), "r"(a[3]), "r"(b[0]), "r"(b[1]));
}
__device__ __forceinline__ void mma_hf(float* d, const uint32_t* a, const uint32_t* b) {
    asm volatile("mma.sync.aligned.m16n8k16.row.col.f32.f16.f16.f32 "
                 "{%0,%1,%2,%3}, {%4,%5,%6,%7}, {%8,%9}, {%0,%1,%2,%3};"
                 : "+f"(d[0]), "+f"(d[1]), "+f"(d[2]), "+f"(d[3])
                 : "r"(a[0]), "r"(a[1]), "r"(a[2]), "r"(a[3]), "r"(b[0]), "r"(b[1]));
}
__device__ __forceinline__ void cp16(uint32_t dst, const void* src, int sz) {
    asm volatile("cp.async.cg.shared.global [%0], [%1], 16, %2;"
                 :: "r"(dst), "l"(src), "r"(sz) : "memory");
}
__device__ __forceinline__ void cp_commit() {
    asm volatile("cp.async.commit_group;" ::: "memory");
}
__device__ __forceinline__ void split_bf(float v, __nv_bfloat16& h, __nv_bfloat16& l) {
    h = __float2bfloat16(v);
    l = __float2bfloat16(v - __bfloat162float(h));
}

// =====================================================================
// fp16 single-pass GEMM (adj path)
// =====================================================================
__device__ __forceinline__ void load_stage_f16(
    uint32_t sb, const __half* __restrict__ A, int lda,
    const __half* __restrict__ B, int ldb,
    int row0, int M, int kb, int ke, int tid)
{
    for (int g = tid; g < 1408; g += 256) {
        const __half* srow;
        uint32_t toff;
        int r, c;
        bool rv;
        if (g < 512) {
            r = g >> 2; c = g & 3;
            srow = A; toff = F_SA;
            rv = (row0 + r) < M;
            if (rv) srow += (size_t)(row0 + r) * lda;
        } else {
            int idx = g - 512;
            r = idx >> 2; c = idx & 3;
            srow = B; toff = F_SB;
            rv = r < NCOL;
            if (rv) srow += (size_t)r * ldb;
        }
        int k0 = kb + c * 8;
        int sz = 0;
        const void* sp = srow;
        if (rv) {
            int kv = (ke - k0) * 2;
            sz = kv >= 16 ? 16 : (kv > 0 ? kv : 0);
            if (sz > 0) sp = srow + k0;
        }
        cp16(sb + toff + swz((uint32_t)(r * 64 + c * 16)), sp, sz);
    }
}

__global__ __launch_bounds__(256)
void mma_f16(const __half* __restrict__ A, int lda,
             const __half* __restrict__ B, int ldb,
             int M, int Ktot, int ksize, float* __restrict__ Cbase)
{
    extern __shared__ char dsm_raw[];
    const int tid  = threadIdx.x;
    const int wid  = tid >> 5;
    const int lane = tid & 31;
    const int wm   = wid >> 2;
    const int wn   = wid & 3;
    const int row0 = blockIdx.x * BMM;
    const int ks   = blockIdx.y * ksize;
    const int ke   = (ks + ksize < Ktot) ? (ks + ksize) : Ktot;
    float* Cout = Cbase + (size_t)blockIdx.y * SFULL;

    const uint32_t base = (smem_u32(dsm_raw) + 1023u) & ~1023u;

    float acc[4][7][4];
#pragma unroll
    for (int mt = 0; mt < 4; mt++)
#pragma unroll
        for (int nt = 0; nt < 7; nt++)
#pragma unroll
            for (int q = 0; q < 4; q++) acc[mt][nt][q] = 0.0f;

    const int nck = (ke - ks + 31) >> 5;

    int issued = 0;
    for (; issued < nck && issued < F_NST - 1; issued++) {
        load_stage_f16(base + issued * F_STAGE, A, lda, B, ldb,
                       row0, M, ks + issued * 32, ke, tid);
        cp_commit();
    }

    for (int i = 0; i < nck; i++) {
        int allow = nck - i - 1;
        if (allow > F_NST - 2) allow = F_NST - 2;
        if (allow >= 2)      asm volatile("cp.async.wait_group 2;" ::: "memory");
        else if (allow == 1) asm volatile("cp.async.wait_group 1;" ::: "memory");
        else                 asm volatile("cp.async.wait_group 0;" ::: "memory");
        __syncthreads();
        if (issued < nck) {
            load_stage_f16(base + (uint32_t)(issued % F_NST) * F_STAGE, A, lda, B, ldb,
                           row0, M, ks + issued * 32, ke, tid);
            cp_commit();
            issued++;
        }

        const uint32_t aB = base + (uint32_t)(i % F_NST) * F_STAGE + F_SA;
        const uint32_t bB = base + (uint32_t)(i % F_NST) * F_STAGE + F_SB;

#pragma unroll
        for (int ksub = 0; ksub < 2; ksub++) {
            uint32_t ah[4][4];
#pragma unroll
            for (int mt = 0; mt < 4; mt++) {
                int r  = wm * 64 + mt * 16 + (lane & 15);
                int ch = 2 * ksub + (lane >> 4);
                ldsm4(ah[mt], aB + swz((uint32_t)(r * 64 + ch * 16)));
            }
#pragma unroll
            for (int nt = 0; nt < 7; nt++) {
                int rb = wn * 56 + nt * 8 + (lane & 7);
                int cb = 2 * ksub + ((lane >> 3) & 1);
                uint32_t bb[2];
                ldsm2(bb, bB + swz((uint32_t)(rb * 64 + cb * 16)));
#pragma unroll
                for (int mt = 0; mt < 4; mt++) mma_hf(acc[mt][nt], ah[mt], bb);
            }
        }
    }

#pragma unroll
    for (int mt = 0; mt < 4; mt++)
#pragma unroll
        for (int hf = 0; hf < 2; hf++) {
            const int r = row0 + wm * 64 + mt * 16 + (lane >> 2) + 8 * hf;
            if (r >= M) continue;
#pragma unroll
            for (int nt = 0; nt < 7; nt++) {
                const int c = wn * 56 + nt * 8 + (lane & 3) * 2;
                if (c >= NCOL) continue;
                float2 o;
                o.x = acc[mt][nt][2 * hf];
                o.y = acc[mt][nt][2 * hf + 1];
                *(float2*)&Cout[(size_t)r * NCOL + c] = o;
            }
        }
}

// =====================================================================
// split-bf16 3-pass GEMM.
// EP: 1 relu+bias, 3 +bias, 4 +bias+speaker,
//     5 dual-segment (by: 0 -> A @ B[:,0:200], 1 -> A2 @ B[:,200:400])
// =====================================================================
__device__ __forceinline__ void load_stage(
    uint32_t sb, const __nv_bfloat16* __restrict__ Ah, const __nv_bfloat16* __restrict__ Al,
    int lda, const __nv_bfloat16* __restrict__ Bh, const __nv_bfloat16* __restrict__ Bl,
    int ldb, int row0, int M, int kb, int ke, int tid)
{
    for (int g = tid; g < 2816; g += 256) {
        const __nv_bfloat16* srow;
        uint32_t toff;
        int r, c;
        bool rv;
        if (g < 1024) {
            int t = g >> 9, idx = g & 511;
            r = idx >> 2; c = idx & 3;
            srow = (t ? Al : Ah);
            toff = t ? SA_L : SA_H;
            rv = (row0 + r) < M;
            if (rv) srow += (size_t)(row0 + r) * lda;
        } else {
            int gb = g - 1024;
            int t = gb >= 896;
            int idx = t ? gb - 896 : gb;
            r = idx >> 2; c = idx & 3;
            srow = (t ? Bl : Bh);
            toff = t ? SB_L : SB_H;
            rv = r < NCOL;
            if (rv) srow += (size_t)r * ldb;
        }
        int k0 = kb + c * 8;
        int sz = 0;
        const void* sp = srow;
        if (rv) {
            int kv = (ke - k0) * 2;
            sz = kv >= 16 ? 16 : (kv > 0 ? kv : 0);
            if (sz > 0) sp = srow + k0;
        }
        cp16(sb + toff + swz((uint32_t)(r * 64 + c * 16)), sp, sz);
    }
}

template <int EP>
__global__ __launch_bounds__(256)
void mma_gemm(const __nv_bfloat16* __restrict__ Ah, const __nv_bfloat16* __restrict__ Al, int lda,
              const __nv_bfloat16* __restrict__ Bh, const __nv_bfloat16* __restrict__ Bl, int ldb,
              int M, int Ktot,
              float* __restrict__ Cbase,
              const float* __restrict__ bias,
              const float* __restrict__ aux0, const float* __restrict__ aux1,
              const __nv_bfloat16* __restrict__ Ah2, const __nv_bfloat16* __restrict__ Al2)
{
    extern __shared__ char dsm_raw[];
    const int tid  = threadIdx.x;
    const int wid  = tid >> 5;
    const int lane = tid & 31;
    const int wm   = wid >> 2;
    const int wn   = wid & 3;
    const int row0 = blockIdx.x * BMM;
    const int seg  = blockIdx.y;
    float* Cout = (EP == 5) ? (Cbase + (size_t)seg * SFULL) : Cbase;

    const __nv_bfloat16* AhU = (EP == 5 && seg) ? Ah2 : Ah;
    const __nv_bfloat16* AlU = (EP == 5 && seg) ? Al2 : Al;
    const __nv_bfloat16* BhU = (EP == 5) ? (Bh + seg * NCOL) : Bh;
    const __nv_bfloat16* BlU = (EP == 5) ? (Bl + seg * NCOL) : Bl;

    const uint32_t base = (smem_u32(dsm_raw) + 1023u) & ~1023u;

    float acc[4][7][4];
#pragma unroll
    for (int mt = 0; mt < 4; mt++)
#pragma unroll
        for (int nt = 0; nt < 7; nt++)
#pragma unroll
            for (int q = 0; q < 4; q++) acc[mt][nt][q] = 0.0f;

    const int nck = (Ktot + 31) >> 5;

    int issued = 0;
    for (; issued < nck && issued < NST - 1; issued++) {
        load_stage(base + issued * STAGE, AhU, AlU, lda, BhU, BlU, ldb,
                   row0, M, issued * 32, Ktot, tid);
        cp_commit();
    }

    for (int i = 0; i < nck; i++) {
        if (nck - i >= 2) asm volatile("cp.async.wait_group 1;" ::: "memory");
        else              asm volatile("cp.async.wait_group 0;" ::: "memory");
        __syncthreads();
        if (issued < nck) {
            load_stage(base + (uint32_t)(issued % NST) * STAGE, AhU, AlU, lda, BhU, BlU, ldb,
                       row0, M, issued * 32, Ktot, tid);
            cp_commit();
            issued++;
        }

        const uint32_t sb  = base + (uint32_t)(i % NST) * STAGE;
        const uint32_t aHu = sb + SA_H, aLu = sb + SA_L;
        const uint32_t bHu = sb + SB_H, bLu = sb + SB_L;

#pragma unroll
        for (int ksub = 0; ksub < 2; ksub++) {
            uint32_t ah[4][4], al[4][4];
#pragma unroll
            for (int mt = 0; mt < 4; mt++) {
                int r  = wm * 64 + mt * 16 + (lane & 15);
                int ch = 2 * ksub + (lane >> 4);
                uint32_t off = swz((uint32_t)(r * 64 + ch * 16));
                ldsm4(ah[mt], aHu + off);
                ldsm4(al[mt], aLu + off);
            }
#pragma unroll
            for (int nt = 0; nt < 7; nt++) {
                int rb = wn * 56 + nt * 8 + (lane & 7);
                int cb = 2 * ksub + ((lane >> 3) & 1);
                uint32_t off = swz((uint32_t)(rb * 64 + cb * 16));
                uint32_t bh[2], bl[2];
                ldsm2(bh, bHu + off);
                ldsm2(bl, bLu + off);
#pragma unroll
                for (int mt = 0; mt < 4; mt++) {
                    mma_bf(acc[mt][nt], ah[mt], bh);
                    mma_bf(acc[mt][nt], ah[mt], bl);
                    mma_bf(acc[mt][nt], al[mt], bh);
                }
            }
        }
    }

#pragma unroll
    for (int mt = 0; mt < 4; mt++) {
#pragma unroll
        for (int hf = 0; hf < 2; hf++) {
            const int r = row0 + wm * 64 + mt * 16 + (lane >> 2) + 8 * hf;
            if (r >= M) continue;
            int spk = 0;
            if (EP == 4) {
                int bI = r / 100, tI = r % 100;
                const float* q = aux0 + ((size_t)tI * 20 + bI) * 2;
                spk = (q[1] > q[0]) ? 1 : 0;
            }
#pragma unroll
            for (int nt = 0; nt < 7; nt++) {
                const int c = wn * 56 + nt * 8 + (lane & 3) * 2;
                if (c >= NCOL) continue;
                float vx = acc[mt][nt][2 * hf];
                float vy = acc[mt][nt][2 * hf + 1];
                if (EP == 1) {
                    vx = fmaxf(vx + bias[c], 0.0f);
                    vy = fmaxf(vy + bias[c + 1], 0.0f);
                } else if (EP == 3) {
                    vx += bias[c];
                    vy += bias[c + 1];
                } else if (EP == 4) {
                    vx += bias[c]     + aux1[spk * NCOL + c];
                    vy += bias[c + 1] + aux1[spk * NCOL + c + 1];
                }
                float2 o; o.x = vx; o.y = vy;
                *(float2*)&Cout[(size_t)r * NCOL + c] = o;
            }
        }
    }
}

// =====================================================================
// elementwise / conversion kernels
// =====================================================================
__global__ void convert_adj(const float4* __restrict__ src, __half* __restrict__ dst) {
    int i = blockIdx.x * blockDim.x + threadIdx.x;
    if (i < NROW * NROW / 8) {
        float4 v0 = src[2 * i];
        float4 v1 = src[2 * i + 1];
        __half2 a = __floats2half2_rn(v0.x * ADJ_SCALE, v0.y * ADJ_SCALE);
        __half2 b = __floats2half2_rn(v0.z * ADJ_SCALE, v0.w * ADJ_SCALE);
        __half2 c = __floats2half2_rn(v1.x * ADJ_SCALE, v1.y * ADJ_SCALE);
        __half2 d = __floats2half2_rn(v1.z * ADJ_SCALE, v1.w * ADJ_SCALE);
        uint4 o;
        o.x = *(uint32_t*)&a; o.y = *(uint32_t*)&b;
        o.z = *(uint32_t*)&c; o.w = *(uint32_t*)&d;
        ((uint4*)dst)[i] = o;
    }
}

__global__ void convert_split4(const float* __restrict__ src, int n4,
                               __nv_bfloat16* __restrict__ dh,
                               __nv_bfloat16* __restrict__ dl)
{
    int i = blockIdx.x * blockDim.x + threadIdx.x;
    if (i < n4) {
        float4 v = ((const float4*)src)[i];
        __nv_bfloat16 h0, l0, h1, l1, h2, l2, h3, l3;
        split_bf(v.x, h0, l0); split_bf(v.y, h1, l1);
        split_bf(v.z, h2, l2); split_bf(v.w, h3, l3);
        __nv_bfloat162* H = (__nv_bfloat162*)dh;
        __nv_bfloat162* L = (__nv_bfloat162*)dl;
        H[2 * i]     = __nv_bfloat162(h0, h1);
        H[2 * i + 1] = __nv_bfloat162(h2, h3);
        L[2 * i]     = __nv_bfloat162(l0, l1);
        L[2 * i + 1] = __nv_bfloat162(l2, l3);
    }
}

__global__ void padsplit(const float* __restrict__ src, int R, int C, int Cp,
                         __nv_bfloat16* __restrict__ dh, __nv_bfloat16* __restrict__ dl)
{
    int i = blockIdx.x * blockDim.x + threadIdx.x;
    if (i < R * Cp) {
        int r = i / Cp, c = i % Cp;
        float v = (c < C) ? src[(size_t)r * C + c] : 0.0f;
        __nv_bfloat16 h, l;
        split_bf(v, h, l);
        dh[i] = h; dl[i] = l;
    }
}

__global__ void tsplit(const float* __restrict__ src, int R, int C, int Rp,
                       __nv_bfloat16* __restrict__ dh, __nv_bfloat16* __restrict__ dl)
{
    __shared__ float t[32][33];
    int r = blockIdx.x * 32 + threadIdx.y;
    int c = blockIdx.y * 32 + threadIdx.x;
    if (r < R && c < C) t[threadIdx.y][threadIdx.x] = src[(size_t)r * C + c];
    __syncthreads();
    int rr = blockIdx.x * 32 + threadIdx.x;
    int cc = blockIdx.y * 32 + threadIdx.y;
    if (rr < Rp && cc < C) {
        float v = (rr < R) ? t[threadIdx.x][threadIdx.y] : 0.0f;
        __nv_bfloat16 h, l;
        split_bf(v, h, l);
        dh[(size_t)cc * Rp + rr] = h;
        dl[(size_t)cc * Rp + rr] = l;
    }
}

// batched W transposes: z=0 -> W0 [200,200], z=1..8 -> convW layer [400,200]
__global__ void tsplit_w(const float* __restrict__ W0, const float* __restrict__ convW) {
    __shared__ float t[32][33];
    int z = blockIdx.z;
    const float* src;
    __nv_bfloat16 *dh, *dl;
    int R;
    if (z == 0) { src = W0; dh = g_W0Th; dl = g_W0Tl; R = NCOL; }
    else {
        src = convW + (size_t)(z - 1) * 2 * NCOL * NCOL;
        dh = g_WTh8 + (size_t)(z - 1) * WSTRIDE;
        dl = g_WTl8 + (size_t)(z - 1) * WSTRIDE;
        R = 2 * NCOL;
    }
    int r = blockIdx.x * 32 + threadIdx.y;
    int c = blockIdx.y * 32 + threadIdx.x;
    if (r < R && c < NCOL) t[threadIdx.y][threadIdx.x] = src[(size_t)r * NCOL + c];
    __syncthreads();
    int rr = blockIdx.x * 32 + threadIdx.x;
    int cc = blockIdx.y * 32 + threadIdx.y;
    if (rr < R && cc < NCOL) {
        __nv_bfloat16 h, l;
        split_bf(t[threadIdx.x][threadIdx.y], h, l);
        dh[(size_t)cc * R + rr] = h;
        dl[(size_t)cc * R + rr] = l;
    }
}

// transpose h0 -> g_hT16 (once)
__global__ void t_f16(const float* __restrict__ src) {
    __shared__ float t[32][33];
    int r = blockIdx.x * 32 + threadIdx.y;
    int c = blockIdx.y * 32 + threadIdx.x;
    if (r < NROW && c < NCOL) t[threadIdx.y][threadIdx.x] = src[(size_t)r * NCOL + c];
    __syncthreads();
    int rr = blockIdx.x * 32 + threadIdx.x;
    int cc = blockIdx.y * 32 + threadIdx.y;
    if (rr < NROW && cc < NCOL)
        g_hT16[(size_t)cc * NROW + rr] = __float2half(t[threadIdx.x][threadIdx.y]);
}

// hi = (sum of 3 adj partials)*2^-14 ; write f32 + linear bf16 split
__global__ void reduce_hi() {
    int i = blockIdx.x * blockDim.x + threadIdx.x;
    if (i < SFULL / 4) {
        const float4* p = (const float4*)g_part;
        float4 a = p[i], b = p[i + SFULL / 4], c = p[i + SFULL / 2];
        float4 s;
        s.x = (a.x + b.x + c.x) * ADJ_ISCALE;
        s.y = (a.y + b.y + c.y) * ADJ_ISCALE;
        s.z = (a.z + b.z + c.z) * ADJ_ISCALE;
        s.w = (a.w + b.w + c.w) * ADJ_ISCALE;
        ((float4*)g_hi)[i] = s;
        __nv_bfloat16 h0, l0, h1, l1, h2, l2, h3, l3;
        split_bf(s.x, h0, l0); split_bf(s.y, h1, l1);
        split_bf(s.z, h2, l2); split_bf(s.w, h3, l3);
        __nv_bfloat162 H0(h0, h1), H1(h2, h3), L0(l0, l1), L1(l2, l3);
        uint2 oh, ol;
        oh.x = *(uint32_t*)&H0; oh.y = *(uint32_t*)&H1;
        ol.x = *(uint32_t*)&L0; ol.y = *(uint32_t*)&L1;
        ((uint2*)g_hih)[i] = oh;
        ((uint2*)g_hil)[i] = ol;
    }
}

// combine 2 S@W partials + GCNII + relu -> g_h ; also write h^T fp16
__global__ void reduce_gcnii(float theta) {
    __shared__ float t[32][33];
    const int r0 = blockIdx.x * 32;
    const int c0 = blockIdx.y * 32;
    const int S = SFULL;
#pragma unroll
    for (int q = 0; q < 4; q++) {
        int r = r0 + threadIdx.y * 4 + q;
        int c = c0 + threadIdx.x;
        float val = 0.0f;
        if (r < NROW && c < NCOL) {
            int i = r * NCOL + c;
            float sw = g_part[i] + g_part[i + S];
            float rr = 0.9f * g_hi[i] + 0.1f * g_h0[i];
            val = fmaxf(theta * sw + (1.0f - theta) * rr, 0.0f);
            g_h[i] = val;
        }
        t[threadIdx.y * 4 + q][threadIdx.x] = val;
    }
    __syncthreads();
#pragma unroll
    for (int q = 0; q < 4; q++) {
        int rr2 = r0 + threadIdx.x;
        int cc  = c0 + threadIdx.y * 4 + q;
        if (rr2 < NROW && cc < NCOL)
            g_hT16[(size_t)cc * NROW + rr2] = __float2half(t[threadIdx.x][threadIdx.y * 4 + q]);
    }
}

__global__ void assemble_kernel(float4* __restrict__ out) {
    int i4 = blockIdx.x * blockDim.x + threadIdx.x;
    if (i4 < NUTT * 300) {
        int row = i4 / 300;
        int c4  = i4 % 300;
        int m   = c4 / 100;
        int j   = c4 % 100;
        const float4* src = (j < 50) ? (const float4*)g_x : (const float4*)g_h;
        out[i4] = src[(size_t)(m * NUTT + row) * 50 + (j % 50)];
    }
}

// =====================================================================
extern "C" void kernel_launch(void* const* d_in, const int* in_sizes, int n_in,
                              void* d_out, int out_size)
{
    const float* a     = (const float*)d_in[0];
    const float* v     = (const float*)d_in[1];
    const float* l     = (const float*)d_in[2];
    const float* qmask = (const float*)d_in[3];
    const float* adj   = (const float*)d_in[4];
    const float* Wa    = (const float*)d_in[5];
    const float* ba    = (const float*)d_in[6];
    const float* Wv    = (const float*)d_in[7];
    const float* bv    = (const float*)d_in[8];
    const float* Wl    = (const float*)d_in[9];
    const float* bl    = (const float*)d_in[10];
    const float* spk   = (const float*)d_in[11];
    const float* W0    = (const float*)d_in[12];
    const float* b0    = (const float*)d_in[13];
    const float* convW = (const float*)d_in[14];
    float* out = (float*)d_out;

    float *gx, *gh0, *gpart;
    __half *adj16, *hT16;
    __nv_bfloat16 *hih, *hil, *h0h, *h0l, *WTh8, *WTl8, *W0Th, *W0Tl, *xh, *xl;
    __nv_bfloat16 *ah_, *al_, *vh_, *vl_, *lh_, *ll_;
    __nv_bfloat16 *WaTh, *WaTl, *WvTh, *WvTl, *WlTh, *WlTl;
    cudaGetSymbolAddress((void**)&gx,    g_x);
    cudaGetSymbolAddress((void**)&gh0,   g_h0);
    cudaGetSymbolAddress((void**)&gpart, g_part);
    cudaGetSymbolAddress((void**)&adj16, g_adj16);
    cudaGetSymbolAddress((void**)&hT16,  g_hT16);
    cudaGetSymbolAddress((void**)&hih,   g_hih);
    cudaGetSymbolAddress((void**)&hil,   g_hil);
    cudaGetSymbolAddress((void**)&h0h,   g_h0h);
    cudaGetSymbolAddress((void**)&h0l,   g_h0l);
    cudaGetSymbolAddress((void**)&WTh8,  g_WTh8);
    cudaGetSymbolAddress((void**)&WTl8,  g_WTl8);
    cudaGetSymbolAddress((void**)&W0Th,  g_W0Th);
    cudaGetSymbolAddress((void**)&W0Tl,  g_W0Tl);
    cudaGetSymbolAddress((void**)&xh,    g_xh);
    cudaGetSymbolAddress((void**)&xl,    g_xl);
    cudaGetSymbolAddress((void**)&ah_,   g_ah_);
    cudaGetSymbolAddress((void**)&al_,   g_al_);
    cudaGetSymbolAddress((void**)&vh_,   g_vh_);
    cudaGetSymbolAddress((void**)&vl_,   g_vl_);
    cudaGetSymbolAddress((void**)&lh_,   g_lh_);
    cudaGetSymbolAddress((void**)&ll_,   g_ll_);
    cudaGetSymbolAddress((void**)&WaTh,  g_WaTh);
    cudaGetSymbolAddress((void**)&WaTl,  g_WaTl);
    cudaGetSymbolAddress((void**)&WvTh,  g_WvTh);
    cudaGetSymbolAddress((void**)&WvTl,  g_WvTl);
    cudaGetSymbolAddress((void**)&WlTh,  g_WlTh);
    cudaGetSymbolAddress((void**)&WlTl,  g_WlTl);

    cudaFuncSetAttribute(mma_f16,     cudaFuncAttributeMaxDynamicSharedMemorySize, F_DSMEM);
    cudaFuncSetAttribute(mma_gemm<1>, cudaFuncAttributeMaxDynamicSharedMemorySize, DSMEM);
    cudaFuncSetAttribute(mma_gemm<3>, cudaFuncAttributeMaxDynamicSharedMemorySize, DSMEM);
    cudaFuncSetAttribute(mma_gemm<4>, cudaFuncAttributeMaxDynamicSharedMemorySize, DSMEM);
    cudaFuncSetAttribute(mma_gemm<5>, cudaFuncAttributeMaxDynamicSharedMemorySize, DSMEM);

    // ---- one-time conversions ----
    convert_adj<<<(NROW * NROW / 8 + 255) / 256, 256>>>((const float4*)adj, adj16);
    padsplit<<<(2000 * 304 + 255) / 256, 256>>>(a, 2000, 300,  304,  ah_, al_);
    padsplit<<<(2000 * 352 + 255) / 256, 256>>>(v, 2000, 342,  352,  vh_, vl_);
    padsplit<<<(2000 * 1024 + 255) / 256, 256>>>(l, 2000, 1024, 1024, lh_, ll_);
    tsplit<<<dim3(10, 7), dim3(32, 32)>>>(Wa, 300,  NCOL, 304,  WaTh, WaTl);
    tsplit<<<dim3(11, 7), dim3(32, 32)>>>(Wv, 342,  NCOL, 352,  WvTh, WvTl);
    tsplit<<<dim3(32, 7), dim3(32, 32)>>>(Wl, 1024, NCOL, 1024, WlTh, WlTl);
    tsplit_w<<<dim3(13, 7, 9), dim3(32, 32)>>>(W0, convW);

    // ---- modality projections -> g_x ----
    const int gProj = (NUTT + BMM - 1) / BMM;    // 16
    const int gFull = (NROW + BMM - 1) / BMM;    // 47
    mma_gemm<3><<<dim3(gProj, 1), 256, DSMEM>>>(ah_, al_, 304, WaTh, WaTl, 304,
        NUTT, 304, gx, ba, nullptr, nullptr, nullptr, nullptr);
    mma_gemm<3><<<dim3(gProj, 1), 256, DSMEM>>>(vh_, vl_, 352, WvTh, WvTl, 352,
        NUTT, 352, gx + (size_t)NUTT * NCOL, bv, nullptr, nullptr, nullptr, nullptr);
    mma_gemm<4><<<dim3(gProj, 1), 256, DSMEM>>>(lh_, ll_, 1024, WlTh, WlTl, 1024,
        NUTT, 1024, gx + (size_t)2 * NUTT * NCOL, bl, qmask, spk, nullptr, nullptr);

    // ---- h0 = relu(x @ W0 + b0) ----
    convert_split4<<<(SFULL / 4 + 255) / 256, 256>>>(gx, SFULL / 4, xh, xl);
    mma_gemm<1><<<dim3(gFull, 1), 256, DSMEM>>>(xh, xl, NCOL, W0Th, W0Tl, NCOL,
        NROW, NCOL, gh0, b0, nullptr, nullptr, nullptr, nullptr);
    convert_split4<<<(SFULL / 4 + 255) / 256, 256>>>(gh0, SFULL / 4, h0h, h0l);
    t_f16<<<dim3(188, 7), dim3(32, 32)>>>(gh0);

    // ---- GCNII layers (4 launches each; weights pre-transposed) ----
    for (int lay = 0; lay < NLAY; lay++) {
        float theta = logf(0.5f / (float)(lay + 1) + 1.0f);

        // hi partials = (adj*2^14) @ h   (fp16, K split 3)
        mma_f16<<<dim3(gFull, 3), 256, F_DSMEM>>>(adj16, NROW, hT16, NROW,
            NROW, NROW, 2000, gpart);
        reduce_hi<<<(SFULL / 4 + 255) / 256, 256>>>();

        // S@W = hi @ W[:200] + h0 @ W[200:]  (dual-segment, 2 partials)
        const __nv_bfloat16* Wh  = WTh8 + (size_t)lay * WSTRIDE;
        const __nv_bfloat16* Wl2 = WTl8 + (size_t)lay * WSTRIDE;
        mma_gemm<5><<<dim3(gFull, 2), 256, DSMEM>>>(hih, hil, NCOL, Wh, Wl2, 2 * NCOL,
            NROW, NCOL, gpart, nullptr, nullptr, nullptr, h0h, h0l);

        // combine + relu -> g_h ; write h^T fp16 for next layer
        reduce_gcnii<<<dim3(188, 7), dim3(32, 8)>>>(theta);
    }

    assemble_kernel<<<(NUTT * 300 + 255) / 256, 256>>>((float4*)out);
}

// round 13
// speedup vs baseline: 1.2285x; 1.0994x over previous
#include <cuda_runtime.h>
#include <cuda_bf16.h>
#include <cuda_fp16.h>
#include <math.h>
#include <stdint.h>

#define NUTT   2000
#define NROW   6000
#define NCOL   200
#define NLAY   8
#define SFULL  (NROW * NCOL)
#define WSTRIDE (NCOL * 2 * NCOL)

#define ADJ_SCALE   16384.0f
#define ADJ_ISCALE  (1.0f / 16384.0f)

#define BMM   128
#define NST   3
#define SA_H  0u
#define SA_L  8192u
#define SB_H  16384u
#define SB_L  30720u
#define STAGE 45056u
#define DSMEM (3*45056 + 1024)

#define F_NST   4
#define F_SA    0u
#define F_SB    8192u
#define F_STAGE 22528u
#define F_DSMEM (4*22528 + 1024)

__device__ __align__(256) float g_x   [SFULL];
__device__ __align__(256) float g_h0  [SFULL];
__device__ __align__(256) float g_h   [SFULL];
__device__ __align__(256) float g_hi  [SFULL];
__device__ __align__(256) float g_part[3 * SFULL];

__device__ __align__(256) __half        g_adj16[NROW * NROW];
__device__ __align__(256) __half        g_hT16 [NCOL * NROW];
__device__ __align__(256) __nv_bfloat16 g_hih  [SFULL];
__device__ __align__(256) __nv_bfloat16 g_hil  [SFULL];
__device__ __align__(256) __nv_bfloat16 g_h0h  [SFULL];
__device__ __align__(256) __nv_bfloat16 g_h0l  [SFULL];
__device__ __align__(256) __nv_bfloat16 g_WTh8 [NLAY * WSTRIDE];
__device__ __align__(256) __nv_bfloat16 g_WTl8 [NLAY * WSTRIDE];
__device__ __align__(256) __nv_bfloat16 g_W0Th [NCOL * NCOL];
__device__ __align__(256) __nv_bfloat16 g_W0Tl [NCOL * NCOL];
__device__ __align__(256) __nv_bfloat16 g_xh   [SFULL];
__device__ __align__(256) __nv_bfloat16 g_xl   [SFULL];

__device__ __align__(256) __half g_a16  [2000 * 304];
__device__ __align__(256) __half g_v16  [2000 * 352];
__device__ __align__(256) __half g_l16  [2000 * 1024];
__device__ __align__(256) __half g_WaT16[NCOL * 304];
__device__ __align__(256) __half g_WvT16[NCOL * 352];
__device__ __align__(256) __half g_WlT16[NCOL * 1024];

__device__ __forceinline__ uint32_t smem_u32(const void* p) {
    uint32_t a;
    asm("{ .reg .u64 t; cvta.to.shared.u64 t, %1; cvt.u32.u64 %0, t; }" : "=r"(a) : "l"(p));
    return a;
}
__device__ __forceinline__ uint32_t swz(uint32_t off) {
    return off ^ ((off >> 3) & 0x30u);
}
__device__ __forceinline__ void ldsm4(uint32_t* r, uint32_t a) {
    asm volatile("ldmatrix.sync.aligned.m8n8.x4.shared.b16 {%0,%1,%2,%3}, [%4];"
                 : "=r"(r[0]), "=r"(r[1]), "=r"(r[2]), "=r"(r[3]) : "r"(a));
}
__device__ __forceinline__ void ldsm2(uint32_t* r, uint32_t a) {
    asm volatile("ldmatrix.sync.aligned.m8n8.x2.shared.b16 {%0,%1}, [%2];"
                 : "=r"(r[0]), "=r"(r[1]) : "r"(a));
}
__device__ __forceinline__ void mma_bf(float* d, const uint32_t* a, const uint32_t* b) {
    asm volatile("mma.sync.aligned.m16n8k16.row.col.f32.bf16.bf16.f32 "
                 "{%0,%1,%2,%3}, {%4,%5,%6,%7}, {%8,%9}, {%0,%1,%2,%3};"
                 : "+f"(d[0]), "+f"(d[1]), "+f"(d[2]), "+f"(d[3])
                 : "r"(a[0]), "r"(a[1]), "r"(a[2]), "r"(a[3]), "r"(b[0]), "r"(b[1]));
}
__device__ __forceinline__ void mma_hf(float* d, const uint32_t* a, const uint32_t* b) {
    asm volatile("mma.sync.aligned.m16n8k16.row.col.f32.f16.f16.f32 "
                 "{%0,%1,%2,%3}, {%4,%5,%6,%7}, {%8,%9}, {%0,%1,%2,%3};"
                 : "+f"(d[0]), "+f"(d[1]), "+f"(d[2]), "+f"(d[3])
                 : "r"(a[0]), "r"(a[1]), "r"(a[2]), "r"(a[3]), "r"(b[0]), "r"(b[1]));
}
__device__ __forceinline__ void cp16(uint32_t dst, const void* src, int sz) {
    asm volatile("cp.async.cg.shared.global [%0], [%1], 16, %2;"
                 :: "r"(dst), "l"(src), "r"(sz) : "memory");
}
__device__ __forceinline__ void cp_commit() {
    asm volatile("cp.async.commit_group;" ::: "memory");
}
__device__ __forceinline__ void split_bf(float v, __nv_bfloat16& h, __nv_bfloat16& l) {
    h = __float2bfloat16(v);
    l = __float2bfloat16(v - __bfloat162float(h));
}

// ---------------- fp16 stage loader + mainloop ----------------
__device__ __forceinline__ void load_stage_f16(
    uint32_t sb, const __half* __restrict__ A, int lda,
    const __half* __restrict__ B, int ldb,
    int row0, int M, int kb, int ke, int tid)
{
    for (int g = tid; g < 1408; g += 256) {
        const __half* srow;
        uint32_t toff;
        int r, c;
        bool rv;
        if (g < 512) {
            r = g >> 2; c = g & 3;
            srow = A; toff = F_SA;
            rv = (row0 + r) < M;
            if (rv) srow += (size_t)(row0 + r) * lda;
        } else {
            int idx = g - 512;
            r = idx >> 2; c = idx & 3;
            srow = B; toff = F_SB;
            rv = r < NCOL;
            if (rv) srow += (size_t)r * ldb;
        }
        int k0 = kb + c * 8;
        int sz = 0;
        const void* sp = srow;
        if (rv) {
            int kv = (ke - k0) * 2;
            sz = kv >= 16 ? 16 : (kv > 0 ? kv : 0);
            if (sz > 0) sp = srow + k0;
        }
        cp16(sb + toff + swz((uint32_t)(r * 64 + c * 16)), sp, sz);
    }
}

__device__ __forceinline__ void f16_mainloop(
    float acc[4][7][4], uint32_t base,
    const __half* __restrict__ A, int lda,
    const __half* __restrict__ B, int ldb,
    int row0, int M, int ks, int ke, int tid, int wm, int wn, int lane)
{
    const int nck = (ke - ks + 31) >> 5;
    int issued = 0;
    for (; issued < nck && issued < F_NST - 1; issued++) {
        load_stage_f16(base + issued * F_STAGE, A, lda, B, ldb,
                       row0, M, ks + issued * 32, ke, tid);
        cp_commit();
    }
    for (int i = 0; i < nck; i++) {
        int allow = nck - i - 1;
        if (allow > F_NST - 2) allow = F_NST - 2;
        if (allow >= 2)      asm volatile("cp.async.wait_group 2;" ::: "memory");
        else if (allow == 1) asm volatile("cp.async.wait_group 1;" ::: "memory");
        else                 asm volatile("cp.async.wait_group 0;" ::: "memory");
        __syncthreads();
        if (issued < nck) {
            load_stage_f16(base + (uint32_t)(issued % F_NST) * F_STAGE, A, lda, B, ldb,
                           row0, M, ks + issued * 32, ke, tid);
            cp_commit();
            issued++;
        }
        const uint32_t aB = base + (uint32_t)(i % F_NST) * F_STAGE + F_SA;
        const uint32_t bB = base + (uint32_t)(i % F_NST) * F_STAGE + F_SB;
#pragma unroll
        for (int ksub = 0; ksub < 2; ksub++) {
            uint32_t ah[4][4];
#pragma unroll
            for (int mt = 0; mt < 4; mt++) {
                int r  = wm * 64 + mt * 16 + (lane & 15);
                int ch = 2 * ksub + (lane >> 4);
                ldsm4(ah[mt], aB + swz((uint32_t)(r * 64 + ch * 16)));
            }
#pragma unroll
            for (int nt = 0; nt < 7; nt++) {
                int rb = wn * 56 + nt * 8 + (lane & 7);
                int cb = 2 * ksub + ((lane >> 3) & 1);
                uint32_t bb[2];
                ldsm2(bb, bB + swz((uint32_t)(rb * 64 + cb * 16)));
#pragma unroll
                for (int mt = 0; mt < 4; mt++) mma_hf(acc[mt][nt], ah[mt], bb);
            }
        }
    }
}

// ---------------- adj path ----------------
__global__ __launch_bounds__(256)
void mma_f16(const __half* __restrict__ A, int lda,
             const __half* __restrict__ B, int ldb,
             int M, int Ktot, int ksize, float* __restrict__ Cbase)
{
    extern __shared__ char dsm_raw[];
    const int tid  = threadIdx.x;
    const int wid  = tid >> 5;
    const int lane = tid & 31;
    const int wm   = wid >> 2;
    const int wn   = wid & 3;
    const int row0 = blockIdx.x * BMM;
    const int ks   = blockIdx.y * ksize;
    const int ke   = (ks + ksize < Ktot) ? (ks + ksize) : Ktot;
    float* Cout = Cbase + (size_t)blockIdx.y * SFULL;

    const uint32_t base = (smem_u32(dsm_raw) + 1023u) & ~1023u;

    float acc[4][7][4];
#pragma unroll
    for (int mt = 0; mt < 4; mt++)
#pragma unroll
        for (int nt = 0; nt < 7; nt++)
#pragma unroll
            for (int q = 0; q < 4; q++) acc[mt][nt][q] = 0.0f;

    f16_mainloop(acc, base, A, lda, B, ldb, row0, M, ks, ke, tid, wm, wn, lane);

#pragma unroll
    for (int mt = 0; mt < 4; mt++)
#pragma unroll
        for (int hf = 0; hf < 2; hf++) {
            const int r = row0 + wm * 64 + mt * 16 + (lane >> 2) + 8 * hf;
            if (r >= M) continue;
#pragma unroll
            for (int nt = 0; nt < 7; nt++) {
                const int c = wn * 56 + nt * 8 + (lane & 3) * 2;
                if (c >= NCOL) continue;
                float2 o;
                o.x = acc[mt][nt][2 * hf];
                o.y = acc[mt][nt][2 * hf + 1];
                *(float2*)&Cout[(size_t)r * NCOL + c] = o;
            }
        }
}

// ---------------- all 3 modality projections in one launch ----------------
__global__ __launch_bounds__(256)
void mma_f16_proj(const __half* __restrict__ A0, const __half* __restrict__ A1,
                  const __half* __restrict__ A2,
                  const __half* __restrict__ B0, const __half* __restrict__ B1,
                  const __half* __restrict__ B2,
                  int K0, int K1, int K2,
                  const float* __restrict__ ba, const float* __restrict__ bv,
                  const float* __restrict__ bl,
                  const float* __restrict__ qmask, const float* __restrict__ spkE,
                  float* __restrict__ Cbase)
{
    extern __shared__ char dsm_raw[];
    const int tid  = threadIdx.x;
    const int wid  = tid >> 5;
    const int lane = tid & 31;
    const int wm   = wid >> 2;
    const int wn   = wid & 3;
    const int row0 = blockIdx.x * BMM;
    const int m    = blockIdx.y;

    const __half* A = (m == 0) ? A0 : (m == 1) ? A1 : A2;
    const __half* B = (m == 0) ? B0 : (m == 1) ? B1 : B2;
    const int     K = (m == 0) ? K0 : (m == 1) ? K1 : K2;
    const float* bias = (m == 0) ? ba : (m == 1) ? bv : bl;
    float* Cout = Cbase + (size_t)m * NUTT * NCOL;

    const uint32_t base = (smem_u32(dsm_raw) + 1023u) & ~1023u;

    float acc[4][7][4];
#pragma unroll
    for (int mt = 0; mt < 4; mt++)
#pragma unroll
        for (int nt = 0; nt < 7; nt++)
#pragma unroll
            for (int q = 0; q < 4; q++) acc[mt][nt][q] = 0.0f;

    f16_mainloop(acc, base, A, K, B, K, row0, NUTT, 0, K, tid, wm, wn, lane);

#pragma unroll
    for (int mt = 0; mt < 4; mt++)
#pragma unroll
        for (int hf = 0; hf < 2; hf++) {
            const int r = row0 + wm * 64 + mt * 16 + (lane >> 2) + 8 * hf;
            if (r >= NUTT) continue;
            int spk = 0;
            if (m == 2) {
                int bI = r / 100, tI = r % 100;
                const float* q = qmask + ((size_t)tI * 20 + bI) * 2;
                spk = (q[1] > q[0]) ? 1 : 0;
            }
#pragma unroll
            for (int nt = 0; nt < 7; nt++) {
                const int c = wn * 56 + nt * 8 + (lane & 3) * 2;
                if (c >= NCOL) continue;
                float vx = acc[mt][nt][2 * hf] + bias[c];
                float vy = acc[mt][nt][2 * hf + 1] + bias[c + 1];
                if (m == 2) {
                    vx += spkE[spk * NCOL + c];
                    vy += spkE[spk * NCOL + c + 1];
                }
                float2 o; o.x = vx; o.y = vy;
                *(float2*)&Cout[(size_t)r * NCOL + c] = o;
            }
        }
}

// =====================================================================
// split-bf16 3-pass GEMM. EP: 1 relu+bias, 5 dual-segment
// =====================================================================
__device__ __forceinline__ void load_stage(
    uint32_t sb, const __nv_bfloat16* __restrict__ Ah, const __nv_bfloat16* __restrict__ Al,
    int lda, const __nv_bfloat16* __restrict__ Bh, const __nv_bfloat16* __restrict__ Bl,
    int ldb, int row0, int M, int kb, int ke, int tid)
{
    for (int g = tid; g < 2816; g += 256) {
        const __nv_bfloat16* srow;
        uint32_t toff;
        int r, c;
        bool rv;
        if (g < 1024) {
            int t = g >> 9, idx = g & 511;
            r = idx >> 2; c = idx & 3;
            srow = (t ? Al : Ah);
            toff = t ? SA_L : SA_H;
            rv = (row0 + r) < M;
            if (rv) srow += (size_t)(row0 + r) * lda;
        } else {
            int gb = g - 1024;
            int t = gb >= 896;
            int idx = t ? gb - 896 : gb;
            r = idx >> 2; c = idx & 3;
            srow = (t ? Bl : Bh);
            toff = t ? SB_L : SB_H;
            rv = r < NCOL;
            if (rv) srow += (size_t)r * ldb;
        }
        int k0 = kb + c * 8;
        int sz = 0;
        const void* sp = srow;
        if (rv) {
            int kv = (ke - k0) * 2;
            sz = kv >= 16 ? 16 : (kv > 0 ? kv : 0);
            if (sz > 0) sp = srow + k0;
        }
        cp16(sb + toff + swz((uint32_t)(r * 64 + c * 16)), sp, sz);
    }
}

template <int EP>
__global__ __launch_bounds__(256)
void mma_gemm(const __nv_bfloat16* __restrict__ Ah, const __nv_bfloat16* __restrict__ Al, int lda,
              const __nv_bfloat16* __restrict__ Bh, const __nv_bfloat16* __restrict__ Bl, int ldb,
              int M, int Ktot,
              float* __restrict__ Cbase,
              const float* __restrict__ bias,
              const __nv_bfloat16* __restrict__ Ah2, const __nv_bfloat16* __restrict__ Al2)
{
    extern __shared__ char dsm_raw[];
    const int tid  = threadIdx.x;
    const int wid  = tid >> 5;
    const int lane = tid & 31;
    const int wm   = wid >> 2;
    const int wn   = wid & 3;
    const int row0 = blockIdx.x * BMM;
    const int seg  = blockIdx.y;
    float* Cout = (EP == 5) ? (Cbase + (size_t)seg * SFULL) : Cbase;

    const __nv_bfloat16* AhU = (EP == 5 && seg) ? Ah2 : Ah;
    const __nv_bfloat16* AlU = (EP == 5 && seg) ? Al2 : Al;
    const __nv_bfloat16* BhU = (EP == 5) ? (Bh + seg * NCOL) : Bh;
    const __nv_bfloat16* BlU = (EP == 5) ? (Bl + seg * NCOL) : Bl;

    const uint32_t base = (smem_u32(dsm_raw) + 1023u) & ~1023u;

    float acc[4][7][4];
#pragma unroll
    for (int mt = 0; mt < 4; mt++)
#pragma unroll
        for (int nt = 0; nt < 7; nt++)
#pragma unroll
            for (int q = 0; q < 4; q++) acc[mt][nt][q] = 0.0f;

    const int nck = (Ktot + 31) >> 5;

    int issued = 0;
    for (; issued < nck && issued < NST - 1; issued++) {
        load_stage(base + issued * STAGE, AhU, AlU, lda, BhU, BlU, ldb,
                   row0, M, issued * 32, Ktot, tid);
        cp_commit();
    }

    for (int i = 0; i < nck; i++) {
        if (nck - i >= 2) asm volatile("cp.async.wait_group 1;" ::: "memory");
        else              asm volatile("cp.async.wait_group 0;" ::: "memory");
        __syncthreads();
        if (issued < nck) {
            load_stage(base + (uint32_t)(issued % NST) * STAGE, AhU, AlU, lda, BhU, BlU, ldb,
                       row0, M, issued * 32, Ktot, tid);
            cp_commit();
            issued++;
        }

        const uint32_t sb  = base + (uint32_t)(i % NST) * STAGE;
        const uint32_t aHu = sb + SA_H, aLu = sb + SA_L;
        const uint32_t bHu = sb + SB_H, bLu = sb + SB_L;

#pragma unroll
        for (int ksub = 0; ksub < 2; ksub++) {
            uint32_t ah[4][4], al[4][4];
#pragma unroll
            for (int mt = 0; mt < 4; mt++) {
                int r  = wm * 64 + mt * 16 + (lane & 15);
                int ch = 2 * ksub + (lane >> 4);
                uint32_t off = swz((uint32_t)(r * 64 + ch * 16));
                ldsm4(ah[mt], aHu + off);
                ldsm4(al[mt], aLu + off);
            }
#pragma unroll
            for (int nt = 0; nt < 7; nt++) {
                int rb = wn * 56 + nt * 8 + (lane & 7);
                int cb = 2 * ksub + ((lane >> 3) & 1);
                uint32_t off = swz((uint32_t)(rb * 64 + cb * 16));
                uint32_t bh[2], bl[2];
                ldsm2(bh, bHu + off);
                ldsm2(bl, bLu + off);
#pragma unroll
                for (int mt = 0; mt < 4; mt++) {
                    mma_bf(acc[mt][nt], ah[mt], bh);
                    mma_bf(acc[mt][nt], ah[mt], bl);
                    mma_bf(acc[mt][nt], al[mt], bh);
                }
            }
        }
    }

#pragma unroll
    for (int mt = 0; mt < 4; mt++) {
#pragma unroll
        for (int hf = 0; hf < 2; hf++) {
            const int r = row0 + wm * 64 + mt * 16 + (lane >> 2) + 8 * hf;
            if (r >= M) continue;
#pragma unroll
            for (int nt = 0; nt < 7; nt++) {
                const int c = wn * 56 + nt * 8 + (lane & 3) * 2;
                if (c >= NCOL) continue;
                float vx = acc[mt][nt][2 * hf];
                float vy = acc[mt][nt][2 * hf + 1];
                if (EP == 1) {
                    vx = fmaxf(vx + bias[c], 0.0f);
                    vy = fmaxf(vy + bias[c + 1], 0.0f);
                }
                float2 o; o.x = vx; o.y = vy;
                *(float2*)&Cout[(size_t)r * NCOL + c] = o;
            }
        }
    }
}

// =====================================================================
// elementwise / conversion kernels
// =====================================================================
__global__ void convert_adj(const float4* __restrict__ src, __half* __restrict__ dst) {
    int i = blockIdx.x * blockDim.x + threadIdx.x;
    if (i < NROW * NROW / 8) {
        float4 v0 = src[2 * i];
        float4 v1 = src[2 * i + 1];
        __half2 a = __floats2half2_rn(v0.x * ADJ_SCALE, v0.y * ADJ_SCALE);
        __half2 b = __floats2half2_rn(v0.z * ADJ_SCALE, v0.w * ADJ_SCALE);
        __half2 c = __floats2half2_rn(v1.x * ADJ_SCALE, v1.y * ADJ_SCALE);
        __half2 d = __floats2half2_rn(v1.z * ADJ_SCALE, v1.w * ADJ_SCALE);
        uint4 o;
        o.x = *(uint32_t*)&a; o.y = *(uint32_t*)&b;
        o.z = *(uint32_t*)&c; o.w = *(uint32_t*)&d;
        ((uint4*)dst)[i] = o;
    }
}

__global__ void convert_split4(const float* __restrict__ src, int n4,
                               __nv_bfloat16* __restrict__ dh,
                               __nv_bfloat16* __restrict__ dl)
{
    int i = blockIdx.x * blockDim.x + threadIdx.x;
    if (i < n4) {
        float4 v = ((const float4*)src)[i];
        __nv_bfloat16 h0, l0, h1, l1, h2, l2, h3, l3;
        split_bf(v.x, h0, l0); split_bf(v.y, h1, l1);
        split_bf(v.z, h2, l2); split_bf(v.w, h3, l3);
        __nv_bfloat162* H = (__nv_bfloat162*)dh;
        __nv_bfloat162* L = (__nv_bfloat162*)dl;
        H[2 * i]     = __nv_bfloat162(h0, h1);
        H[2 * i + 1] = __nv_bfloat162(h2, h3);
        L[2 * i]     = __nv_bfloat162(l0, l1);
        L[2 * i + 1] = __nv_bfloat162(l2, l3);
    }
}

__global__ void padhalf(const float* __restrict__ src, int R, int C, int Cp,
                        __half* __restrict__ dst)
{
    int i = blockIdx.x * blockDim.x + threadIdx.x;
    if (i < R * Cp) {
        int r = i / Cp, c = i % Cp;
        float v = (c < C) ? src[(size_t)r * C + c] : 0.0f;
        dst[i] = __float2half(v);
    }
}

__global__ void thalf(const float* __restrict__ src, int R, int C, int Rp,
                      __half* __restrict__ dst)
{
    __shared__ float t[32][33];
    int r = blockIdx.x * 32 + threadIdx.y;
    int c = blockIdx.y * 32 + threadIdx.x;
    if (r < R && c < C) t[threadIdx.y][threadIdx.x] = src[(size_t)r * C + c];
    __syncthreads();
    int rr = blockIdx.x * 32 + threadIdx.x;
    int cc = blockIdx.y * 32 + threadIdx.y;
    if (rr < Rp && cc < C) {
        float v = (rr < R) ? t[threadIdx.x][threadIdx.y] : 0.0f;
        dst[(size_t)cc * Rp + rr] = __float2half(v);
    }
}

__global__ void tsplit_w(const float* __restrict__ W0, const float* __restrict__ convW) {
    __shared__ float t[32][33];
    int z = blockIdx.z;
    const float* src;
    __nv_bfloat16 *dh, *dl;
    int R;
    if (z == 0) { src = W0; dh = g_W0Th; dl = g_W0Tl; R = NCOL; }
    else {
        src = convW + (size_t)(z - 1) * 2 * NCOL * NCOL;
        dh = g_WTh8 + (size_t)(z - 1) * WSTRIDE;
        dl = g_WTl8 + (size_t)(z - 1) * WSTRIDE;
        R = 2 * NCOL;
    }
    int r = blockIdx.x * 32 + threadIdx.y;
    int c = blockIdx.y * 32 + threadIdx.x;
    if (r < R && c < NCOL) t[threadIdx.y][threadIdx.x] = src[(size_t)r * NCOL + c];
    __syncthreads();
    int rr = blockIdx.x * 32 + threadIdx.x;
    int cc = blockIdx.y * 32 + threadIdx.y;
    if (rr < R && cc < NCOL) {
        __nv_bfloat16 h, l;
        split_bf(t[threadIdx.x][threadIdx.y], h, l);
        dh[(size_t)cc * R + rr] = h;
        dl[(size_t)cc * R + rr] = l;
    }
}

__global__ void t_f16(const float* __restrict__ src) {
    __shared__ float t[32][33];
    int r = blockIdx.x * 32 + threadIdx.y;
    int c = blockIdx.y * 32 + threadIdx.x;
    if (r < NROW && c < NCOL) t[threadIdx.y][threadIdx.x] = src[(size_t)r * NCOL + c];
    __syncthreads();
    int rr = blockIdx.x * 32 + threadIdx.x;
    int cc = blockIdx.y * 32 + threadIdx.y;
    if (rr < NROW && cc < NCOL)
        g_hT16[(size_t)cc * NROW + rr] = __float2half(t[threadIdx.x][threadIdx.y]);
}

__global__ void reduce_hi() {
    int i = blockIdx.x * blockDim.x + threadIdx.x;
    if (i < SFULL / 4) {
        const float4* p = (const float4*)g_part;
        float4 a = p[i], b = p[i + SFULL / 4], c = p[i + SFULL / 2];
        float4 s;
        s.x = (a.x + b.x + c.x) * ADJ_ISCALE;
        s.y = (a.y + b.y + c.y) * ADJ_ISCALE;
        s.z = (a.z + b.z + c.z) * ADJ_ISCALE;
        s.w = (a.w + b.w + c.w) * ADJ_ISCALE;
        ((float4*)g_hi)[i] = s;
        __nv_bfloat16 h0, l0, h1, l1, h2, l2, h3, l3;
        split_bf(s.x, h0, l0); split_bf(s.y, h1, l1);
        split_bf(s.z, h2, l2); split_bf(s.w, h3, l3);
        __nv_bfloat162 H0(h0, h1), H1(h2, h3), L0(l0, l1), L1(l2, l3);
        uint2 oh, ol;
        oh.x = *(uint32_t*)&H0; oh.y = *(uint32_t*)&H1;
        ol.x = *(uint32_t*)&L0; ol.y = *(uint32_t*)&L1;
        ((uint2*)g_hih)[i] = oh;
        ((uint2*)g_hil)[i] = ol;
    }
}

__global__ void reduce_gcnii(float theta) {
    __shared__ float t[32][33];
    const int r0 = blockIdx.x * 32;
    const int c0 = blockIdx.y * 32;
    const int S = SFULL;
#pragma unroll
    for (int q = 0; q < 4; q++) {
        int r = r0 + threadIdx.y * 4 + q;
        int c = c0 + threadIdx.x;
        float val = 0.0f;
        if (r < NROW && c < NCOL) {
            int i = r * NCOL + c;
            float sw = g_part[i] + g_part[i + S];
            float rr = 0.9f * g_hi[i] + 0.1f * g_h0[i];
            val = fmaxf(theta * sw + (1.0f - theta) * rr, 0.0f);
            g_h[i] = val;
        }
        t[threadIdx.y * 4 + q][threadIdx.x] = val;
    }
    __syncthreads();
#pragma unroll
    for (int q = 0; q < 4; q++) {
        int rr2 = r0 + threadIdx.x;
        int cc  = c0 + threadIdx.y * 4 + q;
        if (rr2 < NROW && cc < NCOL)
            g_hT16[(size_t)cc * NROW + rr2] = __float2half(t[threadIdx.x][threadIdx.y * 4 + q]);
    }
}

__global__ void assemble_kernel(float4* __restrict__ out) {
    int i4 = blockIdx.x * blockDim.x + threadIdx.x;
    if (i4 < NUTT * 300) {
        int row = i4 / 300;
        int c4  = i4 % 300;
        int m   = c4 / 100;
        int j   = c4 % 100;
        const float4* src = (j < 50) ? (const float4*)g_x : (const float4*)g_h;
        out[i4] = src[(size_t)(m * NUTT + row) * 50 + (j % 50)];
    }
}

// =====================================================================
extern "C" void kernel_launch(void* const* d_in, const int* in_sizes, int n_in,
                              void* d_out, int out_size)
{
    const float* a     = (const float*)d_in[0];
    const float* v     = (const float*)d_in[1];
    const float* l     = (const float*)d_in[2];
    const float* qmask = (const float*)d_in[3];
    const float* adj   = (const float*)d_in[4];
    const float* Wa    = (const float*)d_in[5];
    const float* ba    = (const float*)d_in[6];
    const float* Wv    = (const float*)d_in[7];
    const float* bv    = (const float*)d_in[8];
    const float* Wl    = (const float*)d_in[9];
    const float* bl    = (const float*)d_in[10];
    const float* spk   = (const float*)d_in[11];
    const float* W0    = (const float*)d_in[12];
    const float* b0    = (const float*)d_in[13];
    const float* convW = (const float*)d_in[14];
    float* out = (float*)d_out;

    float *gx, *gh0, *gpart;
    __half *adj16, *hT16, *a16, *v16, *l16, *WaT16, *WvT16, *WlT16;
    __nv_bfloat16 *hih, *hil, *h0h, *h0l, *WTh8, *WTl8, *W0Th, *W0Tl, *xh, *xl;
    cudaGetSymbolAddress((void**)&gx,    g_x);
    cudaGetSymbolAddress((void**)&gh0,   g_h0);
    cudaGetSymbolAddress((void**)&gpart, g_part);
    cudaGetSymbolAddress((void**)&adj16, g_adj16);
    cudaGetSymbolAddress((void**)&hT16,  g_hT16);
    cudaGetSymbolAddress((void**)&hih,   g_hih);
    cudaGetSymbolAddress((void**)&hil,   g_hil);
    cudaGetSymbolAddress((void**)&h0h,   g_h0h);
    cudaGetSymbolAddress((void**)&h0l,   g_h0l);
    cudaGetSymbolAddress((void**)&WTh8,  g_WTh8);
    cudaGetSymbolAddress((void**)&WTl8,  g_WTl8);
    cudaGetSymbolAddress((void**)&W0Th,  g_W0Th);
    cudaGetSymbolAddress((void**)&W0Tl,  g_W0Tl);
    cudaGetSymbolAddress((void**)&xh,    g_xh);
    cudaGetSymbolAddress((void**)&xl,    g_xl);
    cudaGetSymbolAddress((void**)&a16,   g_a16);
    cudaGetSymbolAddress((void**)&v16,   g_v16);
    cudaGetSymbolAddress((void**)&l16,   g_l16);
    cudaGetSymbolAddress((void**)&WaT16, g_WaT16);
    cudaGetSymbolAddress((void**)&WvT16, g_WvT16);
    cudaGetSymbolAddress((void**)&WlT16, g_WlT16);

    cudaFuncSetAttribute(mma_f16,      cudaFuncAttributeMaxDynamicSharedMemorySize, F_DSMEM);
    cudaFuncSetAttribute(mma_f16_proj, cudaFuncAttributeMaxDynamicSharedMemorySize, F_DSMEM);
    cudaFuncSetAttribute(mma_gemm<1>,  cudaFuncAttributeMaxDynamicSharedMemorySize, DSMEM);
    cudaFuncSetAttribute(mma_gemm<5>,  cudaFuncAttributeMaxDynamicSharedMemorySize, DSMEM);

    // ---- one-time conversions ----
    convert_adj<<<(NROW * NROW / 8 + 255) / 256, 256>>>((const float4*)adj, adj16);
    padhalf<<<(2000 * 304 + 255) / 256, 256>>>(a, 2000, 300,  304,  a16);
    padhalf<<<(2000 * 352 + 255) / 256, 256>>>(v, 2000, 342,  352,  v16);
    padhalf<<<(2000 * 1024 + 255) / 256, 256>>>(l, 2000, 1024, 1024, l16);
    thalf<<<dim3(10, 7), dim3(32, 32)>>>(Wa, 300,  NCOL, 304,  WaT16);
    thalf<<<dim3(11, 7), dim3(32, 32)>>>(Wv, 342,  NCOL, 352,  WvT16);
    thalf<<<dim3(32, 7), dim3(32, 32)>>>(Wl, 1024, NCOL, 1024, WlT16);
    tsplit_w<<<dim3(13, 7, 9), dim3(32, 32)>>>(W0, convW);

    // ---- all 3 modality projections in ONE launch (fp16 single-pass) ----
    const int gProj = (NUTT + BMM - 1) / BMM;    // 16
    const int gFull = (NROW + BMM - 1) / BMM;    // 47
    mma_f16_proj<<<dim3(gProj, 3), 256, F_DSMEM>>>(
        a16, v16, l16, WaT16, WvT16, WlT16, 304, 352, 1024,
        ba, bv, bl, qmask, spk, gx);

    // ---- h0 = relu(x @ W0 + b0)  (split-bf16) ----
    convert_split4<<<(SFULL / 4 + 255) / 256, 256>>>(gx, SFULL / 4, xh, xl);
    mma_gemm<1><<<dim3(gFull, 1), 256, DSMEM>>>(xh, xl, NCOL, W0Th, W0Tl, NCOL,
        NROW, NCOL, gh0, b0, nullptr, nullptr);
    convert_split4<<<(SFULL / 4 + 255) / 256, 256>>>(gh0, SFULL / 4, h0h, h0l);
    t_f16<<<dim3(188, 7), dim3(32, 32)>>>(gh0);

    // ---- GCNII layers ----
    for (int lay = 0; lay < NLAY; lay++) {
        float theta = logf(0.5f / (float)(lay + 1) + 1.0f);

        mma_f16<<<dim3(gFull, 3), 256, F_DSMEM>>>(adj16, NROW, hT16, NROW,
            NROW, NROW, 2000, gpart);
        reduce_hi<<<(SFULL / 4 + 255) / 256, 256>>>();

        const __nv_bfloat16* Wh  = WTh8 + (size_t)lay * WSTRIDE;
        const __nv_bfloat16* Wl2 = WTl8 + (size_t)lay * WSTRIDE;
        mma_gemm<5><<<dim3(gFull, 2), 256, DSMEM>>>(hih, hil, NCOL, Wh, Wl2, 2 * NCOL,
            NROW, NCOL, gpart, nullptr, h0h, h0l);

        reduce_gcnii<<<dim3(188, 7), dim3(32, 8)>>>(theta);
    }

    assemble_kernel<<<(NUTT * 300 + 255) / 256, 256>>>((float4*)out);
}

// round 15
// speedup vs baseline: 1.3327x; 1.0849x over previous
#include <cuda_runtime.h>
#include <cuda_bf16.h>
#include <cuda_fp16.h>
#include <math.h>
#include <stdint.h>

#define NUTT   2000
#define NROW   6000
#define NCOL   200
#define NLAY   8
#define SFULL  (NROW * NCOL)
#define WSTRIDE (NCOL * 2 * NCOL)

#define ADJ_SCALE   16384.0f
#define ADJ_ISCALE  (1.0f / 16384.0f)

#define BMM   128
#define NST   3
#define SA_H  0u
#define SA_L  8192u
#define SB_H  16384u
#define SB_L  30720u
#define STAGE 45056u
#define DSMEM (3*45056 + 1024)

#define F_NST   4
#define F_SA    0u
#define F_SB    8192u
#define F_STAGE 22528u
#define F_DSMEM (4*22528 + 1024)

__device__ __align__(256) float g_x   [SFULL];
__device__ __align__(256) float g_h0  [SFULL];
__device__ __align__(256) float g_h   [SFULL];
__device__ __align__(256) float g_hi  [SFULL];
__device__ __align__(256) float g_part[2 * SFULL + SFULL];   // 3 partials (adj split-3)

__device__ __align__(256) __half        g_adj16[NROW * NROW];
__device__ __align__(256) __half        g_hT16 [NCOL * NROW];
__device__ __align__(256) __half        g_hi16 [SFULL];
__device__ __align__(256) __half        g_h016 [SFULL];
__device__ __align__(256) __half        g_WT16_8[NLAY * WSTRIDE];
__device__ __align__(256) __nv_bfloat16 g_W0Th [NCOL * NCOL];
__device__ __align__(256) __nv_bfloat16 g_W0Tl [NCOL * NCOL];
__device__ __align__(256) __nv_bfloat16 g_xh   [SFULL];
__device__ __align__(256) __nv_bfloat16 g_xl   [SFULL];

__device__ __align__(256) __half g_a16  [2000 * 304];
__device__ __align__(256) __half g_v16  [2000 * 352];
__device__ __align__(256) __half g_l16  [2000 * 1024];
__device__ __align__(256) __half g_WaT16[NCOL * 304];
__device__ __align__(256) __half g_WvT16[NCOL * 352];
__device__ __align__(256) __half g_WlT16[NCOL * 1024];

__device__ __forceinline__ uint32_t smem_u32(const void* p) {
    uint32_t a;
    asm("{ .reg .u64 t; cvta.to.shared.u64 t, %1; cvt.u32.u64 %0, t; }" : "=r"(a) : "l"(p));
    return a;
}
__device__ __forceinline__ uint32_t swz(uint32_t off) {
    return off ^ ((off >> 3) & 0x30u);
}
__device__ __forceinline__ void ldsm4(uint32_t* r, uint32_t a) {
    asm volatile("ldmatrix.sync.aligned.m8n8.x4.shared.b16 {%0,%1,%2,%3}, [%4];"
                 : "=r"(r[0]), "=r"(r[1]), "=r"(r[2]), "=r"(r[3]) : "r"(a));
}
__device__ __forceinline__ void ldsm2(uint32_t* r, uint32_t a) {
    asm volatile("ldmatrix.sync.aligned.m8n8.x2.shared.b16 {%0,%1}, [%2];"
                 : "=r"(r[0]), "=r"(r[1]) : "r"(a));
}
__device__ __forceinline__ void mma_bf(float* d, const uint32_t* a, const uint32_t* b) {
    asm volatile("mma.sync.aligned.m16n8k16.row.col.f32.bf16.bf16.f32 "
                 "{%0,%1,%2,%3}, {%4,%5,%6,%7}, {%8,%9}, {%0,%1,%2,%3};"
                 : "+f"(d[0]), "+f"(d[1]), "+f"(d[2]), "+f"(d[3])
                 : "r"(a[0]), "r"(a[1]), "r"(a[2]), "r"(a[3]), "r"(b[0]), "r"(b[1]));
}
__device__ __forceinline__ void mma_hf(float* d, const uint32_t* a, const uint32_t* b) {
    asm volatile("mma.sync.aligned.m16n8k16.row.col.f32.f16.f16.f32 "
                 "{%0,%1,%2,%3}, {%4,%5,%6,%7}, {%8,%9}, {%0,%1,%2,%3};"
                 : "+f"(d[0]), "+f"(d[1]), "+f"(d[2]), "+f"(d[3])
                 : "r"(a[0]), "r"(a[1]), "r"(a[2]), "r"(a[3]), "r"(b[0]), "r"(b[1]));
}
__device__ __forceinline__ void cp16(uint32_t dst, const void* src, int sz) {
    asm volatile("cp.async.cg.shared.global [%0], [%1], 16, %2;"
                 :: "r"(dst), "l"(src), "r"(sz) : "memory");
}
__device__ __forceinline__ void cp_commit() {
    asm volatile("cp.async.commit_group;" ::: "memory");
}
__device__ __forceinline__ void split_bf(float v, __nv_bfloat16& h, __nv_bfloat16& l) {
    h = __float2bfloat16(v);
    l = __float2bfloat16(v - __bfloat162float(h));
}

// ---------------- fp16 stage loader + mainloop ----------------
__device__ __forceinline__ void load_stage_f16(
    uint32_t sb, const __half* __restrict__ A, int lda,
    const __half* __restrict__ B, int ldb,
    int row0, int M, int kb, int ke, int tid)
{
    for (int g = tid; g < 1408; g += 256) {
        const __half* srow;
        uint32_t toff;
        int r, c;
        bool rv;
        if (g < 512) {
            r = g >> 2; c = g & 3;
            srow = A; toff = F_SA;
            rv = (row0 + r) < M;
            if (rv) srow += (size_t)(row0 + r) * lda;
        } else {
            int idx = g - 512;
            r = idx >> 2; c = idx & 3;
            srow = B; toff = F_SB;
            rv = r < NCOL;
            if (rv) srow += (size_t)r * ldb;
        }
        int k0 = kb + c * 8;
        int sz = 0;
        const void* sp = srow;
        if (rv) {
            int kv = (ke - k0) * 2;
            sz = kv >= 16 ? 16 : (kv > 0 ? kv : 0);
            if (sz > 0) sp = srow + k0;
        }
        cp16(sb + toff + swz((uint32_t)(r * 64 + c * 16)), sp, sz);
    }
}

__device__ __forceinline__ void f16_mainloop(
    float acc[4][7][4], uint32_t base,
    const __half* __restrict__ A, int lda,
    const __half* __restrict__ B, int ldb,
    int row0, int M, int ks, int ke, int tid, int wm, int wn, int lane)
{
    const int nck = (ke - ks + 31) >> 5;
    int issued = 0;
    for (; issued < nck && issued < F_NST - 1; issued++) {
        load_stage_f16(base + issued * F_STAGE, A, lda, B, ldb,
                       row0, M, ks + issued * 32, ke, tid);
        cp_commit();
    }
    for (int i = 0; i < nck; i++) {
        int allow = nck - i - 1;
        if (allow > F_NST - 2) allow = F_NST - 2;
        if (allow >= 2)      asm volatile("cp.async.wait_group 2;" ::: "memory");
        else if (allow == 1) asm volatile("cp.async.wait_group 1;" ::: "memory");
        else                 asm volatile("cp.async.wait_group 0;" ::: "memory");
        __syncthreads();
        if (issued < nck) {
            load_stage_f16(base + (uint32_t)(issued % F_NST) * F_STAGE, A, lda, B, ldb,
                           row0, M, ks + issued * 32, ke, tid);
            cp_commit();
            issued++;
        }
        const uint32_t aB = base + (uint32_t)(i % F_NST) * F_STAGE + F_SA;
        const uint32_t bB = base + (uint32_t)(i % F_NST) * F_STAGE + F_SB;
#pragma unroll
        for (int ksub = 0; ksub < 2; ksub++) {
            uint32_t ah[4][4];
#pragma unroll
            for (int mt = 0; mt < 4; mt++) {
                int r  = wm * 64 + mt * 16 + (lane & 15);
                int ch = 2 * ksub + (lane >> 4);
                ldsm4(ah[mt], aB + swz((uint32_t)(r * 64 + ch * 16)));
            }
#pragma unroll
            for (int nt = 0; nt < 7; nt++) {
                int rb = wn * 56 + nt * 8 + (lane & 7);
                int cb = 2 * ksub + ((lane >> 3) & 1);
                uint32_t bb[2];
                ldsm2(bb, bB + swz((uint32_t)(rb * 64 + cb * 16)));
#pragma unroll
                for (int mt = 0; mt < 4; mt++) mma_hf(acc[mt][nt], ah[mt], bb);
            }
        }
    }
}

// ---------------- adj path ----------------
__global__ __launch_bounds__(256)
void mma_f16(const __half* __restrict__ A, int lda,
             const __half* __restrict__ B, int ldb,
             int M, int Ktot, int ksize, float* __restrict__ Cbase)
{
    extern __shared__ char dsm_raw[];
    const int tid  = threadIdx.x;
    const int wid  = tid >> 5;
    const int lane = tid & 31;
    const int wm   = wid >> 2;
    const int wn   = wid & 3;
    const int row0 = blockIdx.x * BMM;
    const int ks   = blockIdx.y * ksize;
    const int ke   = (ks + ksize < Ktot) ? (ks + ksize) : Ktot;
    float* Cout = Cbase + (size_t)blockIdx.y * SFULL;

    const uint32_t base = (smem_u32(dsm_raw) + 1023u) & ~1023u;

    float acc[4][7][4];
#pragma unroll
    for (int mt = 0; mt < 4; mt++)
#pragma unroll
        for (int nt = 0; nt < 7; nt++)
#pragma unroll
            for (int q = 0; q < 4; q++) acc[mt][nt][q] = 0.0f;

    f16_mainloop(acc, base, A, lda, B, ldb, row0, M, ks, ke, tid, wm, wn, lane);

#pragma unroll
    for (int mt = 0; mt < 4; mt++)
#pragma unroll
        for (int hf = 0; hf < 2; hf++) {
            const int r = row0 + wm * 64 + mt * 16 + (lane >> 2) + 8 * hf;
            if (r >= M) continue;
#pragma unroll
            for (int nt = 0; nt < 7; nt++) {
                const int c = wn * 56 + nt * 8 + (lane & 3) * 2;
                if (c >= NCOL) continue;
                float2 o;
                o.x = acc[mt][nt][2 * hf];
                o.y = acc[mt][nt][2 * hf + 1];
                *(float2*)&Cout[(size_t)r * NCOL + c] = o;
            }
        }
}

// ---------------- dual-segment S@W (fp16):  seg0 hi@W1, seg1 h0@W2 ----------------
__global__ __launch_bounds__(256)
void mma_f16_dual(const __half* __restrict__ A0, const __half* __restrict__ A1,
                  const __half* __restrict__ B, int ldb, float* __restrict__ Cbase)
{
    extern __shared__ char dsm_raw[];
    const int tid  = threadIdx.x;
    const int wid  = tid >> 5;
    const int lane = tid & 31;
    const int wm   = wid >> 2;
    const int wn   = wid & 3;
    const int row0 = blockIdx.x * BMM;
    const int seg  = blockIdx.y;

    const __half* A  = seg ? A1 : A0;
    const __half* Bu = B + seg * NCOL;     // K offset within [200][400] rows
    float* Cout = Cbase + (size_t)seg * SFULL;

    const uint32_t base = (smem_u32(dsm_raw) + 1023u) & ~1023u;

    float acc[4][7][4];
#pragma unroll
    for (int mt = 0; mt < 4; mt++)
#pragma unroll
        for (int nt = 0; nt < 7; nt++)
#pragma unroll
            for (int q = 0; q < 4; q++) acc[mt][nt][q] = 0.0f;

    f16_mainloop(acc, base, A, NCOL, Bu, ldb, row0, NROW, 0, NCOL, tid, wm, wn, lane);

#pragma unroll
    for (int mt = 0; mt < 4; mt++)
#pragma unroll
        for (int hf = 0; hf < 2; hf++) {
            const int r = row0 + wm * 64 + mt * 16 + (lane >> 2) + 8 * hf;
            if (r >= NROW) continue;
#pragma unroll
            for (int nt = 0; nt < 7; nt++) {
                const int c = wn * 56 + nt * 8 + (lane & 3) * 2;
                if (c >= NCOL) continue;
                float2 o;
                o.x = acc[mt][nt][2 * hf];
                o.y = acc[mt][nt][2 * hf + 1];
                *(float2*)&Cout[(size_t)r * NCOL + c] = o;
            }
        }
}

// ---------------- all 3 modality projections in one launch ----------------
__global__ __launch_bounds__(256)
void mma_f16_proj(const __half* __restrict__ A0, const __half* __restrict__ A1,
                  const __half* __restrict__ A2,
                  const __half* __restrict__ B0, const __half* __restrict__ B1,
                  const __half* __restrict__ B2,
                  int K0, int K1, int K2,
                  const float* __restrict__ ba, const float* __restrict__ bv,
                  const float* __restrict__ bl,
                  const float* __restrict__ qmask, const float* __restrict__ spkE,
                  float* __restrict__ Cbase)
{
    extern __shared__ char dsm_raw[];
    const int tid  = threadIdx.x;
    const int wid  = tid >> 5;
    const int lane = tid & 31;
    const int wm   = wid >> 2;
    const int wn   = wid & 3;
    const int row0 = blockIdx.x * BMM;
    const int m    = blockIdx.y;

    const __half* A = (m == 0) ? A0 : (m == 1) ? A1 : A2;
    const __half* B = (m == 0) ? B0 : (m == 1) ? B1 : B2;
    const int     K = (m == 0) ? K0 : (m == 1) ? K1 : K2;
    const float* bias = (m == 0) ? ba : (m == 1) ? bv : bl;
    float* Cout = Cbase + (size_t)m * NUTT * NCOL;

    const uint32_t base = (smem_u32(dsm_raw) + 1023u) & ~1023u;

    float acc[4][7][4];
#pragma unroll
    for (int mt = 0; mt < 4; mt++)
#pragma unroll
        for (int nt = 0; nt < 7; nt++)
#pragma unroll
            for (int q = 0; q < 4; q++) acc[mt][nt][q] = 0.0f;

    f16_mainloop(acc, base, A, K, B, K, row0, NUTT, 0, K, tid, wm, wn, lane);

#pragma unroll
    for (int mt = 0; mt < 4; mt++)
#pragma unroll
        for (int hf = 0; hf < 2; hf++) {
            const int r = row0 + wm * 64 + mt * 16 + (lane >> 2) + 8 * hf;
            if (r >= NUTT) continue;
            int spk = 0;
            if (m == 2) {
                int bI = r / 100, tI = r % 100;
                const float* q = qmask + ((size_t)tI * 20 + bI) * 2;
                spk = (q[1] > q[0]) ? 1 : 0;
            }
#pragma unroll
            for (int nt = 0; nt < 7; nt++) {
                const int c = wn * 56 + nt * 8 + (lane & 3) * 2;
                if (c >= NCOL) continue;
                float vx = acc[mt][nt][2 * hf] + bias[c];
                float vy = acc[mt][nt][2 * hf + 1] + bias[c + 1];
                if (m == 2) {
                    vx += spkE[spk * NCOL + c];
                    vy += spkE[spk * NCOL + c + 1];
                }
                float2 o; o.x = vx; o.y = vy;
                *(float2*)&Cout[(size_t)r * NCOL + c] = o;
            }
        }
}

// =====================================================================
// split-bf16 3-pass GEMM (h0 only). EP: 1 relu+bias
// =====================================================================
__device__ __forceinline__ void load_stage(
    uint32_t sb, const __nv_bfloat16* __restrict__ Ah, const __nv_bfloat16* __restrict__ Al,
    int lda, const __nv_bfloat16* __restrict__ Bh, const __nv_bfloat16* __restrict__ Bl,
    int ldb, int row0, int M, int kb, int ke, int tid)
{
    for (int g = tid; g < 2816; g += 256) {
        const __nv_bfloat16* srow;
        uint32_t toff;
        int r, c;
        bool rv;
        if (g < 1024) {
            int t = g >> 9, idx = g & 511;
            r = idx >> 2; c = idx & 3;
            srow = (t ? Al : Ah);
            toff = t ? SA_L : SA_H;
            rv = (row0 + r) < M;
            if (rv) srow += (size_t)(row0 + r) * lda;
        } else {
            int gb = g - 1024;
            int t = gb >= 896;
            int idx = t ? gb - 896 : gb;
            r = idx >> 2; c = idx & 3;
            srow = (t ? Bl : Bh);
            toff = t ? SB_L : SB_H;
            rv = r < NCOL;
            if (rv) srow += (size_t)r * ldb;
        }
        int k0 = kb + c * 8;
        int sz = 0;
        const void* sp = srow;
        if (rv) {
            int kv = (ke - k0) * 2;
            sz = kv >= 16 ? 16 : (kv > 0 ? kv : 0);
            if (sz > 0) sp = srow + k0;
        }
        cp16(sb + toff + swz((uint32_t)(r * 64 + c * 16)), sp, sz);
    }
}

__global__ __launch_bounds__(256)
void mma_gemm_relu(const __nv_bfloat16* __restrict__ Ah, const __nv_bfloat16* __restrict__ Al, int lda,
                   const __nv_bfloat16* __restrict__ Bh, const __nv_bfloat16* __restrict__ Bl, int ldb,
                   int M, int Ktot, float* __restrict__ Cout,
                   const float* __restrict__ bias)
{
    extern __shared__ char dsm_raw[];
    const int tid  = threadIdx.x;
    const int wid  = tid >> 5;
    const int lane = tid & 31;
    const int wm   = wid >> 2;
    const int wn   = wid & 3;
    const int row0 = blockIdx.x * BMM;

    const uint32_t base = (smem_u32(dsm_raw) + 1023u) & ~1023u;

    float acc[4][7][4];
#pragma unroll
    for (int mt = 0; mt < 4; mt++)
#pragma unroll
        for (int nt = 0; nt < 7; nt++)
#pragma unroll
            for (int q = 0; q < 4; q++) acc[mt][nt][q] = 0.0f;

    const int nck = (Ktot + 31) >> 5;

    int issued = 0;
    for (; issued < nck && issued < NST - 1; issued++) {
        load_stage(base + issued * STAGE, Ah, Al, lda, Bh, Bl, ldb,
                   row0, M, issued * 32, Ktot, tid);
        cp_commit();
    }

    for (int i = 0; i < nck; i++) {
        if (nck - i >= 2) asm volatile("cp.async.wait_group 1;" ::: "memory");
        else              asm volatile("cp.async.wait_group 0;" ::: "memory");
        __syncthreads();
        if (issued < nck) {
            load_stage(base + (uint32_t)(issued % NST) * STAGE, Ah, Al, lda, Bh, Bl, ldb,
                       row0, M, issued * 32, Ktot, tid);
            cp_commit();
            issued++;
        }

        const uint32_t sb  = base + (uint32_t)(i % NST) * STAGE;
        const uint32_t aHu = sb + SA_H, aLu = sb + SA_L;
        const uint32_t bHu = sb + SB_H, bLu = sb + SB_L;

#pragma unroll
        for (int ksub = 0; ksub < 2; ksub++) {
            uint32_t ah[4][4], al[4][4];
#pragma unroll
            for (int mt = 0; mt < 4; mt++) {
                int r  = wm * 64 + mt * 16 + (lane & 15);
                int ch = 2 * ksub + (lane >> 4);
                uint32_t off = swz((uint32_t)(r * 64 + ch * 16));
                ldsm4(ah[mt], aHu + off);
                ldsm4(al[mt], aLu + off);
            }
#pragma unroll
            for (int nt = 0; nt < 7; nt++) {
                int rb = wn * 56 + nt * 8 + (lane & 7);
                int cb = 2 * ksub + ((lane >> 3) & 1);
                uint32_t off = swz((uint32_t)(rb * 64 + cb * 16));
                uint32_t bh[2], bl[2];
                ldsm2(bh, bHu + off);
                ldsm2(bl, bLu + off);
#pragma unroll
                for (int mt = 0; mt < 4; mt++) {
                    mma_bf(acc[mt][nt], ah[mt], bh);
                    mma_bf(acc[mt][nt], ah[mt], bl);
                    mma_bf(acc[mt][nt], al[mt], bh);
                }
            }
        }
    }

#pragma unroll
    for (int mt = 0; mt < 4; mt++) {
#pragma unroll
        for (int hf = 0; hf < 2; hf++) {
            const int r = row0 + wm * 64 + mt * 16 + (lane >> 2) + 8 * hf;
            if (r >= M) continue;
#pragma unroll
            for (int nt = 0; nt < 7; nt++) {
                const int c = wn * 56 + nt * 8 + (lane & 3) * 2;
                if (c >= NCOL) continue;
                float vx = fmaxf(acc[mt][nt][2 * hf] + bias[c], 0.0f);
                float vy = fmaxf(acc[mt][nt][2 * hf + 1] + bias[c + 1], 0.0f);
                float2 o; o.x = vx; o.y = vy;
                *(float2*)&Cout[(size_t)r * NCOL + c] = o;
            }
        }
    }
}

// =====================================================================
// elementwise / conversion kernels
// =====================================================================
__global__ void convert_adj(const float4* __restrict__ src, __half* __restrict__ dst) {
    int i = blockIdx.x * blockDim.x + threadIdx.x;
    if (i < NROW * NROW / 8) {
        float4 v0 = src[2 * i];
        float4 v1 = src[2 * i + 1];
        __half2 a = __floats2half2_rn(v0.x * ADJ_SCALE, v0.y * ADJ_SCALE);
        __half2 b = __floats2half2_rn(v0.z * ADJ_SCALE, v0.w * ADJ_SCALE);
        __half2 c = __floats2half2_rn(v1.x * ADJ_SCALE, v1.y * ADJ_SCALE);
        __half2 d = __floats2half2_rn(v1.z * ADJ_SCALE, v1.w * ADJ_SCALE);
        uint4 o;
        o.x = *(uint32_t*)&a; o.y = *(uint32_t*)&b;
        o.z = *(uint32_t*)&c; o.w = *(uint32_t*)&d;
        ((uint4*)dst)[i] = o;
    }
}

__global__ void convert_split4(const float* __restrict__ src, int n4,
                               __nv_bfloat16* __restrict__ dh,
                               __nv_bfloat16* __restrict__ dl)
{
    int i = blockIdx.x * blockDim.x + threadIdx.x;
    if (i < n4) {
        float4 v = ((const float4*)src)[i];
        __nv_bfloat16 h0, l0, h1, l1, h2, l2, h3, l3;
        split_bf(v.x, h0, l0); split_bf(v.y, h1, l1);
        split_bf(v.z, h2, l2); split_bf(v.w, h3, l3);
        __nv_bfloat162* H = (__nv_bfloat162*)dh;
        __nv_bfloat162* L = (__nv_bfloat162*)dl;
        H[2 * i]     = __nv_bfloat162(h0, h1);
        H[2 * i + 1] = __nv_bfloat162(h2, h3);
        L[2 * i]     = __nv_bfloat162(l0, l1);
        L[2 * i + 1] = __nv_bfloat162(l2, l3);
    }
}

__global__ void padhalf(const float* __restrict__ src, int R, int C, int Cp,
                        __half* __restrict__ dst)
{
    int i = blockIdx.x * blockDim.x + threadIdx.x;
    if (i < R * Cp) {
        int r = i / Cp, c = i % Cp;
        float v = (c < C) ? src[(size_t)r * C + c] : 0.0f;
        dst[i] = __float2half(v);
    }
}

__global__ void thalf(const float* __restrict__ src, int R, int C, int Rp,
                      __half* __restrict__ dst)
{
    __shared__ float t[32][33];
    int r = blockIdx.x * 32 + threadIdx.y;
    int c = blockIdx.y * 32 + threadIdx.x;
    if (r < R && c < C) t[threadIdx.y][threadIdx.x] = src[(size_t)r * C + c];
    __syncthreads();
    int rr = blockIdx.x * 32 + threadIdx.x;
    int cc = blockIdx.y * 32 + threadIdx.y;
    if (rr < Rp && cc < C) {
        float v = (rr < R) ? t[threadIdx.x][threadIdx.y] : 0.0f;
        dst[(size_t)cc * Rp + rr] = __float2half(v);
    }
}

// W transposes: z=0 -> W0 bf16-split, z=1..8 -> convW layer fp16
__global__ void tsplit_w(const float* __restrict__ W0, const float* __restrict__ convW) {
    __shared__ float t[32][33];
    int z = blockIdx.z;
    const float* src;
    int R;
    if (z == 0) { src = W0; R = NCOL; }
    else        { src = convW + (size_t)(z - 1) * 2 * NCOL * NCOL; R = 2 * NCOL; }
    int r = blockIdx.x * 32 + threadIdx.y;
    int c = blockIdx.y * 32 + threadIdx.x;
    if (r < R && c < NCOL) t[threadIdx.y][threadIdx.x] = src[(size_t)r * NCOL + c];
    __syncthreads();
    int rr = blockIdx.x * 32 + threadIdx.x;
    int cc = blockIdx.y * 32 + threadIdx.y;
    if (rr < R && cc < NCOL) {
        float v = t[threadIdx.x][threadIdx.y];
        if (z == 0) {
            __nv_bfloat16 h, l;
            split_bf(v, h, l);
            g_W0Th[(size_t)cc * R + rr] = h;
            g_W0Tl[(size_t)cc * R + rr] = l;
        } else {
            g_WT16_8[(size_t)(z - 1) * WSTRIDE + (size_t)cc * R + rr] = __float2half(v);
        }
    }
}

// transpose h0 -> g_hT16, and row-major h0 -> g_h016 (once)
__global__ void t_f16(const float* __restrict__ src) {
    __shared__ float t[32][33];
    int r = blockIdx.x * 32 + threadIdx.y;
    int c = blockIdx.y * 32 + threadIdx.x;
    if (r < NROW && c < NCOL) {
        float v = src[(size_t)r * NCOL + c];
        t[threadIdx.y][threadIdx.x] = v;
        g_h016[(size_t)r * NCOL + c] = __float2half(v);
    }
    __syncthreads();
    int rr = blockIdx.x * 32 + threadIdx.x;
    int cc = blockIdx.y * 32 + threadIdx.y;
    if (rr < NROW && cc < NCOL)
        g_hT16[(size_t)cc * NROW + rr] = __float2half(t[threadIdx.x][threadIdx.y]);
}

// hi = (sum of 3 adj partials)*2^-14 ; write f32 + fp16
__global__ void reduce_hi() {
    int i = blockIdx.x * blockDim.x + threadIdx.x;
    if (i < SFULL / 4) {
        const float4* p = (const float4*)g_part;
        float4 a = p[i], b = p[i + SFULL / 4], c = p[i + SFULL / 2];
        float4 s;
        s.x = (a.x + b.x + c.x) * ADJ_ISCALE;
        s.y = (a.y + b.y + c.y) * ADJ_ISCALE;
        s.z = (a.z + b.z + c.z) * ADJ_ISCALE;
        s.w = (a.w + b.w + c.w) * ADJ_ISCALE;
        ((float4*)g_hi)[i] = s;
        __half2 h0 = __floats2half2_rn(s.x, s.y);
        __half2 h1 = __floats2half2_rn(s.z, s.w);
        uint2 o;
        o.x = *(uint32_t*)&h0; o.y = *(uint32_t*)&h1;
        ((uint2*)g_hi16)[i] = o;
    }
}

// combine 2 S@W partials + GCNII + relu -> g_h ; also write h^T fp16
__global__ void reduce_gcnii(float theta) {
    __shared__ float t[32][33];
    const int r0 = blockIdx.x * 32;
    const int c0 = blockIdx.y * 32;
    const int S = SFULL;
#pragma unroll
    for (int q = 0; q < 4; q++) {
        int r = r0 + threadIdx.y * 4 + q;
        int c = c0 + threadIdx.x;
        float val = 0.0f;
        if (r < NROW && c < NCOL) {
            int i = r * NCOL + c;
            float sw = g_part[i] + g_part[i + S];
            float rr = 0.9f * g_hi[i] + 0.1f * g_h0[i];
            val = fmaxf(theta * sw + (1.0f - theta) * rr, 0.0f);
            g_h[i] = val;
        }
        t[threadIdx.y * 4 + q][threadIdx.x] = val;
    }
    __syncthreads();
#pragma unroll
    for (int q = 0; q < 4; q++) {
        int rr2 = r0 + threadIdx.x;
        int cc  = c0 + threadIdx.y * 4 + q;
        if (rr2 < NROW && cc < NCOL)
            g_hT16[(size_t)cc * NROW + rr2] = __float2half(t[threadIdx.x][threadIdx.y * 4 + q]);
    }
}

__global__ void assemble_kernel(float4* __restrict__ out) {
    int i4 = blockIdx.x * blockDim.x + threadIdx.x;
    if (i4 < NUTT * 300) {
        int row = i4 / 300;
        int c4  = i4 % 300;
        int m   = c4 / 100;
        int j   = c4 % 100;
        const float4* src = (j < 50) ? (const float4*)g_x : (const float4*)g_h;
        out[i4] = src[(size_t)(m * NUTT + row) * 50 + (j % 50)];
    }
}

// =====================================================================
extern "C" void kernel_launch(void* const* d_in, const int* in_sizes, int n_in,
                              void* d_out, int out_size)
{
    const float* a     = (const float*)d_in[0];
    const float* v     = (const float*)d_in[1];
    const float* l     = (const float*)d_in[2];
    const float* qmask = (const float*)d_in[3];
    const float* adj   = (const float*)d_in[4];
    const float* Wa    = (const float*)d_in[5];
    const float* ba    = (const float*)d_in[6];
    const float* Wv    = (const float*)d_in[7];
    const float* bv    = (const float*)d_in[8];
    const float* Wl    = (const float*)d_in[9];
    const float* bl    = (const float*)d_in[10];
    const float* spk   = (const float*)d_in[11];
    const float* W0    = (const float*)d_in[12];
    const float* b0    = (const float*)d_in[13];
    const float* convW = (const float*)d_in[14];
    float* out = (float*)d_out;

    float *gx, *gh0, *gpart;
    __half *adj16, *hT16, *hi16, *h016, *WT16_8;
    __half *a16, *v16, *l16, *WaT16, *WvT16, *WlT16;
    __nv_bfloat16 *W0Th, *W0Tl, *xh, *xl;
    cudaGetSymbolAddress((void**)&gx,     g_x);
    cudaGetSymbolAddress((void**)&gh0,    g_h0);
    cudaGetSymbolAddress((void**)&gpart,  g_part);
    cudaGetSymbolAddress((void**)&adj16,  g_adj16);
    cudaGetSymbolAddress((void**)&hT16,   g_hT16);
    cudaGetSymbolAddress((void**)&hi16,   g_hi16);
    cudaGetSymbolAddress((void**)&h016,   g_h016);
    cudaGetSymbolAddress((void**)&WT16_8, g_WT16_8);
    cudaGetSymbolAddress((void**)&W0Th,   g_W0Th);
    cudaGetSymbolAddress((void**)&W0Tl,   g_W0Tl);
    cudaGetSymbolAddress((void**)&xh,     g_xh);
    cudaGetSymbolAddress((void**)&xl,     g_xl);
    cudaGetSymbolAddress((void**)&a16,    g_a16);
    cudaGetSymbolAddress((void**)&v16,    g_v16);
    cudaGetSymbolAddress((void**)&l16,    g_l16);
    cudaGetSymbolAddress((void**)&WaT16,  g_WaT16);
    cudaGetSymbolAddress((void**)&WvT16,  g_WvT16);
    cudaGetSymbolAddress((void**)&WlT16,  g_WlT16);

    cudaFuncSetAttribute(mma_f16,       cudaFuncAttributeMaxDynamicSharedMemorySize, F_DSMEM);
    cudaFuncSetAttribute(mma_f16_dual,  cudaFuncAttributeMaxDynamicSharedMemorySize, F_DSMEM);
    cudaFuncSetAttribute(mma_f16_proj,  cudaFuncAttributeMaxDynamicSharedMemorySize, F_DSMEM);
    cudaFuncSetAttribute(mma_gemm_relu, cudaFuncAttributeMaxDynamicSharedMemorySize, DSMEM);

    // ---- one-time conversions ----
    convert_adj<<<(NROW * NROW / 8 + 255) / 256, 256>>>((const float4*)adj, adj16);
    padhalf<<<(2000 * 304 + 255) / 256, 256>>>(a, 2000, 300,  304,  a16);
    padhalf<<<(2000 * 352 + 255) / 256, 256>>>(v, 2000, 342,  352,  v16);
    padhalf<<<(2000 * 1024 + 255) / 256, 256>>>(l, 2000, 1024, 1024, l16);
    thalf<<<dim3(10, 7), dim3(32, 32)>>>(Wa, 300,  NCOL, 304,  WaT16);
    thalf<<<dim3(11, 7), dim3(32, 32)>>>(Wv, 342,  NCOL, 352,  WvT16);
    thalf<<<dim3(32, 7), dim3(32, 32)>>>(Wl, 1024, NCOL, 1024, WlT16);
    tsplit_w<<<dim3(13, 7, 9), dim3(32, 32)>>>(W0, convW);

    // ---- all 3 modality projections in ONE launch (fp16) ----
    const int gProj = (NUTT + BMM - 1) / BMM;    // 16
    const int gFull = (NROW + BMM - 1) / BMM;    // 47
    mma_f16_proj<<<dim3(gProj, 3), 256, F_DSMEM>>>(
        a16, v16, l16, WaT16, WvT16, WlT16, 304, 352, 1024,
        ba, bv, bl, qmask, spk, gx);

    // ---- h0 = relu(x @ W0 + b0)  (split-bf16, precision anchor) ----
    convert_split4<<<(SFULL / 4 + 255) / 256, 256>>>(gx, SFULL / 4, xh, xl);
    mma_gemm_relu<<<dim3(gFull, 1), 256, DSMEM>>>(xh, xl, NCOL, W0Th, W0Tl, NCOL,
        NROW, NCOL, gh0, b0);
    t_f16<<<dim3(188, 7), dim3(32, 32)>>>(gh0);   // writes hT16 + h016

    // ---- GCNII layers ----
    for (int lay = 0; lay < NLAY; lay++) {
        float theta = logf(0.5f / (float)(lay + 1) + 1.0f);

        // hi partials = (adj*2^14) @ h   (fp16, K split 3)
        mma_f16<<<dim3(gFull, 3), 256, F_DSMEM>>>(adj16, NROW, hT16, NROW,
            NROW, NROW, 2000, gpart);
        reduce_hi<<<(SFULL / 4 + 255) / 256, 256>>>();

        // S@W = hi @ W1 + h0 @ W2  (fp16 dual-segment, 2 partials)
        mma_f16_dual<<<dim3(gFull, 2), 256, F_DSMEM>>>(
            hi16, h016, WT16_8 + (size_t)lay * WSTRIDE, 2 * NCOL, gpart);

        // combine + relu -> g_h ; write h^T fp16 for next layer
        reduce_gcnii<<<dim3(188, 7), dim3(32, 8)>>>(theta);
    }

    assemble_kernel<<<(NUTT * 300 + 255) / 256, 256>>>((float4*)out);
}

// round 16
// speedup vs baseline: 1.3430x; 1.0077x over previous
#include <cuda_runtime.h>
#include <cuda_bf16.h>
#include <cuda_fp16.h>
#include <math.h>
#include <stdint.h>

#define NUTT   2000
#define NROW   6000
#define NCOL   200
#define NLAY   8
#define SFULL  (NROW * NCOL)
#define WSTRIDE (NCOL * 2 * NCOL)

#define ADJ_SCALE   16384.0f
#define ADJ_ISCALE  (1.0f / 16384.0f)

#define BMM   128
#define NST   3
#define SA_H  0u
#define SA_L  8192u
#define SB_H  16384u
#define SB_L  30720u
#define STAGE 45056u
#define DSMEM (3*45056 + 1024)

#define F_NST   4
#define F_SA    0u
#define F_SB    8192u
#define F_STAGE 22528u
#define F_DSMEM (4*22528 + 1024)

__device__ __align__(256) float g_x   [SFULL];
__device__ __align__(256) float g_h0  [SFULL];
__device__ __align__(256) float g_h   [SFULL];
__device__ __align__(256) float g_part[3 * SFULL];

__device__ __align__(256) __half        g_adj16[NROW * NROW];
__device__ __align__(256) __half        g_hT16 [NCOL * NROW];
__device__ __align__(256) __half        g_hi16 [SFULL];
__device__ __align__(256) __half        g_h016 [SFULL];
__device__ __align__(256) __half        g_WT16_8[NLAY * WSTRIDE];
__device__ __align__(256) __nv_bfloat16 g_W0Th [NCOL * NCOL];
__device__ __align__(256) __nv_bfloat16 g_W0Tl [NCOL * NCOL];
__device__ __align__(256) __nv_bfloat16 g_xh   [SFULL];
__device__ __align__(256) __nv_bfloat16 g_xl   [SFULL];

__device__ __align__(256) __half g_a16  [2000 * 304];
__device__ __align__(256) __half g_v16  [2000 * 352];
__device__ __align__(256) __half g_l16  [2000 * 1024];
__device__ __align__(256) __half g_WaT16[NCOL * 304];
__device__ __align__(256) __half g_WvT16[NCOL * 352];
__device__ __align__(256) __half g_WlT16[NCOL * 1024];

__device__ __forceinline__ uint32_t smem_u32(const void* p) {
    uint32_t a;
    asm("{ .reg .u64 t; cvta.to.shared.u64 t, %1; cvt.u32.u64 %0, t; }" : "=r"(a) : "l"(p));
    return a;
}
__device__ __forceinline__ uint32_t swz(uint32_t off) {
    return off ^ ((off >> 3) & 0x30u);
}
__device__ __forceinline__ void ldsm4(uint32_t* r, uint32_t a) {
    asm volatile("ldmatrix.sync.aligned.m8n8.x4.shared.b16 {%0,%1,%2,%3}, [%4];"
                 : "=r"(r[0]), "=r"(r[1]), "=r"(r[2]), "=r"(r[3]) : "r"(a));
}
__device__ __forceinline__ void ldsm2(uint32_t* r, uint32_t a) {
    asm volatile("ldmatrix.sync.aligned.m8n8.x2.shared.b16 {%0,%1}, [%2];"
                 : "=r"(r[0]), "=r"(r[1]) : "r"(a));
}
__device__ __forceinline__ void mma_bf(float* d, const uint32_t* a, const uint32_t* b) {
    asm volatile("mma.sync.aligned.m16n8k16.row.col.f32.bf16.bf16.f32 "
                 "{%0,%1,%2,%3}, {%4,%5,%6,%7}, {%8,%9}, {%0,%1,%2,%3};"
                 : "+f"(d[0]), "+f"(d[1]), "+f"(d[2]), "+f"(d[3])
                 : "r"(a[0]), "r"(a[1]), "r"(a[2]), "r"(a[3]), "r"(b[0]), "r"(b[1]));
}
__device__ __forceinline__ void mma_hf(float* d, const uint32_t* a, const uint32_t* b) {
    asm volatile("mma.sync.aligned.m16n8k16.row.col.f32.f16.f16.f32 "
                 "{%0,%1,%2,%3}, {%4,%5,%6,%7}, {%8,%9}, {%0,%1,%2,%3};"
                 : "+f"(d[0]), "+f"(d[1]), "+f"(d[2]), "+f"(d[3])
                 : "r"(a[0]), "r"(a[1]), "r"(a[2]), "r"(a[3]), "r"(b[0]), "r"(b[1]));
}
__device__ __forceinline__ void cp16(uint32_t dst, const void* src, int sz) {
    asm volatile("cp.async.cg.shared.global [%0], [%1], 16, %2;"
                 :: "r"(dst), "l"(src), "r"(sz) : "memory");
}
__device__ __forceinline__ void cp_commit() {
    asm volatile("cp.async.commit_group;" ::: "memory");
}
__device__ __forceinline__ void split_bf(float v, __nv_bfloat16& h, __nv_bfloat16& l) {
    h = __float2bfloat16(v);
    l = __float2bfloat16(v - __bfloat162float(h));
}

// ---------------- fp16 stage loader + mainloop ----------------
__device__ __forceinline__ void load_stage_f16(
    uint32_t sb, const __half* __restrict__ A, int lda,
    const __half* __restrict__ B, int ldb,
    int row0, int M, int kb, int ke, int tid)
{
    for (int g = tid; g < 1408; g += 256) {
        const __half* srow;
        uint32_t toff;
        int r, c;
        bool rv;
        if (g < 512) {
            r = g >> 2; c = g & 3;
            srow = A; toff = F_SA;
            rv = (row0 + r) < M;
            if (rv) srow += (size_t)(row0 + r) * lda;
        } else {
            int idx = g - 512;
            r = idx >> 2; c = idx & 3;
            srow = B; toff = F_SB;
            rv = r < NCOL;
            if (rv) srow += (size_t)r * ldb;
        }
        int k0 = kb + c * 8;
        int sz = 0;
        const void* sp = srow;
        if (rv) {
            int kv = (ke - k0) * 2;
            sz = kv >= 16 ? 16 : (kv > 0 ? kv : 0);
            if (sz > 0) sp = srow + k0;
        }
        cp16(sb + toff + swz((uint32_t)(r * 64 + c * 16)), sp, sz);
    }
}

__device__ __forceinline__ void f16_mainloop(
    float acc[4][7][4], uint32_t base,
    const __half* __restrict__ A, int lda,
    const __half* __restrict__ B, int ldb,
    int row0, int M, int ks, int ke, int tid, int wm, int wn, int lane)
{
    const int nck = (ke - ks + 31) >> 5;
    int issued = 0;
    for (; issued < nck && issued < F_NST - 1; issued++) {
        load_stage_f16(base + issued * F_STAGE, A, lda, B, ldb,
                       row0, M, ks + issued * 32, ke, tid);
        cp_commit();
    }
    for (int i = 0; i < nck; i++) {
        int allow = nck - i - 1;
        if (allow > F_NST - 2) allow = F_NST - 2;
        if (allow >= 2)      asm volatile("cp.async.wait_group 2;" ::: "memory");
        else if (allow == 1) asm volatile("cp.async.wait_group 1;" ::: "memory");
        else                 asm volatile("cp.async.wait_group 0;" ::: "memory");
        __syncthreads();
        if (issued < nck) {
            load_stage_f16(base + (uint32_t)(issued % F_NST) * F_STAGE, A, lda, B, ldb,
                           row0, M, ks + issued * 32, ke, tid);
            cp_commit();
            issued++;
        }
        const uint32_t aB = base + (uint32_t)(i % F_NST) * F_STAGE + F_SA;
        const uint32_t bB = base + (uint32_t)(i % F_NST) * F_STAGE + F_SB;
#pragma unroll
        for (int ksub = 0; ksub < 2; ksub++) {
            uint32_t ah[4][4];
#pragma unroll
            for (int mt = 0; mt < 4; mt++) {
                int r  = wm * 64 + mt * 16 + (lane & 15);
                int ch = 2 * ksub + (lane >> 4);
                ldsm4(ah[mt], aB + swz((uint32_t)(r * 64 + ch * 16)));
            }
#pragma unroll
            for (int nt = 0; nt < 7; nt++) {
                int rb = wn * 56 + nt * 8 + (lane & 7);
                int cb = 2 * ksub + ((lane >> 3) & 1);
                uint32_t bb[2];
                ldsm2(bb, bB + swz((uint32_t)(rb * 64 + cb * 16)));
#pragma unroll
                for (int mt = 0; mt < 4; mt++) mma_hf(acc[mt][nt], ah[mt], bb);
            }
        }
    }
}

// ---------------- adj path ----------------
__global__ __launch_bounds__(256)
void mma_f16(const __half* __restrict__ A, int lda,
             const __half* __restrict__ B, int ldb,
             int M, int Ktot, int ksize, float* __restrict__ Cbase)
{
    extern __shared__ char dsm_raw[];
    const int tid  = threadIdx.x;
    const int wid  = tid >> 5;
    const int lane = tid & 31;
    const int wm   = wid >> 2;
    const int wn   = wid & 3;
    const int row0 = blockIdx.x * BMM;
    const int ks   = blockIdx.y * ksize;
    const int ke   = (ks + ksize < Ktot) ? (ks + ksize) : Ktot;
    float* Cout = Cbase + (size_t)blockIdx.y * SFULL;

    const uint32_t base = (smem_u32(dsm_raw) + 1023u) & ~1023u;

    float acc[4][7][4];
#pragma unroll
    for (int mt = 0; mt < 4; mt++)
#pragma unroll
        for (int nt = 0; nt < 7; nt++)
#pragma unroll
            for (int q = 0; q < 4; q++) acc[mt][nt][q] = 0.0f;

    f16_mainloop(acc, base, A, lda, B, ldb, row0, M, ks, ke, tid, wm, wn, lane);

#pragma unroll
    for (int mt = 0; mt < 4; mt++)
#pragma unroll
        for (int hf = 0; hf < 2; hf++) {
            const int r = row0 + wm * 64 + mt * 16 + (lane >> 2) + 8 * hf;
            if (r >= M) continue;
#pragma unroll
            for (int nt = 0; nt < 7; nt++) {
                const int c = wn * 56 + nt * 8 + (lane & 3) * 2;
                if (c >= NCOL) continue;
                float2 o;
                o.x = acc[mt][nt][2 * hf];
                o.y = acc[mt][nt][2 * hf + 1];
                *(float2*)&Cout[(size_t)r * NCOL + c] = o;
            }
        }
}

// ---------------- dual-segment S@W (fp16): seg0 hi@W1, seg1 h0@W2 ----------------
__global__ __launch_bounds__(256)
void mma_f16_dual(const __half* __restrict__ A0, const __half* __restrict__ A1,
                  const __half* __restrict__ B, int ldb, float* __restrict__ Cbase)
{
    extern __shared__ char dsm_raw[];
    const int tid  = threadIdx.x;
    const int wid  = tid >> 5;
    const int lane = tid & 31;
    const int wm   = wid >> 2;
    const int wn   = wid & 3;
    const int row0 = blockIdx.x * BMM;
    const int seg  = blockIdx.y;

    const __half* A  = seg ? A1 : A0;
    const __half* Bu = B + seg * NCOL;
    float* Cout = Cbase + (size_t)seg * SFULL;

    const uint32_t base = (smem_u32(dsm_raw) + 1023u) & ~1023u;

    float acc[4][7][4];
#pragma unroll
    for (int mt = 0; mt < 4; mt++)
#pragma unroll
        for (int nt = 0; nt < 7; nt++)
#pragma unroll
            for (int q = 0; q < 4; q++) acc[mt][nt][q] = 0.0f;

    f16_mainloop(acc, base, A, NCOL, Bu, ldb, row0, NROW, 0, NCOL, tid, wm, wn, lane);

#pragma unroll
    for (int mt = 0; mt < 4; mt++)
#pragma unroll
        for (int hf = 0; hf < 2; hf++) {
            const int r = row0 + wm * 64 + mt * 16 + (lane >> 2) + 8 * hf;
            if (r >= NROW) continue;
#pragma unroll
            for (int nt = 0; nt < 7; nt++) {
                const int c = wn * 56 + nt * 8 + (lane & 3) * 2;
                if (c >= NCOL) continue;
                float2 o;
                o.x = acc[mt][nt][2 * hf];
                o.y = acc[mt][nt][2 * hf + 1];
                *(float2*)&Cout[(size_t)r * NCOL + c] = o;
            }
        }
}

// ---------------- all 3 modality projections in one launch ----------------
__global__ __launch_bounds__(256)
void mma_f16_proj(const __half* __restrict__ A0, const __half* __restrict__ A1,
                  const __half* __restrict__ A2,
                  const __half* __restrict__ B0, const __half* __restrict__ B1,
                  const __half* __restrict__ B2,
                  int K0, int K1, int K2,
                  const float* __restrict__ ba, const float* __restrict__ bv,
                  const float* __restrict__ bl,
                  const float* __restrict__ qmask, const float* __restrict__ spkE,
                  float* __restrict__ Cbase)
{
    extern __shared__ char dsm_raw[];
    const int tid  = threadIdx.x;
    const int wid  = tid >> 5;
    const int lane = tid & 31;
    const int wm   = wid >> 2;
    const int wn   = wid & 3;
    const int row0 = blockIdx.x * BMM;
    const int m    = blockIdx.y;

    const __half* A = (m == 0) ? A0 : (m == 1) ? A1 : A2;
    const __half* B = (m == 0) ? B0 : (m == 1) ? B1 : B2;
    const int     K = (m == 0) ? K0 : (m == 1) ? K1 : K2;
    const float* bias = (m == 0) ? ba : (m == 1) ? bv : bl;
    float* Cout = Cbase + (size_t)m * NUTT * NCOL;

    const uint32_t base = (smem_u32(dsm_raw) + 1023u) & ~1023u;

    float acc[4][7][4];
#pragma unroll
    for (int mt = 0; mt < 4; mt++)
#pragma unroll
        for (int nt = 0; nt < 7; nt++)
#pragma unroll
            for (int q = 0; q < 4; q++) acc[mt][nt][q] = 0.0f;

    f16_mainloop(acc, base, A, K, B, K, row0, NUTT, 0, K, tid, wm, wn, lane);

#pragma unroll
    for (int mt = 0; mt < 4; mt++)
#pragma unroll
        for (int hf = 0; hf < 2; hf++) {
            const int r = row0 + wm * 64 + mt * 16 + (lane >> 2) + 8 * hf;
            if (r >= NUTT) continue;
            int spk = 0;
            if (m == 2) {
                int bI = r / 100, tI = r % 100;
                const float* q = qmask + ((size_t)tI * 20 + bI) * 2;
                spk = (q[1] > q[0]) ? 1 : 0;
            }
#pragma unroll
            for (int nt = 0; nt < 7; nt++) {
                const int c = wn * 56 + nt * 8 + (lane & 3) * 2;
                if (c >= NCOL) continue;
                float vx = acc[mt][nt][2 * hf] + bias[c];
                float vy = acc[mt][nt][2 * hf + 1] + bias[c + 1];
                if (m == 2) {
                    vx += spkE[spk * NCOL + c];
                    vy += spkE[spk * NCOL + c + 1];
                }
                float2 o; o.x = vx; o.y = vy;
                *(float2*)&Cout[(size_t)r * NCOL + c] = o;
            }
        }
}

// =====================================================================
// split-bf16 3-pass GEMM (h0 only)
// =====================================================================
__device__ __forceinline__ void load_stage(
    uint32_t sb, const __nv_bfloat16* __restrict__ Ah, const __nv_bfloat16* __restrict__ Al,
    int lda, const __nv_bfloat16* __restrict__ Bh, const __nv_bfloat16* __restrict__ Bl,
    int ldb, int row0, int M, int kb, int ke, int tid)
{
    for (int g = tid; g < 2816; g += 256) {
        const __nv_bfloat16* srow;
        uint32_t toff;
        int r, c;
        bool rv;
        if (g < 1024) {
            int t = g >> 9, idx = g & 511;
            r = idx >> 2; c = idx & 3;
            srow = (t ? Al : Ah);
            toff = t ? SA_L : SA_H;
            rv = (row0 + r) < M;
            if (rv) srow += (size_t)(row0 + r) * lda;
        } else {
            int gb = g - 1024;
            int t = gb >= 896;
            int idx = t ? gb - 896 : gb;
            r = idx >> 2; c = idx & 3;
            srow = (t ? Bl : Bh);
            toff = t ? SB_L : SB_H;
            rv = r < NCOL;
            if (rv) srow += (size_t)r * ldb;
        }
        int k0 = kb + c * 8;
        int sz = 0;
        const void* sp = srow;
        if (rv) {
            int kv = (ke - k0) * 2;
            sz = kv >= 16 ? 16 : (kv > 0 ? kv : 0);
            if (sz > 0) sp = srow + k0;
        }
        cp16(sb + toff + swz((uint32_t)(r * 64 + c * 16)), sp, sz);
    }
}

__global__ __launch_bounds__(256)
void mma_gemm_relu(const __nv_bfloat16* __restrict__ Ah, const __nv_bfloat16* __restrict__ Al, int lda,
                   const __nv_bfloat16* __restrict__ Bh, const __nv_bfloat16* __restrict__ Bl, int ldb,
                   int M, int Ktot, float* __restrict__ Cout,
                   const float* __restrict__ bias)
{
    extern __shared__ char dsm_raw[];
    const int tid  = threadIdx.x;
    const int wid  = tid >> 5;
    const int lane = tid & 31;
    const int wm   = wid >> 2;
    const int wn   = wid & 3;
    const int row0 = blockIdx.x * BMM;

    const uint32_t base = (smem_u32(dsm_raw) + 1023u) & ~1023u;

    float acc[4][7][4];
#pragma unroll
    for (int mt = 0; mt < 4; mt++)
#pragma unroll
        for (int nt = 0; nt < 7; nt++)
#pragma unroll
            for (int q = 0; q < 4; q++) acc[mt][nt][q] = 0.0f;

    const int nck = (Ktot + 31) >> 5;

    int issued = 0;
    for (; issued < nck && issued < NST - 1; issued++) {
        load_stage(base + issued * STAGE, Ah, Al, lda, Bh, Bl, ldb,
                   row0, M, issued * 32, Ktot, tid);
        cp_commit();
    }

    for (int i = 0; i < nck; i++) {
        if (nck - i >= 2) asm volatile("cp.async.wait_group 1;" ::: "memory");
        else              asm volatile("cp.async.wait_group 0;" ::: "memory");
        __syncthreads();
        if (issued < nck) {
            load_stage(base + (uint32_t)(issued % NST) * STAGE, Ah, Al, lda, Bh, Bl, ldb,
                       row0, M, issued * 32, Ktot, tid);
            cp_commit();
            issued++;
        }

        const uint32_t sb  = base + (uint32_t)(i % NST) * STAGE;
        const uint32_t aHu = sb + SA_H, aLu = sb + SA_L;
        const uint32_t bHu = sb + SB_H, bLu = sb + SB_L;

#pragma unroll
        for (int ksub = 0; ksub < 2; ksub++) {
            uint32_t ah[4][4], al[4][4];
#pragma unroll
            for (int mt = 0; mt < 4; mt++) {
                int r  = wm * 64 + mt * 16 + (lane & 15);
                int ch = 2 * ksub + (lane >> 4);
                uint32_t off = swz((uint32_t)(r * 64 + ch * 16));
                ldsm4(ah[mt], aHu + off);
                ldsm4(al[mt], aLu + off);
            }
#pragma unroll
            for (int nt = 0; nt < 7; nt++) {
                int rb = wn * 56 + nt * 8 + (lane & 7);
                int cb = 2 * ksub + ((lane >> 3) & 1);
                uint32_t off = swz((uint32_t)(rb * 64 + cb * 16));
                uint32_t bh[2], bl[2];
                ldsm2(bh, bHu + off);
                ldsm2(bl, bLu + off);
#pragma unroll
                for (int mt = 0; mt < 4; mt++) {
                    mma_bf(acc[mt][nt], ah[mt], bh);
                    mma_bf(acc[mt][nt], ah[mt], bl);
                    mma_bf(acc[mt][nt], al[mt], bh);
                }
            }
        }
    }

#pragma unroll
    for (int mt = 0; mt < 4; mt++) {
#pragma unroll
        for (int hf = 0; hf < 2; hf++) {
            const int r = row0 + wm * 64 + mt * 16 + (lane >> 2) + 8 * hf;
            if (r >= M) continue;
#pragma unroll
            for (int nt = 0; nt < 7; nt++) {
                const int c = wn * 56 + nt * 8 + (lane & 3) * 2;
                if (c >= NCOL) continue;
                float vx = fmaxf(acc[mt][nt][2 * hf] + bias[c], 0.0f);
                float vy = fmaxf(acc[mt][nt][2 * hf + 1] + bias[c + 1], 0.0f);
                float2 o; o.x = vx; o.y = vy;
                *(float2*)&Cout[(size_t)r * NCOL + c] = o;
            }
        }
    }
}

// =====================================================================
// elementwise / conversion kernels
// =====================================================================
// adj f32 -> fp16*2^14 : 64B in / 32B out per thread (MLP 4)
__global__ void convert_adj(const float4* __restrict__ src, __half* __restrict__ dst) {
    int i = blockIdx.x * blockDim.x + threadIdx.x;
    if (i < NROW * NROW / 16) {
        float4 v0 = src[4 * i];
        float4 v1 = src[4 * i + 1];
        float4 v2 = src[4 * i + 2];
        float4 v3 = src[4 * i + 3];
        __half2 a = __floats2half2_rn(v0.x * ADJ_SCALE, v0.y * ADJ_SCALE);
        __half2 b = __floats2half2_rn(v0.z * ADJ_SCALE, v0.w * ADJ_SCALE);
        __half2 c = __floats2half2_rn(v1.x * ADJ_SCALE, v1.y * ADJ_SCALE);
        __half2 d = __floats2half2_rn(v1.z * ADJ_SCALE, v1.w * ADJ_SCALE);
        __half2 e = __floats2half2_rn(v2.x * ADJ_SCALE, v2.y * ADJ_SCALE);
        __half2 f = __floats2half2_rn(v2.z * ADJ_SCALE, v2.w * ADJ_SCALE);
        __half2 g = __floats2half2_rn(v3.x * ADJ_SCALE, v3.y * ADJ_SCALE);
        __half2 h = __floats2half2_rn(v3.z * ADJ_SCALE, v3.w * ADJ_SCALE);
        uint4 o0, o1;
        o0.x = *(uint32_t*)&a; o0.y = *(uint32_t*)&b;
        o0.z = *(uint32_t*)&c; o0.w = *(uint32_t*)&d;
        o1.x = *(uint32_t*)&e; o1.y = *(uint32_t*)&f;
        o1.z = *(uint32_t*)&g; o1.w = *(uint32_t*)&h;
        ((uint4*)dst)[2 * i]     = o0;
        ((uint4*)dst)[2 * i + 1] = o1;
    }
}

__global__ void convert_split4(const float* __restrict__ src, int n4,
                               __nv_bfloat16* __restrict__ dh,
                               __nv_bfloat16* __restrict__ dl)
{
    int i = blockIdx.x * blockDim.x + threadIdx.x;
    if (i < n4) {
        float4 v = ((const float4*)src)[i];
        __nv_bfloat16 h0, l0, h1, l1, h2, l2, h3, l3;
        split_bf(v.x, h0, l0); split_bf(v.y, h1, l1);
        split_bf(v.z, h2, l2); split_bf(v.w, h3, l3);
        __nv_bfloat162* H = (__nv_bfloat162*)dh;
        __nv_bfloat162* L = (__nv_bfloat162*)dl;
        H[2 * i]     = __nv_bfloat162(h0, h1);
        H[2 * i + 1] = __nv_bfloat162(h2, h3);
        L[2 * i]     = __nv_bfloat162(l0, l1);
        L[2 * i + 1] = __nv_bfloat162(l2, l3);
    }
}

// generic pad+convert (with padding)
__global__ void padhalf(const float* __restrict__ src, int R, int C, int Cp,
                        __half* __restrict__ dst)
{
    int i = blockIdx.x * blockDim.x + threadIdx.x;
    if (i < R * Cp) {
        int r = i / Cp, c = i % Cp;
        float v = (c < C) ? src[(size_t)r * C + c] : 0.0f;
        dst[i] = __float2half(v);
    }
}

// fast linear convert (no padding): 8 f32 -> 8 fp16 per thread
__global__ void convhalf_lin(const float4* __restrict__ src, int n8,
                             __half* __restrict__ dst)
{
    int i = blockIdx.x * blockDim.x + threadIdx.x;
    if (i < n8) {
        float4 v0 = src[2 * i];
        float4 v1 = src[2 * i + 1];
        __half2 a = __floats2half2_rn(v0.x, v0.y);
        __half2 b = __floats2half2_rn(v0.z, v0.w);
        __half2 c = __floats2half2_rn(v1.x, v1.y);
        __half2 d = __floats2half2_rn(v1.z, v1.w);
        uint4 o;
        o.x = *(uint32_t*)&a; o.y = *(uint32_t*)&b;
        o.z = *(uint32_t*)&c; o.w = *(uint32_t*)&d;
        ((uint4*)dst)[i] = o;
    }
}

__global__ void thalf(const float* __restrict__ src, int R, int C, int Rp,
                      __half* __restrict__ dst)
{
    __shared__ float t[32][33];
    int r = blockIdx.x * 32 + threadIdx.y;
    int c = blockIdx.y * 32 + threadIdx.x;
    if (r < R && c < C) t[threadIdx.y][threadIdx.x] = src[(size_t)r * C + c];
    __syncthreads();
    int rr = blockIdx.x * 32 + threadIdx.x;
    int cc = blockIdx.y * 32 + threadIdx.y;
    if (rr < Rp && cc < C) {
        float v = (rr < R) ? t[threadIdx.x][threadIdx.y] : 0.0f;
        dst[(size_t)cc * Rp + rr] = __float2half(v);
    }
}

// W transposes: z=0 -> W0 bf16-split, z=1..8 -> convW layer fp16
__global__ void tsplit_w(const float* __restrict__ W0, const float* __restrict__ convW) {
    __shared__ float t[32][33];
    int z = blockIdx.z;
    const float* src;
    int R;
    if (z == 0) { src = W0; R = NCOL; }
    else        { src = convW + (size_t)(z - 1) * 2 * NCOL * NCOL; R = 2 * NCOL; }
    int r = blockIdx.x * 32 + threadIdx.y;
    int c = blockIdx.y * 32 + threadIdx.x;
    if (r < R && c < NCOL) t[threadIdx.y][threadIdx.x] = src[(size_t)r * NCOL + c];
    __syncthreads();
    int rr = blockIdx.x * 32 + threadIdx.x;
    int cc = blockIdx.y * 32 + threadIdx.y;
    if (rr < R && cc < NCOL) {
        float v = t[threadIdx.x][threadIdx.y];
        if (z == 0) {
            __nv_bfloat16 h, l;
            split_bf(v, h, l);
            g_W0Th[(size_t)cc * R + rr] = h;
            g_W0Tl[(size_t)cc * R + rr] = l;
        } else {
            g_WT16_8[(size_t)(z - 1) * WSTRIDE + (size_t)cc * R + rr] = __float2half(v);
        }
    }
}

// transpose h0 -> g_hT16, and row-major h0 -> g_h016 (once)
__global__ void t_f16(const float* __restrict__ src) {
    __shared__ float t[32][33];
    int r = blockIdx.x * 32 + threadIdx.y;
    int c = blockIdx.y * 32 + threadIdx.x;
    if (r < NROW && c < NCOL) {
        float v = src[(size_t)r * NCOL + c];
        t[threadIdx.y][threadIdx.x] = v;
        g_h016[(size_t)r * NCOL + c] = __float2half(v);
    }
    __syncthreads();
    int rr = blockIdx.x * 32 + threadIdx.x;
    int cc = blockIdx.y * 32 + threadIdx.y;
    if (rr < NROW && cc < NCOL)
        g_hT16[(size_t)cc * NROW + rr] = __float2half(t[threadIdx.x][threadIdx.y]);
}

// hi16 = fp16( (sum of 3 adj partials) * 2^-14 )  — f32 hi no longer kept
__global__ void reduce_hi() {
    int i = blockIdx.x * blockDim.x + threadIdx.x;
    if (i < SFULL / 4) {
        const float4* p = (const float4*)g_part;
        float4 a = p[i], b = p[i + SFULL / 4], c = p[i + SFULL / 2];
        float4 s;
        s.x = (a.x + b.x + c.x) * ADJ_ISCALE;
        s.y = (a.y + b.y + c.y) * ADJ_ISCALE;
        s.z = (a.z + b.z + c.z) * ADJ_ISCALE;
        s.w = (a.w + b.w + c.w) * ADJ_ISCALE;
        __half2 h0 = __floats2half2_rn(s.x, s.y);
        __half2 h1 = __floats2half2_rn(s.z, s.w);
        uint2 o;
        o.x = *(uint32_t*)&h0; o.y = *(uint32_t*)&h1;
        ((uint2*)g_hi16)[i] = o;
    }
}

// combine 2 S@W partials + GCNII(hi from fp16) + relu -> g_h ; write h^T fp16
__global__ void reduce_gcnii(float theta) {
    __shared__ float t[32][33];
    const int r0 = blockIdx.x * 32;
    const int c0 = blockIdx.y * 32;
    const int S = SFULL;
#pragma unroll
    for (int q = 0; q < 4; q++) {
        int r = r0 + threadIdx.y * 4 + q;
        int c = c0 + threadIdx.x;
        float val = 0.0f;
        if (r < NROW && c < NCOL) {
            int i = r * NCOL + c;
            float sw = g_part[i] + g_part[i + S];
            float hiv = __half2float(g_hi16[i]);
            float rr = 0.9f * hiv + 0.1f * g_h0[i];
            val = fmaxf(theta * sw + (1.0f - theta) * rr, 0.0f);
            g_h[i] = val;
        }
        t[threadIdx.y * 4 + q][threadIdx.x] = val;
    }
    __syncthreads();
#pragma unroll
    for (int q = 0; q < 4; q++) {
        int rr2 = r0 + threadIdx.x;
        int cc  = c0 + threadIdx.y * 4 + q;
        if (rr2 < NROW && cc < NCOL)
            g_hT16[(size_t)cc * NROW + rr2] = __float2half(t[threadIdx.x][threadIdx.y * 4 + q]);
    }
}

__global__ void assemble_kernel(float4* __restrict__ out) {
    int i4 = blockIdx.x * blockDim.x + threadIdx.x;
    if (i4 < NUTT * 300) {
        int row = i4 / 300;
        int c4  = i4 % 300;
        int m   = c4 / 100;
        int j   = c4 % 100;
        const float4* src = (j < 50) ? (const float4*)g_x : (const float4*)g_h;
        out[i4] = src[(size_t)(m * NUTT + row) * 50 + (j % 50)];
    }
}

// =====================================================================
extern "C" void kernel_launch(void* const* d_in, const int* in_sizes, int n_in,
                              void* d_out, int out_size)
{
    const float* a     = (const float*)d_in[0];
    const float* v     = (const float*)d_in[1];
    const float* l     = (const float*)d_in[2];
    const float* qmask = (const float*)d_in[3];
    const float* adj   = (const float*)d_in[4];
    const float* Wa    = (const float*)d_in[5];
    const float* ba    = (const float*)d_in[6];
    const float* Wv    = (const float*)d_in[7];
    const float* bv    = (const float*)d_in[8];
    const float* Wl    = (const float*)d_in[9];
    const float* bl    = (const float*)d_in[10];
    const float* spk   = (const float*)d_in[11];
    const float* W0    = (const float*)d_in[12];
    const float* b0    = (const float*)d_in[13];
    const float* convW = (const float*)d_in[14];
    float* out = (float*)d_out;

    float *gx, *gh0, *gpart;
    __half *adj16, *hT16, *hi16, *h016, *WT16_8;
    __half *a16, *v16, *l16, *WaT16, *WvT16, *WlT16;
    __nv_bfloat16 *W0Th, *W0Tl, *xh, *xl;
    cudaGetSymbolAddress((void**)&gx,     g_x);
    cudaGetSymbolAddress((void**)&gh0,    g_h0);
    cudaGetSymbolAddress((void**)&gpart,  g_part);
    cudaGetSymbolAddress((void**)&adj16,  g_adj16);
    cudaGetSymbolAddress((void**)&hT16,   g_hT16);
    cudaGetSymbolAddress((void**)&hi16,   g_hi16);
    cudaGetSymbolAddress((void**)&h016,   g_h016);
    cudaGetSymbolAddress((void**)&WT16_8, g_WT16_8);
    cudaGetSymbolAddress((void**)&W0Th,   g_W0Th);
    cudaGetSymbolAddress((void**)&W0Tl,   g_W0Tl);
    cudaGetSymbolAddress((void**)&xh,     g_xh);
    cudaGetSymbolAddress((void**)&xl,     g_xl);
    cudaGetSymbolAddress((void**)&a16,    g_a16);
    cudaGetSymbolAddress((void**)&v16,    g_v16);
    cudaGetSymbolAddress((void**)&l16,    g_l16);
    cudaGetSymbolAddress((void**)&WaT16,  g_WaT16);
    cudaGetSymbolAddress((void**)&WvT16,  g_WvT16);
    cudaGetSymbolAddress((void**)&WlT16,  g_WlT16);

    cudaFuncSetAttribute(mma_f16,       cudaFuncAttributeMaxDynamicSharedMemorySize, F_DSMEM);
    cudaFuncSetAttribute(mma_f16_dual,  cudaFuncAttributeMaxDynamicSharedMemorySize, F_DSMEM);
    cudaFuncSetAttribute(mma_f16_proj,  cudaFuncAttributeMaxDynamicSharedMemorySize, F_DSMEM);
    cudaFuncSetAttribute(mma_gemm_relu, cudaFuncAttributeMaxDynamicSharedMemorySize, DSMEM);

    // ---- one-time conversions ----
    convert_adj<<<(NROW * NROW / 16 + 255) / 256, 256>>>((const float4*)adj, adj16);
    padhalf<<<(2000 * 304 + 255) / 256, 256>>>(a, 2000, 300,  304,  a16);
    padhalf<<<(2000 * 352 + 255) / 256, 256>>>(v, 2000, 342,  352,  v16);
    convhalf_lin<<<(2000 * 1024 / 8 + 255) / 256, 256>>>((const float4*)l, 2000 * 1024 / 8, l16);
    thalf<<<dim3(10, 7), dim3(32, 32)>>>(Wa, 300,  NCOL, 304,  WaT16);
    thalf<<<dim3(11, 7), dim3(32, 32)>>>(Wv, 342,  NCOL, 352,  WvT16);
    thalf<<<dim3(32, 7), dim3(32, 32)>>>(Wl, 1024, NCOL, 1024, WlT16);
    tsplit_w<<<dim3(13, 7, 9), dim3(32, 32)>>>(W0, convW);

    // ---- all 3 modality projections in ONE launch (fp16) ----
    const int gProj = (NUTT + BMM - 1) / BMM;    // 16
    const int gFull = (NROW + BMM - 1) / BMM;    // 47
    mma_f16_proj<<<dim3(gProj, 3), 256, F_DSMEM>>>(
        a16, v16, l16, WaT16, WvT16, WlT16, 304, 352, 1024,
        ba, bv, bl, qmask, spk, gx);

    // ---- h0 = relu(x @ W0 + b0)  (split-bf16, precision anchor) ----
    convert_split4<<<(SFULL / 4 + 255) / 256, 256>>>(gx, SFULL / 4, xh, xl);
    mma_gemm_relu<<<dim3(gFull, 1), 256, DSMEM>>>(xh, xl, NCOL, W0Th, W0Tl, NCOL,
        NROW, NCOL, gh0, b0);
    t_f16<<<dim3(188, 7), dim3(32, 32)>>>(gh0);   // writes hT16 + h016

    // ---- GCNII layers ----
    for (int lay = 0; lay < NLAY; lay++) {
        float theta = logf(0.5f / (float)(lay + 1) + 1.0f);

        // hi partials = (adj*2^14) @ h   (fp16, K split 3)
        mma_f16<<<dim3(gFull, 3), 256, F_DSMEM>>>(adj16, NROW, hT16, NROW,
            NROW, NROW, 2000, gpart);
        reduce_hi<<<(SFULL / 4 + 255) / 256, 256>>>();

        // S@W = hi @ W1 + h0 @ W2  (fp16 dual-segment, 2 partials)
        mma_f16_dual<<<dim3(gFull, 2), 256, F_DSMEM>>>(
            hi16, h016, WT16_8 + (size_t)lay * WSTRIDE, 2 * NCOL, gpart);

        // combine + relu -> g_h ; write h^T fp16 for next layer
        reduce_gcnii<<<dim3(188, 7), dim3(32, 8)>>>(theta);
    }

    assemble_kernel<<<(NUTT * 300 + 255) / 256, 256>>>((float4*)out);
}

// round 17
// speedup vs baseline: 1.3799x; 1.0275x over previous
#include <cuda_runtime.h>
#include <cuda_fp16.h>
#include <math.h>
#include <stdint.h>

#define NUTT   2000
#define NROW   6000
#define NCOL   200
#define NLAY   8
#define SFULL  (NROW * NCOL)
#define WSTRIDE (NCOL * 2 * NCOL)

#define ADJ_SCALE   16384.0f
#define ADJ_ISCALE  (1.0f / 16384.0f)

#define BMM   128

#define F_NST   4
#define F_SA    0u
#define F_SB    8192u
#define F_STAGE 22528u
#define F_DSMEM (4*22528 + 1024)

__device__ __align__(256) float g_x   [SFULL];
__device__ __align__(256) float g_h0  [SFULL];
__device__ __align__(256) float g_h   [SFULL];
__device__ __align__(256) float g_part[3 * SFULL];

__device__ __align__(256) __half g_adj16[NROW * NROW];
__device__ __align__(256) __half g_hT16 [NCOL * NROW];
__device__ __align__(256) __half g_hi16 [SFULL];
__device__ __align__(256) __half g_h016 [SFULL];
__device__ __align__(256) __half g_x16  [SFULL];
__device__ __align__(256) __half g_WT16_8[NLAY * WSTRIDE];
__device__ __align__(256) __half g_W0T16[NCOL * NCOL];

__device__ __align__(256) __half g_a16  [2000 * 304];
__device__ __align__(256) __half g_v16  [2000 * 352];
__device__ __align__(256) __half g_l16  [2000 * 1024];
__device__ __align__(256) __half g_WaT16[NCOL * 304];
__device__ __align__(256) __half g_WvT16[NCOL * 352];
__device__ __align__(256) __half g_WlT16[NCOL * 1024];

__device__ __forceinline__ uint32_t smem_u32(const void* p) {
    uint32_t a;
    asm("{ .reg .u64 t; cvta.to.shared.u64 t, %1; cvt.u32.u64 %0, t; }" : "=r"(a) : "l"(p));
    return a;
}
__device__ __forceinline__ uint32_t swz(uint32_t off) {
    return off ^ ((off >> 3) & 0x30u);
}
__device__ __forceinline__ void ldsm4(uint32_t* r, uint32_t a) {
    asm volatile("ldmatrix.sync.aligned.m8n8.x4.shared.b16 {%0,%1,%2,%3}, [%4];"
                 : "=r"(r[0]), "=r"(r[1]), "=r"(r[2]), "=r"(r[3]) : "r"(a));
}
__device__ __forceinline__ void ldsm2(uint32_t* r, uint32_t a) {
    asm volatile("ldmatrix.sync.aligned.m8n8.x2.shared.b16 {%0,%1}, [%2];"
                 : "=r"(r[0]), "=r"(r[1]) : "r"(a));
}
__device__ __forceinline__ void mma_hf(float* d, const uint32_t* a, const uint32_t* b) {
    asm volatile("mma.sync.aligned.m16n8k16.row.col.f32.f16.f16.f32 "
                 "{%0,%1,%2,%3}, {%4,%5,%6,%7}, {%8,%9}, {%0,%1,%2,%3};"
                 : "+f"(d[0]), "+f"(d[1]), "+f"(d[2]), "+f"(d[3])
                 : "r"(a[0]), "r"(a[1]), "r"(a[2]), "r"(a[3]), "r"(b[0]), "r"(b[1]));
}
__device__ __forceinline__ void cp16(uint32_t dst, const void* src, int sz) {
    asm volatile("cp.async.cg.shared.global [%0], [%1], 16, %2;"
                 :: "r"(dst), "l"(src), "r"(sz) : "memory");
}
__device__ __forceinline__ void cp_commit() {
    asm volatile("cp.async.commit_group;" ::: "memory");
}

// ---------------- fp16 stage loader + mainloop ----------------
__device__ __forceinline__ void load_stage_f16(
    uint32_t sb, const __half* __restrict__ A, int lda,
    const __half* __restrict__ B, int ldb,
    int row0, int M, int kb, int ke, int tid)
{
    for (int g = tid; g < 1408; g += 256) {
        const __half* srow;
        uint32_t toff;
        int r, c;
        bool rv;
        if (g < 512) {
            r = g >> 2; c = g & 3;
            srow = A; toff = F_SA;
            rv = (row0 + r) < M;
            if (rv) srow += (size_t)(row0 + r) * lda;
        } else {
            int idx = g - 512;
            r = idx >> 2; c = idx & 3;
            srow = B; toff = F_SB;
            rv = r < NCOL;
            if (rv) srow += (size_t)r * ldb;
        }
        int k0 = kb + c * 8;
        int sz = 0;
        const void* sp = srow;
        if (rv) {
            int kv = (ke - k0) * 2;
            sz = kv >= 16 ? 16 : (kv > 0 ? kv : 0);
            if (sz > 0) sp = srow + k0;
        }
        cp16(sb + toff + swz((uint32_t)(r * 64 + c * 16)), sp, sz);
    }
}

__device__ __forceinline__ void f16_mainloop(
    float acc[4][7][4], uint32_t base,
    const __half* __restrict__ A, int lda,
    const __half* __restrict__ B, int ldb,
    int row0, int M, int ks, int ke, int tid, int wm, int wn, int lane)
{
    const int nck = (ke - ks + 31) >> 5;
    int issued = 0;
    for (; issued < nck && issued < F_NST - 1; issued++) {
        load_stage_f16(base + issued * F_STAGE, A, lda, B, ldb,
                       row0, M, ks + issued * 32, ke, tid);
        cp_commit();
    }
    for (int i = 0; i < nck; i++) {
        int allow = nck - i - 1;
        if (allow > F_NST - 2) allow = F_NST - 2;
        if (allow >= 2)      asm volatile("cp.async.wait_group 2;" ::: "memory");
        else if (allow == 1) asm volatile("cp.async.wait_group 1;" ::: "memory");
        else                 asm volatile("cp.async.wait_group 0;" ::: "memory");
        __syncthreads();
        if (issued < nck) {
            load_stage_f16(base + (uint32_t)(issued % F_NST) * F_STAGE, A, lda, B, ldb,
                           row0, M, ks + issued * 32, ke, tid);
            cp_commit();
            issued++;
        }
        const uint32_t aB = base + (uint32_t)(i % F_NST) * F_STAGE + F_SA;
        const uint32_t bB = base + (uint32_t)(i % F_NST) * F_STAGE + F_SB;
#pragma unroll
        for (int ksub = 0; ksub < 2; ksub++) {
            uint32_t ah[4][4];
#pragma unroll
            for (int mt = 0; mt < 4; mt++) {
                int r  = wm * 64 + mt * 16 + (lane & 15);
                int ch = 2 * ksub + (lane >> 4);
                ldsm4(ah[mt], aB + swz((uint32_t)(r * 64 + ch * 16)));
            }
#pragma unroll
            for (int nt = 0; nt < 7; nt++) {
                int rb = wn * 56 + nt * 8 + (lane & 7);
                int cb = 2 * ksub + ((lane >> 3) & 1);
                uint32_t bb[2];
                ldsm2(bb, bB + swz((uint32_t)(rb * 64 + cb * 16)));
#pragma unroll
                for (int mt = 0; mt < 4; mt++) mma_hf(acc[mt][nt], ah[mt], bb);
            }
        }
    }
}

// ---------------- adj path (partial write) ----------------
__global__ __launch_bounds__(256)
void mma_f16(const __half* __restrict__ A, int lda,
             const __half* __restrict__ B, int ldb,
             int M, int Ktot, int ksize, float* __restrict__ Cbase)
{
    extern __shared__ char dsm_raw[];
    const int tid  = threadIdx.x;
    const int wid  = tid >> 5;
    const int lane = tid & 31;
    const int wm   = wid >> 2;
    const int wn   = wid & 3;
    const int row0 = blockIdx.x * BMM;
    const int ks   = blockIdx.y * ksize;
    const int ke   = (ks + ksize < Ktot) ? (ks + ksize) : Ktot;
    float* Cout = Cbase + (size_t)blockIdx.y * SFULL;

    const uint32_t base = (smem_u32(dsm_raw) + 1023u) & ~1023u;

    float acc[4][7][4];
#pragma unroll
    for (int mt = 0; mt < 4; mt++)
#pragma unroll
        for (int nt = 0; nt < 7; nt++)
#pragma unroll
            for (int q = 0; q < 4; q++) acc[mt][nt][q] = 0.0f;

    f16_mainloop(acc, base, A, lda, B, ldb, row0, M, ks, ke, tid, wm, wn, lane);

#pragma unroll
    for (int mt = 0; mt < 4; mt++)
#pragma unroll
        for (int hf = 0; hf < 2; hf++) {
            const int r = row0 + wm * 64 + mt * 16 + (lane >> 2) + 8 * hf;
            if (r >= M) continue;
#pragma unroll
            for (int nt = 0; nt < 7; nt++) {
                const int c = wn * 56 + nt * 8 + (lane & 3) * 2;
                if (c >= NCOL) continue;
                float2 o;
                o.x = acc[mt][nt][2 * hf];
                o.y = acc[mt][nt][2 * hf + 1];
                *(float2*)&Cout[(size_t)r * NCOL + c] = o;
            }
        }
}

// ---------------- h0 = relu(x16 @ W0T16 + b0) -> g_h0 f32 ----------------
__global__ __launch_bounds__(256)
void mma_f16_h0(const __half* __restrict__ A, const __half* __restrict__ B,
                const float* __restrict__ bias, float* __restrict__ Cout)
{
    extern __shared__ char dsm_raw[];
    const int tid  = threadIdx.x;
    const int wid  = tid >> 5;
    const int lane = tid & 31;
    const int wm   = wid >> 2;
    const int wn   = wid & 3;
    const int row0 = blockIdx.x * BMM;

    const uint32_t base = (smem_u32(dsm_raw) + 1023u) & ~1023u;

    float acc[4][7][4];
#pragma unroll
    for (int mt = 0; mt < 4; mt++)
#pragma unroll
        for (int nt = 0; nt < 7; nt++)
#pragma unroll
            for (int q = 0; q < 4; q++) acc[mt][nt][q] = 0.0f;

    f16_mainloop(acc, base, A, NCOL, B, NCOL, row0, NROW, 0, NCOL, tid, wm, wn, lane);

#pragma unroll
    for (int mt = 0; mt < 4; mt++)
#pragma unroll
        for (int hf = 0; hf < 2; hf++) {
            const int r = row0 + wm * 64 + mt * 16 + (lane >> 2) + 8 * hf;
            if (r >= NROW) continue;
#pragma unroll
            for (int nt = 0; nt < 7; nt++) {
                const int c = wn * 56 + nt * 8 + (lane & 3) * 2;
                if (c >= NCOL) continue;
                float2 o;
                o.x = fmaxf(acc[mt][nt][2 * hf] + bias[c], 0.0f);
                o.y = fmaxf(acc[mt][nt][2 * hf + 1] + bias[c + 1], 0.0f);
                *(float2*)&Cout[(size_t)r * NCOL + c] = o;
            }
        }
}

// ---------------- dual-segment S@W: seg0 hi@W1, seg1 h0@W2 ----------------
__global__ __launch_bounds__(256)
void mma_f16_dual(const __half* __restrict__ A0, const __half* __restrict__ A1,
                  const __half* __restrict__ B, int ldb, float* __restrict__ Cbase)
{
    extern __shared__ char dsm_raw[];
    const int tid  = threadIdx.x;
    const int wid  = tid >> 5;
    const int lane = tid & 31;
    const int wm   = wid >> 2;
    const int wn   = wid & 3;
    const int row0 = blockIdx.x * BMM;
    const int seg  = blockIdx.y;

    const __half* A  = seg ? A1 : A0;
    const __half* Bu = B + seg * NCOL;
    float* Cout = Cbase + (size_t)seg * SFULL;

    const uint32_t base = (smem_u32(dsm_raw) + 1023u) & ~1023u;

    float acc[4][7][4];
#pragma unroll
    for (int mt = 0; mt < 4; mt++)
#pragma unroll
        for (int nt = 0; nt < 7; nt++)
#pragma unroll
            for (int q = 0; q < 4; q++) acc[mt][nt][q] = 0.0f;

    f16_mainloop(acc, base, A, NCOL, Bu, ldb, row0, NROW, 0, NCOL, tid, wm, wn, lane);

#pragma unroll
    for (int mt = 0; mt < 4; mt++)
#pragma unroll
        for (int hf = 0; hf < 2; hf++) {
            const int r = row0 + wm * 64 + mt * 16 + (lane >> 2) + 8 * hf;
            if (r >= NROW) continue;
#pragma unroll
            for (int nt = 0; nt < 7; nt++) {
                const int c = wn * 56 + nt * 8 + (lane & 3) * 2;
                if (c >= NCOL) continue;
                float2 o;
                o.x = acc[mt][nt][2 * hf];
                o.y = acc[mt][nt][2 * hf + 1];
                *(float2*)&Cout[(size_t)r * NCOL + c] = o;
            }
        }
}

// ---------------- all 3 modality projections in one launch ----------------
__global__ __launch_bounds__(256)
void mma_f16_proj(const __half* __restrict__ A0, const __half* __restrict__ A1,
                  const __half* __restrict__ A2,
                  const __half* __restrict__ B0, const __half* __restrict__ B1,
                  const __half* __restrict__ B2,
                  int K0, int K1, int K2,
                  const float* __restrict__ ba, const float* __restrict__ bv,
                  const float* __restrict__ bl,
                  const float* __restrict__ qmask, const float* __restrict__ spkE,
                  float* __restrict__ Cbase)
{
    extern __shared__ char dsm_raw[];
    const int tid  = threadIdx.x;
    const int wid  = tid >> 5;
    const int lane = tid & 31;
    const int wm   = wid >> 2;
    const int wn   = wid & 3;
    const int row0 = blockIdx.x * BMM;
    const int m    = blockIdx.y;

    const __half* A = (m == 0) ? A0 : (m == 1) ? A1 : A2;
    const __half* B = (m == 0) ? B0 : (m == 1) ? B1 : B2;
    const int     K = (m == 0) ? K0 : (m == 1) ? K1 : K2;
    const float* bias = (m == 0) ? ba : (m == 1) ? bv : bl;
    float* Cout = Cbase + (size_t)m * NUTT * NCOL;

    const uint32_t base = (smem_u32(dsm_raw) + 1023u) & ~1023u;

    float acc[4][7][4];
#pragma unroll
    for (int mt = 0; mt < 4; mt++)
#pragma unroll
        for (int nt = 0; nt < 7; nt++)
#pragma unroll
            for (int q = 0; q < 4; q++) acc[mt][nt][q] = 0.0f;

    f16_mainloop(acc, base, A, K, B, K, row0, NUTT, 0, K, tid, wm, wn, lane);

#pragma unroll
    for (int mt = 0; mt < 4; mt++)
#pragma unroll
        for (int hf = 0; hf < 2; hf++) {
            const int r = row0 + wm * 64 + mt * 16 + (lane >> 2) + 8 * hf;
            if (r >= NUTT) continue;
            int spk = 0;
            if (m == 2) {
                int bI = r / 100, tI = r % 100;
                const float* q = qmask + ((size_t)tI * 20 + bI) * 2;
                spk = (q[1] > q[0]) ? 1 : 0;
            }
#pragma unroll
            for (int nt = 0; nt < 7; nt++) {
                const int c = wn * 56 + nt * 8 + (lane & 3) * 2;
                if (c >= NCOL) continue;
                float vx = acc[mt][nt][2 * hf] + bias[c];
                float vy = acc[mt][nt][2 * hf + 1] + bias[c + 1];
                if (m == 2) {
                    vx += spkE[spk * NCOL + c];
                    vy += spkE[spk * NCOL + c + 1];
                }
                float2 o; o.x = vx; o.y = vy;
                *(float2*)&Cout[(size_t)r * NCOL + c] = o;
            }
        }
}

// =====================================================================
// elementwise / conversion kernels
// =====================================================================
__global__ void convert_adj(const float4* __restrict__ src, __half* __restrict__ dst) {
    int i = blockIdx.x * blockDim.x + threadIdx.x;
    if (i < NROW * NROW / 16) {
        float4 v0 = src[4 * i];
        float4 v1 = src[4 * i + 1];
        float4 v2 = src[4 * i + 2];
        float4 v3 = src[4 * i + 3];
        __half2 a = __floats2half2_rn(v0.x * ADJ_SCALE, v0.y * ADJ_SCALE);
        __half2 b = __floats2half2_rn(v0.z * ADJ_SCALE, v0.w * ADJ_SCALE);
        __half2 c = __floats2half2_rn(v1.x * ADJ_SCALE, v1.y * ADJ_SCALE);
        __half2 d = __floats2half2_rn(v1.z * ADJ_SCALE, v1.w * ADJ_SCALE);
        __half2 e = __floats2half2_rn(v2.x * ADJ_SCALE, v2.y * ADJ_SCALE);
        __half2 f = __floats2half2_rn(v2.z * ADJ_SCALE, v2.w * ADJ_SCALE);
        __half2 g = __floats2half2_rn(v3.x * ADJ_SCALE, v3.y * ADJ_SCALE);
        __half2 h = __floats2half2_rn(v3.z * ADJ_SCALE, v3.w * ADJ_SCALE);
        uint4 o0, o1;
        o0.x = *(uint32_t*)&a; o0.y = *(uint32_t*)&b;
        o0.z = *(uint32_t*)&c; o0.w = *(uint32_t*)&d;
        o1.x = *(uint32_t*)&e; o1.y = *(uint32_t*)&f;
        o1.z = *(uint32_t*)&g; o1.w = *(uint32_t*)&h;
        ((uint4*)dst)[2 * i]     = o0;
        ((uint4*)dst)[2 * i + 1] = o1;
    }
}

__global__ void padhalf(const float* __restrict__ src, int R, int C, int Cp,
                        __half* __restrict__ dst)
{
    int i = blockIdx.x * blockDim.x + threadIdx.x;
    if (i < R * Cp) {
        int r = i / Cp, c = i % Cp;
        float v = (c < C) ? src[(size_t)r * C + c] : 0.0f;
        dst[i] = __float2half(v);
    }
}

// fast linear convert: 8 f32 -> 8 fp16 per thread (size multiple of 8)
__global__ void convhalf_lin(const float4* __restrict__ src, int n8,
                             __half* __restrict__ dst)
{
    int i = blockIdx.x * blockDim.x + threadIdx.x;
    if (i < n8) {
        float4 v0 = src[2 * i];
        float4 v1 = src[2 * i + 1];
        __half2 a = __floats2half2_rn(v0.x, v0.y);
        __half2 b = __floats2half2_rn(v0.z, v0.w);
        __half2 c = __floats2half2_rn(v1.x, v1.y);
        __half2 d = __floats2half2_rn(v1.z, v1.w);
        uint4 o;
        o.x = *(uint32_t*)&a; o.y = *(uint32_t*)&b;
        o.z = *(uint32_t*)&c; o.w = *(uint32_t*)&d;
        ((uint4*)dst)[i] = o;
    }
}

__global__ void thalf(const float* __restrict__ src, int R, int C, int Rp,
                      __half* __restrict__ dst)
{
    __shared__ float t[32][33];
    int r = blockIdx.x * 32 + threadIdx.y;
    int c = blockIdx.y * 32 + threadIdx.x;
    if (r < R && c < C) t[threadIdx.y][threadIdx.x] = src[(size_t)r * C + c];
    __syncthreads();
    int rr = blockIdx.x * 32 + threadIdx.x;
    int cc = blockIdx.y * 32 + threadIdx.y;
    if (rr < Rp && cc < C) {
        float v = (rr < R) ? t[threadIdx.x][threadIdx.y] : 0.0f;
        dst[(size_t)cc * Rp + rr] = __float2half(v);
    }
}

// W transposes (all fp16 now): z=0 -> W0 [200,200], z=1..8 -> convW [400,200]
__global__ void tsplit_w(const float* __restrict__ W0, const float* __restrict__ convW) {
    __shared__ float t[32][33];
    int z = blockIdx.z;
    const float* src;
    __half* dst;
    int R;
    if (z == 0) { src = W0; dst = g_W0T16; R = NCOL; }
    else {
        src = convW + (size_t)(z - 1) * 2 * NCOL * NCOL;
        dst = g_WT16_8 + (size_t)(z - 1) * WSTRIDE;
        R = 2 * NCOL;
    }
    int r = blockIdx.x * 32 + threadIdx.y;
    int c = blockIdx.y * 32 + threadIdx.x;
    if (r < R && c < NCOL) t[threadIdx.y][threadIdx.x] = src[(size_t)r * NCOL + c];
    __syncthreads();
    int rr = blockIdx.x * 32 + threadIdx.x;
    int cc = blockIdx.y * 32 + threadIdx.y;
    if (rr < R && cc < NCOL)
        dst[(size_t)cc * R + rr] = __float2half(t[threadIdx.x][threadIdx.y]);
}

// transpose h0 -> g_hT16, and row-major h0 -> g_h016 (once)
__global__ void t_f16(const float* __restrict__ src) {
    __shared__ float t[32][33];
    int r = blockIdx.x * 32 + threadIdx.y;
    int c = blockIdx.y * 32 + threadIdx.x;
    if (r < NROW && c < NCOL) {
        float v = src[(size_t)r * NCOL + c];
        t[threadIdx.y][threadIdx.x] = v;
        g_h016[(size_t)r * NCOL + c] = __float2half(v);
    }
    __syncthreads();
    int rr = blockIdx.x * 32 + threadIdx.x;
    int cc = blockIdx.y * 32 + threadIdx.y;
    if (rr < NROW && cc < NCOL)
        g_hT16[(size_t)cc * NROW + rr] = __float2half(t[threadIdx.x][threadIdx.y]);
}

// hi16 = fp16( (sum of 3 adj partials) * 2^-14 )
__global__ void reduce_hi() {
    int i = blockIdx.x * blockDim.x + threadIdx.x;
    if (i < SFULL / 4) {
        const float4* p = (const float4*)g_part;
        float4 a = p[i], b = p[i + SFULL / 4], c = p[i + SFULL / 2];
        float4 s;
        s.x = (a.x + b.x + c.x) * ADJ_ISCALE;
        s.y = (a.y + b.y + c.y) * ADJ_ISCALE;
        s.z = (a.z + b.z + c.z) * ADJ_ISCALE;
        s.w = (a.w + b.w + c.w) * ADJ_ISCALE;
        __half2 h0 = __floats2half2_rn(s.x, s.y);
        __half2 h1 = __floats2half2_rn(s.z, s.w);
        uint2 o;
        o.x = *(uint32_t*)&h0; o.y = *(uint32_t*)&h1;
        ((uint2*)g_hi16)[i] = o;
    }
}

// combine 2 S@W partials + GCNII + relu -> hT16 (and g_h f32 on final layer)
__global__ void reduce_gcnii(float theta, int write_h) {
    __shared__ float t[32][33];
    const int r0 = blockIdx.x * 32;
    const int c0 = blockIdx.y * 32;
    const int S = SFULL;
#pragma unroll
    for (int q = 0; q < 4; q++) {
        int r = r0 + threadIdx.y * 4 + q;
        int c = c0 + threadIdx.x;
        float val = 0.0f;
        if (r < NROW && c < NCOL) {
            int i = r * NCOL + c;
            float sw = g_part[i] + g_part[i + S];
            float hiv = __half2float(g_hi16[i]);
            float h0v = __half2float(g_h016[i]);
            float rr = 0.9f * hiv + 0.1f * h0v;
            val = fmaxf(theta * sw + (1.0f - theta) * rr, 0.0f);
            if (write_h) g_h[i] = val;
        }
        t[threadIdx.y * 4 + q][threadIdx.x] = val;
    }
    __syncthreads();
#pragma unroll
    for (int q = 0; q < 4; q++) {
        int rr2 = r0 + threadIdx.x;
        int cc  = c0 + threadIdx.y * 4 + q;
        if (rr2 < NROW && cc < NCOL)
            g_hT16[(size_t)cc * NROW + rr2] = __float2half(t[threadIdx.x][threadIdx.y * 4 + q]);
    }
}

__global__ void assemble_kernel(float4* __restrict__ out) {
    int i4 = blockIdx.x * blockDim.x + threadIdx.x;
    if (i4 < NUTT * 300) {
        int row = i4 / 300;
        int c4  = i4 % 300;
        int m   = c4 / 100;
        int j   = c4 % 100;
        const float4* src = (j < 50) ? (const float4*)g_x : (const float4*)g_h;
        out[i4] = src[(size_t)(m * NUTT + row) * 50 + (j % 50)];
    }
}

// =====================================================================
extern "C" void kernel_launch(void* const* d_in, const int* in_sizes, int n_in,
                              void* d_out, int out_size)
{
    const float* a     = (const float*)d_in[0];
    const float* v     = (const float*)d_in[1];
    const float* l     = (const float*)d_in[2];
    const float* qmask = (const float*)d_in[3];
    const float* adj   = (const float*)d_in[4];
    const float* Wa    = (const float*)d_in[5];
    const float* ba    = (const float*)d_in[6];
    const float* Wv    = (const float*)d_in[7];
    const float* bv    = (const float*)d_in[8];
    const float* Wl    = (const float*)d_in[9];
    const float* bl    = (const float*)d_in[10];
    const float* spk   = (const float*)d_in[11];
    const float* W0    = (const float*)d_in[12];
    const float* b0    = (const float*)d_in[13];
    const float* convW = (const float*)d_in[14];
    float* out = (float*)d_out;

    float *gx, *gh0, *gpart;
    __half *adj16, *hT16, *hi16, *h016, *x16, *WT16_8, *W0T16;
    __half *a16, *v16, *l16, *WaT16, *WvT16, *WlT16;
    cudaGetSymbolAddress((void**)&gx,     g_x);
    cudaGetSymbolAddress((void**)&gh0,    g_h0);
    cudaGetSymbolAddress((void**)&gpart,  g_part);
    cudaGetSymbolAddress((void**)&adj16,  g_adj16);
    cudaGetSymbolAddress((void**)&hT16,   g_hT16);
    cudaGetSymbolAddress((void**)&hi16,   g_hi16);
    cudaGetSymbolAddress((void**)&h016,   g_h016);
    cudaGetSymbolAddress((void**)&x16,    g_x16);
    cudaGetSymbolAddress((void**)&WT16_8, g_WT16_8);
    cudaGetSymbolAddress((void**)&W0T16,  g_W0T16);
    cudaGetSymbolAddress((void**)&a16,    g_a16);
    cudaGetSymbolAddress((void**)&v16,    g_v16);
    cudaGetSymbolAddress((void**)&l16,    g_l16);
    cudaGetSymbolAddress((void**)&WaT16,  g_WaT16);
    cudaGetSymbolAddress((void**)&WvT16,  g_WvT16);
    cudaGetSymbolAddress((void**)&WlT16,  g_WlT16);

    cudaFuncSetAttribute(mma_f16,      cudaFuncAttributeMaxDynamicSharedMemorySize, F_DSMEM);
    cudaFuncSetAttribute(mma_f16_h0,   cudaFuncAttributeMaxDynamicSharedMemorySize, F_DSMEM);
    cudaFuncSetAttribute(mma_f16_dual, cudaFuncAttributeMaxDynamicSharedMemorySize, F_DSMEM);
    cudaFuncSetAttribute(mma_f16_proj, cudaFuncAttributeMaxDynamicSharedMemorySize, F_DSMEM);

    // ---- one-time conversions ----
    convert_adj<<<(NROW * NROW / 16 + 255) / 256, 256>>>((const float4*)adj, adj16);
    padhalf<<<(2000 * 304 + 255) / 256, 256>>>(a, 2000, 300,  304,  a16);
    padhalf<<<(2000 * 352 + 255) / 256, 256>>>(v, 2000, 342,  352,  v16);
    convhalf_lin<<<(2000 * 1024 / 8 + 255) / 256, 256>>>((const float4*)l, 2000 * 1024 / 8, l16);
    thalf<<<dim3(10, 7), dim3(32, 32)>>>(Wa, 300,  NCOL, 304,  WaT16);
    thalf<<<dim3(11, 7), dim3(32, 32)>>>(Wv, 342,  NCOL, 352,  WvT16);
    thalf<<<dim3(32, 7), dim3(32, 32)>>>(Wl, 1024, NCOL, 1024, WlT16);
    tsplit_w<<<dim3(13, 7, 9), dim3(32, 32)>>>(W0, convW);

    // ---- all 3 modality projections in ONE launch (fp16) ----
    const int gProj = (NUTT + BMM - 1) / BMM;    // 16
    const int gFull = (NROW + BMM - 1) / BMM;    // 47
    mma_f16_proj<<<dim3(gProj, 3), 256, F_DSMEM>>>(
        a16, v16, l16, WaT16, WvT16, WlT16, 304, 352, 1024,
        ba, bv, bl, qmask, spk, gx);

    // ---- h0 = relu(x @ W0 + b0)  (fp16 single-pass) ----
    convhalf_lin<<<(SFULL / 8 + 255) / 256, 256>>>((const float4*)gx, SFULL / 8, x16);
    mma_f16_h0<<<dim3(gFull, 1), 256, F_DSMEM>>>(x16, W0T16, b0, gh0);
    t_f16<<<dim3(188, 7), dim3(32, 32)>>>(gh0);   // writes hT16 + h016

    // ---- GCNII layers ----
    for (int lay = 0; lay < NLAY; lay++) {
        float theta = logf(0.5f / (float)(lay + 1) + 1.0f);

        // hi partials = (adj*2^14) @ h   (fp16, K split 3)
        mma_f16<<<dim3(gFull, 3), 256, F_DSMEM>>>(adj16, NROW, hT16, NROW,
            NROW, NROW, 2000, gpart);
        reduce_hi<<<(SFULL / 4 + 255) / 256, 256>>>();

        // S@W = hi @ W1 + h0 @ W2  (fp16 dual-segment, 2 partials)
        mma_f16_dual<<<dim3(gFull, 2), 256, F_DSMEM>>>(
            hi16, h016, WT16_8 + (size_t)lay * WSTRIDE, 2 * NCOL, gpart);

        // combine + relu -> hT16 (g_h f32 only on last layer)
        reduce_gcnii<<<dim3(188, 7), dim3(32, 8)>>>(theta, lay == NLAY - 1 ? 1 : 0);
    }

    assemble_kernel<<<(NUTT * 300 + 255) / 256, 256>>>((float4*)out);
}